// round 9
// baseline (speedup 1.0000x reference)
#include <cuda_runtime.h>
#include <cuda_bf16.h>
#include <math.h>
#include <stdint.h>

#define B  4096
#define D  1792
#define NC 3000
#define NM 7000
#define NF 13000
#define NTOT (NC + NM + NF)

// padded (tile-256) class counts for the transposed weight buffers
#define NPC 3072
#define NPM 7168
#define NPF 13056
#define SEC_C 0
#define SEC_M 3072
#define SEC_F 10240
#define NPTOT 23296
#define NSTRIP (NPTOT / 256)      // 91
#define NSUB   (NSTRIP * 4)       // 364 sub-strips of 64 cols

// sub-strip ranges per head (4 per 256-col strip)
#define SUB_C0 0
#define SUB_CN 48                 // 12 strips * 4
#define SUB_M0 48
#define SUB_MN 112                // 28 strips * 4
#define SUB_F0 160
#define SUB_FN 204                // 51 strips * 4

#define OFF_C ((size_t)0)
#define OFF_M ((size_t)B * NC)
#define OFF_F (OFF_M + (size_t)B * NM)

// ---- device scratch (no runtime allocation allowed) ----
__device__ float         g_logits[(size_t)B * NTOT];   // ~377 MB
__device__ __nv_bfloat16 g_A_hi[(size_t)B * D];
__device__ __nv_bfloat16 g_A_lo[(size_t)B * D];
__device__ __nv_bfloat16 g_Wt_hi[(size_t)NPTOT * D];   // transposed [n][k]
__device__ __nv_bfloat16 g_Wt_lo[(size_t)NPTOT * D];
__device__ float g_pm[(size_t)NSUB * B];               // per-sub-strip row max
__device__ float g_ps[(size_t)NSUB * B];               // per-sub-strip row sumexp
__device__ float g_label_xyz[B * 3];
__device__ float g_part_xyz[NTOT * 3];
__device__ int   g_label_idx[3 * B];
__device__ float g_nll[B];
__device__ int   g_counts[5];

// ============================================================
// helpers
// ============================================================
__device__ __forceinline__ uint32_t smem_to_u32(const void* p) {
    uint32_t a;
    asm("{ .reg .u64 t; cvta.to.shared.u64 t, %1; cvt.u32.u64 %0, t; }"
        : "=r"(a) : "l"(p));
    return a;
}
#define CP_ASYNC16(sm, gp) \
    asm volatile("cp.async.cg.shared.global [%0], [%1], 16;" :: "r"(sm), "l"(gp) : "memory")

__device__ __forceinline__ void ldsm_x4(uint32_t* r, uint32_t addr) {
    asm volatile("ldmatrix.sync.aligned.m8n8.x4.shared.b16 {%0,%1,%2,%3}, [%4];"
        : "=r"(r[0]), "=r"(r[1]), "=r"(r[2]), "=r"(r[3]) : "r"(addr));
}
__device__ __forceinline__ void mma_bf16(float* d, const uint32_t* a, const uint32_t* b) {
    asm volatile("mma.sync.aligned.m16n8k16.row.col.f32.bf16.bf16.f32 "
        "{%0,%1,%2,%3}, {%4,%5,%6,%7}, {%8,%9}, {%0,%1,%2,%3};"
        : "+f"(d[0]), "+f"(d[1]), "+f"(d[2]), "+f"(d[3])
        : "r"(a[0]), "r"(a[1]), "r"(a[2]), "r"(a[3]), "r"(b[0]), "r"(b[1]));
}

// ============================================================
// Kernel: precompute unit vectors, zero counters
// ============================================================
__global__ void k_init(const float* __restrict__ labels,
                       const float* __restrict__ cpart,
                       const float* __restrict__ mpart,
                       const float* __restrict__ fpart)
{
    int t = blockIdx.x * blockDim.x + threadIdx.x;
    const float RADF = 0.017453292519943295f;
    if (t < B) {
        float la = labels[t * 2] * RADF, lo = labels[t * 2 + 1] * RADF;
        float cl = cosf(la);
        g_label_xyz[t * 3 + 0] = cl * cosf(lo);
        g_label_xyz[t * 3 + 1] = cl * sinf(lo);
        g_label_xyz[t * 3 + 2] = sinf(la);
    }
    if (t < NTOT) {
        const float* src;
        if (t < NC)            src = cpart + (size_t)t * 2;
        else if (t < NC + NM)  src = mpart + (size_t)(t - NC) * 2;
        else                   src = fpart + (size_t)(t - NC - NM) * 2;
        float la = src[0] * RADF, lo = src[1] * RADF;
        float cl = cosf(la);
        g_part_xyz[t * 3 + 0] = cl * cosf(lo);
        g_part_xyz[t * 3 + 1] = cl * sinf(lo);
        g_part_xyz[t * 3 + 2] = sinf(la);
    }
    if (t < 5) g_counts[t] = 0;
}

// ============================================================
// Kernel: label index — one WARP per (head, b), shfl argmax reduce
// ============================================================
__global__ __launch_bounds__(256)
void k_labelidx()
{
    int gw = blockIdx.x * 8 + (threadIdx.x >> 5);
    if (gw >= 3 * B) return;
    int lane = threadIdx.x & 31;
    int head = gw >> 12;
    int b    = gw & (B - 1);
    int base, n;
    if (head == 0)      { base = 0;       n = NC; }
    else if (head == 1) { base = NC;      n = NM; }
    else                { base = NC + NM; n = NF; }
    float lx = g_label_xyz[b * 3 + 0];
    float ly = g_label_xyz[b * 3 + 1];
    float lz = g_label_xyz[b * 3 + 2];
    const float* P = g_part_xyz + (size_t)base * 3;
    float best = -2.0f; int bi = 0x7fffffff;
    for (int i = lane; i < n; i += 32) {
        float d = lx * P[i * 3] + ly * P[i * 3 + 1] + lz * P[i * 3 + 2];
        if (d > best || (d == best && i < bi)) { best = d; bi = i; }
    }
#pragma unroll
    for (int off = 16; off > 0; off >>= 1) {
        float ob = __shfl_down_sync(0xffffffffu, best, off);
        int   oi = __shfl_down_sync(0xffffffffu, bi,   off);
        if (ob > best || (ob == best && oi < bi)) { best = ob; bi = oi; }
    }
    if (lane == 0) g_label_idx[head * B + b] = bi;
}

// ============================================================
// Kernel: convert features -> bf16 hi/lo, vectorized float4 -> uint2
// ============================================================
__global__ void k_convA(const float4* __restrict__ A)
{
    int t = blockIdx.x * blockDim.x + threadIdx.x;
    if (t >= (B * D) / 4) return;
    float4 v = A[t];
    __nv_bfloat16 h0 = __float2bfloat16(v.x);
    __nv_bfloat16 h1 = __float2bfloat16(v.y);
    __nv_bfloat16 h2 = __float2bfloat16(v.z);
    __nv_bfloat16 h3 = __float2bfloat16(v.w);
    __nv_bfloat16 l0 = __float2bfloat16(v.x - __bfloat162float(h0));
    __nv_bfloat16 l1 = __float2bfloat16(v.y - __bfloat162float(h1));
    __nv_bfloat16 l2 = __float2bfloat16(v.z - __bfloat162float(h2));
    __nv_bfloat16 l3 = __float2bfloat16(v.w - __bfloat162float(h3));
    uint2 hp, lp;
    hp.x = ((uint32_t)__bfloat16_as_ushort(h1) << 16) | __bfloat16_as_ushort(h0);
    hp.y = ((uint32_t)__bfloat16_as_ushort(h3) << 16) | __bfloat16_as_ushort(h2);
    lp.x = ((uint32_t)__bfloat16_as_ushort(l1) << 16) | __bfloat16_as_ushort(l0);
    lp.y = ((uint32_t)__bfloat16_as_ushort(l3) << 16) | __bfloat16_as_ushort(l2);
    ((uint2*)g_A_hi)[t] = hp;
    ((uint2*)g_A_lo)[t] = lp;
}

// ============================================================
// Kernel: fused transpose+convert for ALL heads:
// W [D][N] -> Wt [NPTOT][D] bf16 hi/lo (zero pad)
// ============================================================
__global__ void k_convW(const float* __restrict__ cw,
                        const float* __restrict__ mw,
                        const float* __restrict__ fw)
{
    __shared__ float t[32][33];
    int k0 = blockIdx.x * 32;
    int ng0 = blockIdx.y * 32;
    const float* W; int N, sec;
    if (ng0 < SEC_M)      { W = cw; N = NC; sec = SEC_C; }
    else if (ng0 < SEC_F) { W = mw; N = NM; sec = SEC_M; }
    else                  { W = fw; N = NF; sec = SEC_F; }
    int n0 = ng0 - sec;
#pragma unroll
    for (int j = 0; j < 32; j += 8) {
        int k = k0 + threadIdx.y + j;
        int n = n0 + threadIdx.x;
        t[threadIdx.y + j][threadIdx.x] = (n < N) ? W[(size_t)k * N + n] : 0.f;
    }
    __syncthreads();
#pragma unroll
    for (int j = 0; j < 32; j += 8) {
        int n = ng0 + threadIdx.y + j;
        int k = k0 + threadIdx.x;
        float v = t[threadIdx.x][threadIdx.y + j];
        __nv_bfloat16 h = __float2bfloat16(v);
        __nv_bfloat16 l = __float2bfloat16(v - __bfloat162float(h));
        size_t o = (size_t)n * D + k;
        g_Wt_hi[o] = h;
        g_Wt_lo[o] = l;
    }
}

// ============================================================
// Merged-pass bf16x3 GEMM: per K-chunk compute AhBh + AhBl + AlBh.
// 128x256 tile, warp tile 64x64, 256 threads.
// 4-stage BK=32 cp.async pipeline (SW64 swizzle), ONE barrier/chunk,
// early issue. In-epilogue per-sub-strip LSE partials.
// ============================================================
#define BM 128
#define BN 256
#define BK 32
#define ST_AH 0
#define ST_AL 8192
#define ST_BH 16384
#define ST_BL 32768
#define STAGE_BYTES 49152
#define NSTG 4
#define GEMM_SMEM (NSTG * STAGE_BYTES)     // 192 KB
#define NKC (D / BK)              // 56
#define GRID_M (B / BM)           // 32
#define GRID_N NSTRIP             // 91 = 7 * 13
#define SUPER_N 13

__global__ __launch_bounds__(256, 1)
void k_mmagemm(const float* __restrict__ cb, const float* __restrict__ mb,
               const float* __restrict__ fb)
{
    extern __shared__ __align__(1024) char smem[];
    uint32_t sb = smem_to_u32(smem);
    const int tid  = threadIdx.x;
    const int wid  = tid >> 5;
    const int lane = tid & 31;
    const int wm   = wid >> 2;     // 0..1
    const int wn   = wid & 3;      // 0..3

    // supertile rasterization: 32 m x 13 n per supertile
    const int gid = blockIdx.x;
    const int sy  = gid / (GRID_M * SUPER_N);
    const int r   = gid % (GRID_M * SUPER_N);
    const int mx  = r / SUPER_N;
    const int ny  = sy * SUPER_N + (r % SUPER_N);
    const int m0  = mx * BM;
    const int n0  = ny * BN;

    int N, sec; size_t outOff; const float* bias;
    if (n0 < SEC_M)      { N = NC; sec = SEC_C; outOff = OFF_C; bias = cb; }
    else if (n0 < SEC_F) { N = NM; sec = SEC_M; outOff = OFF_M; bias = mb; }
    else                 { N = NF; sec = SEC_F; outOff = OFF_F; bias = fb; }
    const int nloc0 = n0 - sec;

    // ---- cp.async addressing (SW64: 64B rows) ----
    // A: 2 segs/thread per buffer; B: 4 segs/thread per buffer
    uint32_t aSw[2], aGo[2];
#pragma unroll
    for (int i = 0; i < 2; i++) {
        int idx = tid + i * 256;              // 0..511
        int row = idx >> 2, seg = idx & 3;
        aSw[i] = (uint32_t)(row * 64 + ((seg * 16) ^ ((row & 6) << 3)));
        aGo[i] = (uint32_t)((row * D + seg * 8) * 2);     // byte offset
    }
    uint32_t bSw[4], bGo[4];
#pragma unroll
    for (int i = 0; i < 4; i++) {
        int idx = tid + i * 256;              // 0..1023
        int row = idx >> 2, seg = idx & 3;
        bSw[i] = (uint32_t)(row * 64 + ((seg * 16) ^ ((row & 6) << 3)));
        bGo[i] = (uint32_t)((row * D + seg * 8) * 2);
    }
    const char* Ahp = (const char*)(g_A_hi  + (size_t)m0 * D);
    const char* Alp = (const char*)(g_A_lo  + (size_t)m0 * D);
    const char* Bhp = (const char*)(g_Wt_hi + (size_t)n0 * D);
    const char* Blp = (const char*)(g_Wt_lo + (size_t)n0 * D);

    // ---- ldsm per-lane addressing (SW64) ----
    uint32_t aTerm[4], aXor[4];
#pragma unroll
    for (int mt = 0; mt < 4; mt++) {
        int row = wm * 64 + mt * 16 + (lane & 7) + ((lane >> 3) & 1) * 8;
        aTerm[mt] = (uint32_t)(row * 64);
        aXor[mt]  = (uint32_t)((row & 6) << 3);
    }
    const uint32_t aCSel = ((lane >> 4) & 1) * 16;
    uint32_t bTerm[4], bXor[4];
#pragma unroll
    for (int np = 0; np < 4; np++) {
        int row = wn * 64 + np * 16 + (lane & 7) + ((lane >> 4) & 1) * 8;
        bTerm[np] = (uint32_t)(row * 64);
        bXor[np]  = (uint32_t)((row & 6) << 3);
    }
    const uint32_t bCSel = ((lane >> 3) & 1) * 16;

    float acc[4][8][4];
#pragma unroll
    for (int i = 0; i < 4; i++)
#pragma unroll
        for (int j = 0; j < 8; j++)
#pragma unroll
            for (int k = 0; k < 4; k++) acc[i][j][k] = 0.f;

#define ISSUE(c) do { \
        int _c = (c); \
        uint32_t kb2 = (uint32_t)(_c * BK * 2); \
        uint32_t st = sb + (uint32_t)(_c & (NSTG - 1)) * STAGE_BYTES; \
        _Pragma("unroll") \
        for (int i = 0; i < 2; i++) { \
            CP_ASYNC16(st + ST_AH + aSw[i], Ahp + kb2 + aGo[i]); \
            CP_ASYNC16(st + ST_AL + aSw[i], Alp + kb2 + aGo[i]); \
        } \
        _Pragma("unroll") \
        for (int i = 0; i < 4; i++) { \
            CP_ASYNC16(st + ST_BH + bSw[i], Bhp + kb2 + bGo[i]); \
            CP_ASYNC16(st + ST_BL + bSw[i], Blp + kb2 + bGo[i]); \
        } \
        asm volatile("cp.async.commit_group;" ::: "memory"); \
    } while (0)

    ISSUE(0);
    ISSUE(1);
    ISSUE(2);

    for (int c = 0; c < NKC; c++) {
        if (c <= NKC - 3)      asm volatile("cp.async.wait_group 2;" ::: "memory");
        else if (c == NKC - 2) asm volatile("cp.async.wait_group 1;" ::: "memory");
        else                   asm volatile("cp.async.wait_group 0;" ::: "memory");
        __syncthreads();                       // chunk c visible; stage (c-1)&3 free
        if (c + 3 < NKC) ISSUE(c + 3);

        uint32_t st = sb + (uint32_t)(c & (NSTG - 1)) * STAGE_BYTES;
#pragma unroll
        for (int ks = 0; ks < 2; ks++) {
            const uint32_t kb = (uint32_t)(ks * 32);
            uint32_t a[4][4], bh[4][4], bl[4][4];
#pragma unroll
            for (int mt = 0; mt < 4; mt++)
                ldsm_x4(a[mt], st + ST_AH + aTerm[mt] + ((kb + aCSel) ^ aXor[mt]));
#pragma unroll
            for (int np = 0; np < 4; np++)
                ldsm_x4(bh[np], st + ST_BH + bTerm[np] + ((kb + bCSel) ^ bXor[np]));
#pragma unroll
            for (int np = 0; np < 4; np++)
                ldsm_x4(bl[np], st + ST_BL + bTerm[np] + ((kb + bCSel) ^ bXor[np]));
            // Ah * Bh
#pragma unroll
            for (int mt = 0; mt < 4; mt++)
#pragma unroll
                for (int nt = 0; nt < 8; nt++)
                    mma_bf16(acc[mt][nt], a[mt], &bh[nt >> 1][(nt & 1) * 2]);
            // Ah * Bl
#pragma unroll
            for (int mt = 0; mt < 4; mt++)
#pragma unroll
                for (int nt = 0; nt < 8; nt++)
                    mma_bf16(acc[mt][nt], a[mt], &bl[nt >> 1][(nt & 1) * 2]);
            // Al * Bh (reload a-frags from Al region)
#pragma unroll
            for (int mt = 0; mt < 4; mt++)
                ldsm_x4(a[mt], st + ST_AL + aTerm[mt] + ((kb + aCSel) ^ aXor[mt]));
#pragma unroll
            for (int mt = 0; mt < 4; mt++)
#pragma unroll
                for (int nt = 0; nt < 8; nt++)
                    mma_bf16(acc[mt][nt], a[mt], &bh[nt >> 1][(nt & 1) * 2]);
        }
    }
#undef ISSUE

    // ---- epilogue: bias + store logits + per-sub-strip LSE partials ----
    float* out = g_logits + outOff;
    const int sub = ny * 4 + wn;
    const int rbase = m0 + wm * 64 + (lane >> 2);
    const int cb0 = nloc0 + wn * 64 + (lane & 3) * 2;
#pragma unroll
    for (int mt = 0; mt < 4; mt++) {
        int r0 = rbase + mt * 16;
        float v0[16], v1[16];
#pragma unroll
        for (int nt = 0; nt < 8; nt++) {
            int col = cb0 + nt * 8;
            bool ok = (col < N);
            float bx = 0.f, by = 0.f;
            if (ok) { bx = bias[col]; by = bias[col + 1]; }
            float a0 = acc[mt][nt][0] + bx;
            float a1 = acc[mt][nt][1] + by;
            float a2 = acc[mt][nt][2] + bx;
            float a3 = acc[mt][nt][3] + by;
            if (ok) {
                float2 w0 = { a0, a1 }, w1 = { a2, a3 };
                *(float2*)&out[(size_t)r0 * N + col]       = w0;
                *(float2*)&out[(size_t)(r0 + 8) * N + col] = w1;
            }
            v0[nt * 2 + 0] = ok ? a0 : -1e30f;
            v0[nt * 2 + 1] = ok ? a1 : -1e30f;
            v1[nt * 2 + 0] = ok ? a2 : -1e30f;
            v1[nt * 2 + 1] = ok ? a3 : -1e30f;
        }
        float m0v = v0[0], m1v = v1[0];
#pragma unroll
        for (int j = 1; j < 16; j++) { m0v = fmaxf(m0v, v0[j]); m1v = fmaxf(m1v, v1[j]); }
#pragma unroll
        for (int o = 1; o <= 2; o <<= 1) {
            m0v = fmaxf(m0v, __shfl_xor_sync(0xffffffffu, m0v, o));
            m1v = fmaxf(m1v, __shfl_xor_sync(0xffffffffu, m1v, o));
        }
        float s0 = 0.f, s1 = 0.f;
#pragma unroll
        for (int j = 0; j < 16; j++) {
            s0 += __expf(v0[j] - m0v);
            s1 += __expf(v1[j] - m1v);
        }
#pragma unroll
        for (int o = 1; o <= 2; o <<= 1) {
            s0 += __shfl_xor_sync(0xffffffffu, s0, o);
            s1 += __shfl_xor_sync(0xffffffffu, s1, o);
        }
        if ((lane & 3) == 0) {
            g_pm[(size_t)sub * B + r0]     = m0v;
            g_ps[(size_t)sub * B + r0]     = s0;
            g_pm[(size_t)sub * B + r0 + 8] = m1v;
            g_ps[(size_t)sub * B + r0 + 8] = s1;
        }
    }
}

// ============================================================
// Tail (512 threads): per row b — combine LSE partials, NLL,
// hierarchical argmax via t[m]=Mv[m]+sC[mp[m]], acc bins.
// ============================================================
#define TAIL_SMEM ((NC + NM) * 4)
#define TAIL_T 512

__global__ __launch_bounds__(TAIL_T)
void k_tail(const float* __restrict__ labels,
            const float* __restrict__ fpart,
            const int*   __restrict__ fparents,
            const int*   __restrict__ mparents)
{
    extern __shared__ float sh[];
    float* sC = sh;          // NC
    float* tM = sh + NC;     // NM
    __shared__ float lseS[3];
    __shared__ float rf[16];
    __shared__ int   ri[16];

    int b = blockIdx.x, tid = threadIdx.x;
    int lane = tid & 31, wid = tid >> 5;
    const float* Cv = g_logits + OFF_C + (size_t)b * NC;
    const float* Mv = g_logits + OFF_M + (size_t)b * NM;
    const float* Fv = g_logits + OFF_F + (size_t)b * NF;

    for (int i = tid; i < NC; i += TAIL_T) sC[i] = Cv[i];

    // warps 0..2: combine per-sub-strip LSE partials for head wid (2-pass)
    if (wid < 3) {
        int base = (wid == 0) ? SUB_C0 : (wid == 1) ? SUB_M0 : SUB_F0;
        int cnt  = (wid == 0) ? SUB_CN : (wid == 1) ? SUB_MN : SUB_FN;
        float m = -3.402823466e38f;
        for (int i = lane; i < cnt; i += 32)
            m = fmaxf(m, g_pm[(size_t)(base + i) * B + b]);
#pragma unroll
        for (int o = 16; o > 0; o >>= 1)
            m = fmaxf(m, __shfl_xor_sync(0xffffffffu, m, o));
        float s = 0.f;
        for (int i = lane; i < cnt; i += 32)
            s += g_ps[(size_t)(base + i) * B + b] *
                 __expf(g_pm[(size_t)(base + i) * B + b] - m);
#pragma unroll
        for (int o = 16; o > 0; o >>= 1)
            s += __shfl_xor_sync(0xffffffffu, s, o);
        if (lane == 0) lseS[wid] = m + logf(s);
    }
    __syncthreads();

    // t[m] = Mv[m] + sC[mparents[m]]
    for (int i = tid; i < NM; i += TAIL_T) tM[i] = Mv[i] + sC[mparents[i]];
    __syncthreads();

    // hierarchical argmax over fine classes
    float best = -3.402823466e38f; int bi = 0x7fffffff;
    for (int f = tid; f < NF; f += TAIL_T) {
        float sc = Fv[f] + tM[fparents[f]];
        if (sc > best) { best = sc; bi = f; }
    }
#pragma unroll
    for (int o = 16; o > 0; o >>= 1) {
        float ob = __shfl_xor_sync(0xffffffffu, best, o);
        int   oi = __shfl_xor_sync(0xffffffffu, bi,   o);
        if (ob > best || (ob == best && oi < bi)) { best = ob; bi = oi; }
    }
    if (lane == 0) { rf[wid] = best; ri[wid] = bi; }
    __syncthreads();

    if (tid == 0) {
        float bb = rf[0]; int pp = ri[0];
#pragma unroll
        for (int j = 1; j < 16; j++) {
            if (rf[j] > bb || (rf[j] == bb && ri[j] < pp)) { bb = rf[j]; pp = ri[j]; }
        }
        int liC = g_label_idx[b];
        int liM = g_label_idx[B + b];
        int liF = g_label_idx[2 * B + b];
        g_nll[b] = (lseS[0] - sC[liC]) + (lseS[1] - Mv[liM]) + (lseS[2] - Fv[liF]);

        const float RADF = 0.017453292519943295f;
        float lat1 = labels[b * 2]      * RADF;
        float lon1 = labels[b * 2 + 1]  * RADF;
        float lat2 = fpart[pp * 2]      * RADF;
        float lon2 = fpart[pp * 2 + 1]  * RADF;
        float sdlat = sinf((lat2 - lat1) * 0.5f);
        float sdlon = sinf((lon2 - lon1) * 0.5f);
        float a = sdlat * sdlat + cosf(lat1) * cosf(lat2) * sdlon * sdlon;
        a = fminf(fmaxf(a, 0.f), 1.f);
        float d = 2.0f * 6371.0f * asinf(sqrtf(a));
        if (d <= 1.0f)    atomicAdd(&g_counts[0], 1);
        if (d <= 25.0f)   atomicAdd(&g_counts[1], 1);
        if (d <= 200.0f)  atomicAdd(&g_counts[2], 1);
        if (d <= 750.0f)  atomicAdd(&g_counts[3], 1);
        if (d <= 2500.0f) atomicAdd(&g_counts[4], 1);
    }
}

// ============================================================
// Final deterministic reduction -> out[0]=loss, out[1..5]=acc
// ============================================================
__global__ void k_finalize(float* __restrict__ out)
{
    __shared__ float red[256];
    int tid = threadIdx.x;
    float s = 0.f;
    for (int i = tid; i < B; i += 256) s += g_nll[i];
    red[tid] = s; __syncthreads();
    for (int st = 128; st > 0; st >>= 1) {
        if (tid < st) red[tid] += red[tid + st];
        __syncthreads();
    }
    if (tid == 0) out[0] = red[0] / (float)B;
    if (tid < 5)  out[1 + tid] = (float)g_counts[tid] / (float)B;
}

// ============================================================
extern "C" void kernel_launch(void* const* d_in, const int* in_sizes, int n_in,
                              void* d_out, int out_size)
{
    const float* features = (const float*)d_in[0];
    const float* labels   = (const float*)d_in[1];
    const float* cpart    = (const float*)d_in[2];
    const float* mpart    = (const float*)d_in[3];
    const float* fpart    = (const float*)d_in[4];
    const int*   mparents = (const int*)d_in[5];
    const int*   fparents = (const int*)d_in[6];
    const float* cw = (const float*)d_in[7];
    const float* cb = (const float*)d_in[8];
    const float* mw = (const float*)d_in[9];
    const float* mb = (const float*)d_in[10];
    const float* fw = (const float*)d_in[11];
    const float* fb = (const float*)d_in[12];
    float* out = (float*)d_out;

    static int s_attr_done = 0;
    if (!s_attr_done) {
        cudaFuncSetAttribute(k_mmagemm, cudaFuncAttributeMaxDynamicSharedMemorySize,
                             GEMM_SMEM);
        cudaFuncSetAttribute(k_tail, cudaFuncAttributeMaxDynamicSharedMemorySize,
                             TAIL_SMEM);
        s_attr_done = 1;
    }

    // order: GEMM is my 4th launch so ncu (-s 5 -c 1) profiles it
    k_convA<<<((B * D) / 4 + 255) / 256, 256>>>((const float4*)features);
    k_convW<<<dim3(D / 32, NPTOT / 32), dim3(32, 8)>>>(cw, mw, fw);
    k_init<<<(NTOT + 255) / 256, 256>>>(labels, cpart, mpart, fpart);

    k_mmagemm<<<GRID_M * GRID_N, 256, GEMM_SMEM>>>(cb, mb, fb);

    k_labelidx<<<(3 * B + 7) / 8, 256>>>();
    k_tail<<<B, TAIL_T, TAIL_SMEM>>>(labels, fpart, fparents, mparents);
    k_finalize<<<1, 256>>>(out);
}

// round 10
// speedup vs baseline: 1.4998x; 1.4998x over previous
#include <cuda_runtime.h>
#include <cuda_bf16.h>
#include <math.h>
#include <stdint.h>

#define B  4096
#define D  1792
#define NC 3000
#define NM 7000
#define NF 13000
#define NTOT (NC + NM + NF)

// padded (tile-256) class counts for the transposed weight buffers
#define NPC 3072
#define NPM 7168
#define NPF 13056
#define SEC_C 0
#define SEC_M 3072
#define SEC_F 10240
#define NPTOT 23296
#define NSTRIP (NPTOT / 256)      // 91
#define NSUB   (NSTRIP * 4)       // 364 sub-strips of 64 cols

// sub-strip ranges per head (4 per 256-col strip)
#define SUB_C0 0
#define SUB_CN 48                 // 12 strips * 4
#define SUB_M0 48
#define SUB_MN 112                // 28 strips * 4
#define SUB_F0 160
#define SUB_FN 204                // 51 strips * 4

#define OFF_C ((size_t)0)
#define OFF_M ((size_t)B * NC)
#define OFF_F (OFF_M + (size_t)B * NM)

// ---- device scratch (no runtime allocation allowed) ----
__device__ float         g_logits[(size_t)B * NTOT];   // ~377 MB
__device__ __nv_bfloat16 g_A_hi[(size_t)B * D];
__device__ __nv_bfloat16 g_A_lo[(size_t)B * D];
__device__ __nv_bfloat16 g_Wt_hi[(size_t)NPTOT * D];   // transposed [n][k]
__device__ float g_pm[(size_t)NSUB * B];               // per-sub-strip row max
__device__ float g_ps[(size_t)NSUB * B];               // per-sub-strip row sumexp
__device__ float g_label_xyz[B * 3];
__device__ float g_part_xyz[NTOT * 3];
__device__ int   g_label_idx[3 * B];
__device__ float g_nll[B];
__device__ int   g_counts[5];

// ============================================================
// helpers
// ============================================================
__device__ __forceinline__ uint32_t smem_to_u32(const void* p) {
    uint32_t a;
    asm("{ .reg .u64 t; cvta.to.shared.u64 t, %1; cvt.u32.u64 %0, t; }"
        : "=r"(a) : "l"(p));
    return a;
}
#define CP_ASYNC16(sm, gp) \
    asm volatile("cp.async.cg.shared.global [%0], [%1], 16;" :: "r"(sm), "l"(gp) : "memory")

__device__ __forceinline__ void ldsm_x4(uint32_t* r, uint32_t addr) {
    asm volatile("ldmatrix.sync.aligned.m8n8.x4.shared.b16 {%0,%1,%2,%3}, [%4];"
        : "=r"(r[0]), "=r"(r[1]), "=r"(r[2]), "=r"(r[3]) : "r"(addr));
}
__device__ __forceinline__ void mma_bf16(float* d, const uint32_t* a, const uint32_t* b) {
    asm volatile("mma.sync.aligned.m16n8k16.row.col.f32.bf16.bf16.f32 "
        "{%0,%1,%2,%3}, {%4,%5,%6,%7}, {%8,%9}, {%0,%1,%2,%3};"
        : "+f"(d[0]), "+f"(d[1]), "+f"(d[2]), "+f"(d[3])
        : "r"(a[0]), "r"(a[1]), "r"(a[2]), "r"(a[3]), "r"(b[0]), "r"(b[1]));
}

// ============================================================
// Kernel: precompute unit vectors, zero counters
// ============================================================
__global__ void k_init(const float* __restrict__ labels,
                       const float* __restrict__ cpart,
                       const float* __restrict__ mpart,
                       const float* __restrict__ fpart)
{
    int t = blockIdx.x * blockDim.x + threadIdx.x;
    const float RADF = 0.017453292519943295f;
    if (t < B) {
        float la = labels[t * 2] * RADF, lo = labels[t * 2 + 1] * RADF;
        float cl = cosf(la);
        g_label_xyz[t * 3 + 0] = cl * cosf(lo);
        g_label_xyz[t * 3 + 1] = cl * sinf(lo);
        g_label_xyz[t * 3 + 2] = sinf(la);
    }
    if (t < NTOT) {
        const float* src;
        if (t < NC)            src = cpart + (size_t)t * 2;
        else if (t < NC + NM)  src = mpart + (size_t)(t - NC) * 2;
        else                   src = fpart + (size_t)(t - NC - NM) * 2;
        float la = src[0] * RADF, lo = src[1] * RADF;
        float cl = cosf(la);
        g_part_xyz[t * 3 + 0] = cl * cosf(lo);
        g_part_xyz[t * 3 + 1] = cl * sinf(lo);
        g_part_xyz[t * 3 + 2] = sinf(la);
    }
    if (t < 5) g_counts[t] = 0;
}

// ============================================================
// Kernel: label index — one WARP per (head, b), shfl argmax reduce
// ============================================================
__global__ __launch_bounds__(256)
void k_labelidx()
{
    int gw = blockIdx.x * 8 + (threadIdx.x >> 5);
    if (gw >= 3 * B) return;
    int lane = threadIdx.x & 31;
    int head = gw >> 12;
    int b    = gw & (B - 1);
    int base, n;
    if (head == 0)      { base = 0;       n = NC; }
    else if (head == 1) { base = NC;      n = NM; }
    else                { base = NC + NM; n = NF; }
    float lx = g_label_xyz[b * 3 + 0];
    float ly = g_label_xyz[b * 3 + 1];
    float lz = g_label_xyz[b * 3 + 2];
    const float* P = g_part_xyz + (size_t)base * 3;
    float best = -2.0f; int bi = 0x7fffffff;
    for (int i = lane; i < n; i += 32) {
        float d = lx * P[i * 3] + ly * P[i * 3 + 1] + lz * P[i * 3 + 2];
        if (d > best || (d == best && i < bi)) { best = d; bi = i; }
    }
#pragma unroll
    for (int off = 16; off > 0; off >>= 1) {
        float ob = __shfl_down_sync(0xffffffffu, best, off);
        int   oi = __shfl_down_sync(0xffffffffu, bi,   off);
        if (ob > best || (ob == best && oi < bi)) { best = ob; bi = oi; }
    }
    if (lane == 0) g_label_idx[head * B + b] = bi;
}

// ============================================================
// Kernel: convert features -> bf16 hi/lo, vectorized float4 -> uint2
// ============================================================
__global__ void k_convA(const float4* __restrict__ A)
{
    int t = blockIdx.x * blockDim.x + threadIdx.x;
    if (t >= (B * D) / 4) return;
    float4 v = A[t];
    __nv_bfloat16 h0 = __float2bfloat16(v.x);
    __nv_bfloat16 h1 = __float2bfloat16(v.y);
    __nv_bfloat16 h2 = __float2bfloat16(v.z);
    __nv_bfloat16 h3 = __float2bfloat16(v.w);
    __nv_bfloat16 l0 = __float2bfloat16(v.x - __bfloat162float(h0));
    __nv_bfloat16 l1 = __float2bfloat16(v.y - __bfloat162float(h1));
    __nv_bfloat16 l2 = __float2bfloat16(v.z - __bfloat162float(h2));
    __nv_bfloat16 l3 = __float2bfloat16(v.w - __bfloat162float(h3));
    uint2 hp, lp;
    hp.x = ((uint32_t)__bfloat16_as_ushort(h1) << 16) | __bfloat16_as_ushort(h0);
    hp.y = ((uint32_t)__bfloat16_as_ushort(h3) << 16) | __bfloat16_as_ushort(h2);
    lp.x = ((uint32_t)__bfloat16_as_ushort(l1) << 16) | __bfloat16_as_ushort(l0);
    lp.y = ((uint32_t)__bfloat16_as_ushort(l3) << 16) | __bfloat16_as_ushort(l2);
    ((uint2*)g_A_hi)[t] = hp;
    ((uint2*)g_A_lo)[t] = lp;
}

// ============================================================
// Kernel: fused transpose+convert for ALL heads:
// W [D][N] -> Wt [NPTOT][D] bf16 (hi only, zero pad)
// ============================================================
__global__ void k_convW(const float* __restrict__ cw,
                        const float* __restrict__ mw,
                        const float* __restrict__ fw)
{
    __shared__ float t[32][33];
    int k0 = blockIdx.x * 32;
    int ng0 = blockIdx.y * 32;
    const float* W; int N, sec;
    if (ng0 < SEC_M)      { W = cw; N = NC; sec = SEC_C; }
    else if (ng0 < SEC_F) { W = mw; N = NM; sec = SEC_M; }
    else                  { W = fw; N = NF; sec = SEC_F; }
    int n0 = ng0 - sec;
#pragma unroll
    for (int j = 0; j < 32; j += 8) {
        int k = k0 + threadIdx.y + j;
        int n = n0 + threadIdx.x;
        t[threadIdx.y + j][threadIdx.x] = (n < N) ? W[(size_t)k * N + n] : 0.f;
    }
    __syncthreads();
#pragma unroll
    for (int j = 0; j < 32; j += 8) {
        int n = ng0 + threadIdx.y + j;
        int k = k0 + threadIdx.x;
        float v = t[threadIdx.x][threadIdx.y + j];
        g_Wt_hi[(size_t)n * D + k] = __float2bfloat16(v);
    }
}

// ============================================================
// 2-product bf16 GEMM: per K-chunk compute (Ah + Al) * Bh.
// 128x256 tile, warp tile 64x64, 256 threads, BK=64, 2-stage pipe,
// SW128 swizzle, R8-proven loop structure (2 barriers/chunk).
// In-epilogue per-sub-strip LSE partials.
// ============================================================
#define BM 128
#define BN 256
#define BK 64
#define ST_AH 0
#define ST_AL 16384
#define ST_BH 32768
#define STAGE_BYTES 65536
#define GEMM_SMEM (2 * STAGE_BYTES)        // 128 KB
#define NKC (D / BK)              // 28
#define GRID_M (B / BM)           // 32
#define GRID_N NSTRIP             // 91 = 7 * 13
#define SUPER_N 13

__global__ __launch_bounds__(256, 1)
void k_mmagemm(const float* __restrict__ cb, const float* __restrict__ mb,
               const float* __restrict__ fb)
{
    extern __shared__ __align__(1024) char smem[];
    uint32_t sb = smem_to_u32(smem);
    const int tid  = threadIdx.x;
    const int wid  = tid >> 5;
    const int lane = tid & 31;
    const int wm   = wid >> 2;     // 0..1
    const int wn   = wid & 3;      // 0..3

    // supertile rasterization: 32 m x 13 n per supertile
    const int gid = blockIdx.x;
    const int sy  = gid / (GRID_M * SUPER_N);
    const int r   = gid % (GRID_M * SUPER_N);
    const int mx  = r / SUPER_N;
    const int ny  = sy * SUPER_N + (r % SUPER_N);
    const int m0  = mx * BM;
    const int n0  = ny * BN;

    int N, sec; size_t outOff; const float* bias;
    if (n0 < SEC_M)      { N = NC; sec = SEC_C; outOff = OFF_C; bias = cb; }
    else if (n0 < SEC_F) { N = NM; sec = SEC_M; outOff = OFF_M; bias = mb; }
    else                 { N = NF; sec = SEC_F; outOff = OFF_F; bias = fb; }
    const int nloc0 = n0 - sec;

    // ---- cp.async addressing (SW128, 128B rows) ----
    uint32_t aSw[4], aGo[4];
#pragma unroll
    for (int i = 0; i < 4; i++) {
        int idx = tid + i * 256;              // 0..1023 (A: 128 rows x 8 segs)
        int row = idx >> 3, seg = idx & 7;
        aSw[i] = (uint32_t)(row * 128 + ((seg * 16) ^ ((row & 7) << 4)));
        aGo[i] = (uint32_t)((row * D + seg * 8) * 2);     // byte offset
    }
    uint32_t bSw[8], bGo[8];
#pragma unroll
    for (int i = 0; i < 8; i++) {
        int idx = tid + i * 256;              // 0..2047 (B: 256 rows x 8 segs)
        int row = idx >> 3, seg = idx & 7;
        bSw[i] = (uint32_t)(row * 128 + ((seg * 16) ^ ((row & 7) << 4)));
        bGo[i] = (uint32_t)((row * D + seg * 8) * 2);
    }
    const char* Ahp = (const char*)(g_A_hi  + (size_t)m0 * D);
    const char* Alp = (const char*)(g_A_lo  + (size_t)m0 * D);
    const char* Bhp = (const char*)(g_Wt_hi + (size_t)n0 * D);

    // ---- ldsm per-lane addressing (SW128) ----
    uint32_t aTerm[4], aXor[4];
#pragma unroll
    for (int mt = 0; mt < 4; mt++) {
        int row = wm * 64 + mt * 16 + (lane & 7) + ((lane >> 3) & 1) * 8;
        aTerm[mt] = (uint32_t)(row * 128);
        aXor[mt]  = (uint32_t)((row & 7) << 4);
    }
    const uint32_t aCSel = ((lane >> 4) & 1) * 16;
    uint32_t bTerm[4], bXor[4];
#pragma unroll
    for (int np = 0; np < 4; np++) {
        int row = wn * 64 + np * 16 + (lane & 7) + ((lane >> 4) & 1) * 8;
        bTerm[np] = (uint32_t)(row * 128);
        bXor[np]  = (uint32_t)((row & 7) << 4);
    }
    const uint32_t bCSel = ((lane >> 3) & 1) * 16;

    float acc[4][8][4];
#pragma unroll
    for (int i = 0; i < 4; i++)
#pragma unroll
        for (int j = 0; j < 8; j++)
#pragma unroll
            for (int k = 0; k < 4; k++) acc[i][j][k] = 0.f;

#define ISSUE(c) do { \
        int _c = (c); \
        uint32_t kb2 = (uint32_t)(_c * BK * 2); \
        uint32_t st = sb + (uint32_t)(_c & 1) * STAGE_BYTES; \
        _Pragma("unroll") \
        for (int i = 0; i < 4; i++) { \
            CP_ASYNC16(st + ST_AH + aSw[i], Ahp + kb2 + aGo[i]); \
            CP_ASYNC16(st + ST_AL + aSw[i], Alp + kb2 + aGo[i]); \
        } \
        _Pragma("unroll") \
        for (int i = 0; i < 8; i++) { \
            CP_ASYNC16(st + ST_BH + bSw[i], Bhp + kb2 + bGo[i]); \
        } \
        asm volatile("cp.async.commit_group;" ::: "memory"); \
    } while (0)

    ISSUE(0);
    ISSUE(1);

    for (int c = 0; c < NKC; c++) {
        if (c + 1 < NKC) asm volatile("cp.async.wait_group 1;" ::: "memory");
        else             asm volatile("cp.async.wait_group 0;" ::: "memory");
        __syncthreads();
        uint32_t st = sb + (uint32_t)(c & 1) * STAGE_BYTES;
#pragma unroll
        for (int ks = 0; ks < 4; ks++) {
            const uint32_t kb = (uint32_t)(ks * 32);
            uint32_t a[4][4], bh[4][4];
#pragma unroll
            for (int mt = 0; mt < 4; mt++)
                ldsm_x4(a[mt], st + ST_AH + aTerm[mt] + ((kb + aCSel) ^ aXor[mt]));
#pragma unroll
            for (int np = 0; np < 4; np++)
                ldsm_x4(bh[np], st + ST_BH + bTerm[np] + ((kb + bCSel) ^ bXor[np]));
            // Ah * Bh
#pragma unroll
            for (int mt = 0; mt < 4; mt++)
#pragma unroll
                for (int nt = 0; nt < 8; nt++)
                    mma_bf16(acc[mt][nt], a[mt], &bh[nt >> 1][(nt & 1) * 2]);
            // Al * Bh (reload a-frags from Al region)
#pragma unroll
            for (int mt = 0; mt < 4; mt++)
                ldsm_x4(a[mt], st + ST_AL + aTerm[mt] + ((kb + aCSel) ^ aXor[mt]));
#pragma unroll
            for (int mt = 0; mt < 4; mt++)
#pragma unroll
                for (int nt = 0; nt < 8; nt++)
                    mma_bf16(acc[mt][nt], a[mt], &bh[nt >> 1][(nt & 1) * 2]);
        }
        __syncthreads();
        if (c + 2 < NKC) ISSUE(c + 2);
    }
#undef ISSUE

    // ---- epilogue: bias + store logits + per-sub-strip LSE partials ----
    float* out = g_logits + outOff;
    const int sub = ny * 4 + wn;
    const int rbase = m0 + wm * 64 + (lane >> 2);
    const int cb0 = nloc0 + wn * 64 + (lane & 3) * 2;
#pragma unroll
    for (int mt = 0; mt < 4; mt++) {
        int r0 = rbase + mt * 16;
        float v0[16], v1[16];
#pragma unroll
        for (int nt = 0; nt < 8; nt++) {
            int col = cb0 + nt * 8;
            bool ok = (col < N);
            float bx = 0.f, by = 0.f;
            if (ok) { bx = bias[col]; by = bias[col + 1]; }
            float a0 = acc[mt][nt][0] + bx;
            float a1 = acc[mt][nt][1] + by;
            float a2 = acc[mt][nt][2] + bx;
            float a3 = acc[mt][nt][3] + by;
            if (ok) {
                float2 w0 = { a0, a1 }, w1 = { a2, a3 };
                *(float2*)&out[(size_t)r0 * N + col]       = w0;
                *(float2*)&out[(size_t)(r0 + 8) * N + col] = w1;
            }
            v0[nt * 2 + 0] = ok ? a0 : -1e30f;
            v0[nt * 2 + 1] = ok ? a1 : -1e30f;
            v1[nt * 2 + 0] = ok ? a2 : -1e30f;
            v1[nt * 2 + 1] = ok ? a3 : -1e30f;
        }
        float m0v = v0[0], m1v = v1[0];
#pragma unroll
        for (int j = 1; j < 16; j++) { m0v = fmaxf(m0v, v0[j]); m1v = fmaxf(m1v, v1[j]); }
#pragma unroll
        for (int o = 1; o <= 2; o <<= 1) {
            m0v = fmaxf(m0v, __shfl_xor_sync(0xffffffffu, m0v, o));
            m1v = fmaxf(m1v, __shfl_xor_sync(0xffffffffu, m1v, o));
        }
        float s0 = 0.f, s1 = 0.f;
#pragma unroll
        for (int j = 0; j < 16; j++) {
            s0 += __expf(v0[j] - m0v);
            s1 += __expf(v1[j] - m1v);
        }
#pragma unroll
        for (int o = 1; o <= 2; o <<= 1) {
            s0 += __shfl_xor_sync(0xffffffffu, s0, o);
            s1 += __shfl_xor_sync(0xffffffffu, s1, o);
        }
        if ((lane & 3) == 0) {
            g_pm[(size_t)sub * B + r0]     = m0v;
            g_ps[(size_t)sub * B + r0]     = s0;
            g_pm[(size_t)sub * B + r0 + 8] = m1v;
            g_ps[(size_t)sub * B + r0 + 8] = s1;
        }
    }
}

// ============================================================
// Tail (512 threads): per row b — combine LSE partials, NLL,
// hierarchical argmax via t[m]=Mv[m]+sC[mp[m]], acc bins.
// ============================================================
#define TAIL_SMEM ((NC + NM) * 4)
#define TAIL_T 512

__global__ __launch_bounds__(TAIL_T)
void k_tail(const float* __restrict__ labels,
            const float* __restrict__ fpart,
            const int*   __restrict__ fparents,
            const int*   __restrict__ mparents)
{
    extern __shared__ float sh[];
    float* sC = sh;          // NC
    float* tM = sh + NC;     // NM
    __shared__ float lseS[3];
    __shared__ float rf[16];
    __shared__ int   ri[16];

    int b = blockIdx.x, tid = threadIdx.x;
    int lane = tid & 31, wid = tid >> 5;
    const float* Cv = g_logits + OFF_C + (size_t)b * NC;
    const float* Mv = g_logits + OFF_M + (size_t)b * NM;
    const float* Fv = g_logits + OFF_F + (size_t)b * NF;

    for (int i = tid; i < NC; i += TAIL_T) sC[i] = Cv[i];

    // warps 0..2: combine per-sub-strip LSE partials for head wid (2-pass)
    if (wid < 3) {
        int base = (wid == 0) ? SUB_C0 : (wid == 1) ? SUB_M0 : SUB_F0;
        int cnt  = (wid == 0) ? SUB_CN : (wid == 1) ? SUB_MN : SUB_FN;
        float m = -3.402823466e38f;
        for (int i = lane; i < cnt; i += 32)
            m = fmaxf(m, g_pm[(size_t)(base + i) * B + b]);
#pragma unroll
        for (int o = 16; o > 0; o >>= 1)
            m = fmaxf(m, __shfl_xor_sync(0xffffffffu, m, o));
        float s = 0.f;
        for (int i = lane; i < cnt; i += 32)
            s += g_ps[(size_t)(base + i) * B + b] *
                 __expf(g_pm[(size_t)(base + i) * B + b] - m);
#pragma unroll
        for (int o = 16; o > 0; o >>= 1)
            s += __shfl_xor_sync(0xffffffffu, s, o);
        if (lane == 0) lseS[wid] = m + logf(s);
    }
    __syncthreads();

    // t[m] = Mv[m] + sC[mparents[m]]
    for (int i = tid; i < NM; i += TAIL_T) tM[i] = Mv[i] + sC[mparents[i]];
    __syncthreads();

    // hierarchical argmax over fine classes
    float best = -3.402823466e38f; int bi = 0x7fffffff;
    for (int f = tid; f < NF; f += TAIL_T) {
        float sc = Fv[f] + tM[fparents[f]];
        if (sc > best) { best = sc; bi = f; }
    }
#pragma unroll
    for (int o = 16; o > 0; o >>= 1) {
        float ob = __shfl_xor_sync(0xffffffffu, best, o);
        int   oi = __shfl_xor_sync(0xffffffffu, bi,   o);
        if (ob > best || (ob == best && oi < bi)) { best = ob; bi = oi; }
    }
    if (lane == 0) { rf[wid] = best; ri[wid] = bi; }
    __syncthreads();

    if (tid == 0) {
        float bb = rf[0]; int pp = ri[0];
#pragma unroll
        for (int j = 1; j < 16; j++) {
            if (rf[j] > bb || (rf[j] == bb && ri[j] < pp)) { bb = rf[j]; pp = ri[j]; }
        }
        int liC = g_label_idx[b];
        int liM = g_label_idx[B + b];
        int liF = g_label_idx[2 * B + b];
        g_nll[b] = (lseS[0] - sC[liC]) + (lseS[1] - Mv[liM]) + (lseS[2] - Fv[liF]);

        const float RADF = 0.017453292519943295f;
        float lat1 = labels[b * 2]      * RADF;
        float lon1 = labels[b * 2 + 1]  * RADF;
        float lat2 = fpart[pp * 2]      * RADF;
        float lon2 = fpart[pp * 2 + 1]  * RADF;
        float sdlat = sinf((lat2 - lat1) * 0.5f);
        float sdlon = sinf((lon2 - lon1) * 0.5f);
        float a = sdlat * sdlat + cosf(lat1) * cosf(lat2) * sdlon * sdlon;
        a = fminf(fmaxf(a, 0.f), 1.f);
        float d = 2.0f * 6371.0f * asinf(sqrtf(a));
        if (d <= 1.0f)    atomicAdd(&g_counts[0], 1);
        if (d <= 25.0f)   atomicAdd(&g_counts[1], 1);
        if (d <= 200.0f)  atomicAdd(&g_counts[2], 1);
        if (d <= 750.0f)  atomicAdd(&g_counts[3], 1);
        if (d <= 2500.0f) atomicAdd(&g_counts[4], 1);
    }
}

// ============================================================
// Final deterministic reduction -> out[0]=loss, out[1..5]=acc
// ============================================================
__global__ void k_finalize(float* __restrict__ out)
{
    __shared__ float red[256];
    int tid = threadIdx.x;
    float s = 0.f;
    for (int i = tid; i < B; i += 256) s += g_nll[i];
    red[tid] = s; __syncthreads();
    for (int st = 128; st > 0; st >>= 1) {
        if (tid < st) red[tid] += red[tid + st];
        __syncthreads();
    }
    if (tid == 0) out[0] = red[0] / (float)B;
    if (tid < 5)  out[1 + tid] = (float)g_counts[tid] / (float)B;
}

// ============================================================
extern "C" void kernel_launch(void* const* d_in, const int* in_sizes, int n_in,
                              void* d_out, int out_size)
{
    const float* features = (const float*)d_in[0];
    const float* labels   = (const float*)d_in[1];
    const float* cpart    = (const float*)d_in[2];
    const float* mpart    = (const float*)d_in[3];
    const float* fpart    = (const float*)d_in[4];
    const int*   mparents = (const int*)d_in[5];
    const int*   fparents = (const int*)d_in[6];
    const float* cw = (const float*)d_in[7];
    const float* cb = (const float*)d_in[8];
    const float* mw = (const float*)d_in[9];
    const float* mb = (const float*)d_in[10];
    const float* fw = (const float*)d_in[11];
    const float* fb = (const float*)d_in[12];
    float* out = (float*)d_out;

    static int s_attr_done = 0;
    if (!s_attr_done) {
        cudaFuncSetAttribute(k_mmagemm, cudaFuncAttributeMaxDynamicSharedMemorySize,
                             GEMM_SMEM);
        cudaFuncSetAttribute(k_tail, cudaFuncAttributeMaxDynamicSharedMemorySize,
                             TAIL_SMEM);
        s_attr_done = 1;
    }

    // order: GEMM is my 4th launch so ncu (-s 5 -c 1) profiles it
    k_convA<<<((B * D) / 4 + 255) / 256, 256>>>((const float4*)features);
    k_convW<<<dim3(D / 32, NPTOT / 32), dim3(32, 8)>>>(cw, mw, fw);
    k_init<<<(NTOT + 255) / 256, 256>>>(labels, cpart, mpart, fpart);

    k_mmagemm<<<GRID_M * GRID_N, 256, GEMM_SMEM>>>(cb, mb, fb);

    k_labelidx<<<(3 * B + 7) / 8, 256>>>();
    k_tail<<<B, TAIL_T, TAIL_SMEM>>>(labels, fpart, fparents, mparents);
    k_finalize<<<1, 256>>>(out);
}

// round 11
// speedup vs baseline: 2.2675x; 1.5118x over previous
#include <cuda_runtime.h>
#include <cuda_bf16.h>
#include <math.h>
#include <stdint.h>

#define B  4096
#define D  1792
#define NC 3000
#define NM 7000
#define NF 13000
#define NTOT (NC + NM + NF)

// padded (tile-256) class counts for the transposed weight buffers
#define NPC 3072
#define NPM 7168
#define NPF 13056
#define SEC_C 0
#define SEC_M 3072
#define SEC_F 10240
#define NPTOT 23296
#define NSTRIP (NPTOT / 256)      // 91
#define NSUB   (NSTRIP * 4)       // 364 sub-strips of 64 cols

// sub-strip ranges per head (4 per 256-col strip)
#define SUB_C0 0
#define SUB_CN 48                 // 12 strips * 4
#define SUB_M0 48
#define SUB_MN 112                // 28 strips * 4
#define SUB_F0 160
#define SUB_FN 204                // 51 strips * 4

#define OFF_C ((size_t)0)
#define OFF_M ((size_t)B * NC)
#define OFF_F (OFF_M + (size_t)B * NM)

// ---- device scratch (no runtime allocation allowed) ----
__device__ float         g_logits[(size_t)B * NTOT];   // ~377 MB
__device__ __nv_bfloat16 g_A_hi[(size_t)B * D];
__device__ __nv_bfloat16 g_Wt_hi[(size_t)NPTOT * D];   // transposed [n][k]
__device__ float g_pm[(size_t)NSUB * B];               // per-sub-strip row max
__device__ float g_ps[(size_t)NSUB * B];               // per-sub-strip row sumexp
__device__ float g_label_xyz[B * 3];
__device__ float g_part_xyz[NTOT * 3];
__device__ int   g_label_idx[3 * B];
__device__ float g_nll[B];
__device__ int   g_counts[5];

// ============================================================
// helpers
// ============================================================
__device__ __forceinline__ uint32_t smem_to_u32(const void* p) {
    uint32_t a;
    asm("{ .reg .u64 t; cvta.to.shared.u64 t, %1; cvt.u32.u64 %0, t; }"
        : "=r"(a) : "l"(p));
    return a;
}
#define CP_ASYNC16(sm, gp) \
    asm volatile("cp.async.cg.shared.global [%0], [%1], 16;" :: "r"(sm), "l"(gp) : "memory")

__device__ __forceinline__ void ldsm_x4(uint32_t* r, uint32_t addr) {
    asm volatile("ldmatrix.sync.aligned.m8n8.x4.shared.b16 {%0,%1,%2,%3}, [%4];"
        : "=r"(r[0]), "=r"(r[1]), "=r"(r[2]), "=r"(r[3]) : "r"(addr));
}
__device__ __forceinline__ void mma_bf16(float* d, const uint32_t* a, const uint32_t* b) {
    asm volatile("mma.sync.aligned.m16n8k16.row.col.f32.bf16.bf16.f32 "
        "{%0,%1,%2,%3}, {%4,%5,%6,%7}, {%8,%9}, {%0,%1,%2,%3};"
        : "+f"(d[0]), "+f"(d[1]), "+f"(d[2]), "+f"(d[3])
        : "r"(a[0]), "r"(a[1]), "r"(a[2]), "r"(a[3]), "r"(b[0]), "r"(b[1]));
}

// ============================================================
// Kernel: precompute unit vectors, zero counters
// ============================================================
__global__ void k_init(const float* __restrict__ labels,
                       const float* __restrict__ cpart,
                       const float* __restrict__ mpart,
                       const float* __restrict__ fpart)
{
    int t = blockIdx.x * blockDim.x + threadIdx.x;
    const float RADF = 0.017453292519943295f;
    if (t < B) {
        float la = labels[t * 2] * RADF, lo = labels[t * 2 + 1] * RADF;
        float cl = cosf(la);
        g_label_xyz[t * 3 + 0] = cl * cosf(lo);
        g_label_xyz[t * 3 + 1] = cl * sinf(lo);
        g_label_xyz[t * 3 + 2] = sinf(la);
    }
    if (t < NTOT) {
        const float* src;
        if (t < NC)            src = cpart + (size_t)t * 2;
        else if (t < NC + NM)  src = mpart + (size_t)(t - NC) * 2;
        else                   src = fpart + (size_t)(t - NC - NM) * 2;
        float la = src[0] * RADF, lo = src[1] * RADF;
        float cl = cosf(la);
        g_part_xyz[t * 3 + 0] = cl * cosf(lo);
        g_part_xyz[t * 3 + 1] = cl * sinf(lo);
        g_part_xyz[t * 3 + 2] = sinf(la);
    }
    if (t < 5) g_counts[t] = 0;
}

// ============================================================
// Kernel: label index — one WARP per (head, b), shfl argmax reduce
// ============================================================
__global__ __launch_bounds__(256)
void k_labelidx()
{
    int gw = blockIdx.x * 8 + (threadIdx.x >> 5);
    if (gw >= 3 * B) return;
    int lane = threadIdx.x & 31;
    int head = gw >> 12;
    int b    = gw & (B - 1);
    int base, n;
    if (head == 0)      { base = 0;       n = NC; }
    else if (head == 1) { base = NC;      n = NM; }
    else                { base = NC + NM; n = NF; }
    float lx = g_label_xyz[b * 3 + 0];
    float ly = g_label_xyz[b * 3 + 1];
    float lz = g_label_xyz[b * 3 + 2];
    const float* P = g_part_xyz + (size_t)base * 3;
    float best = -2.0f; int bi = 0x7fffffff;
    for (int i = lane; i < n; i += 32) {
        float d = lx * P[i * 3] + ly * P[i * 3 + 1] + lz * P[i * 3 + 2];
        if (d > best || (d == best && i < bi)) { best = d; bi = i; }
    }
#pragma unroll
    for (int off = 16; off > 0; off >>= 1) {
        float ob = __shfl_down_sync(0xffffffffu, best, off);
        int   oi = __shfl_down_sync(0xffffffffu, bi,   off);
        if (ob > best || (ob == best && oi < bi)) { best = ob; bi = oi; }
    }
    if (lane == 0) g_label_idx[head * B + b] = bi;
}

// ============================================================
// Kernel: convert features -> bf16 (hi only), float4 -> uint2
// ============================================================
__global__ void k_convA(const float4* __restrict__ A)
{
    int t = blockIdx.x * blockDim.x + threadIdx.x;
    if (t >= (B * D) / 4) return;
    float4 v = A[t];
    __nv_bfloat16 h0 = __float2bfloat16(v.x);
    __nv_bfloat16 h1 = __float2bfloat16(v.y);
    __nv_bfloat16 h2 = __float2bfloat16(v.z);
    __nv_bfloat16 h3 = __float2bfloat16(v.w);
    uint2 hp;
    hp.x = ((uint32_t)__bfloat16_as_ushort(h1) << 16) | __bfloat16_as_ushort(h0);
    hp.y = ((uint32_t)__bfloat16_as_ushort(h3) << 16) | __bfloat16_as_ushort(h2);
    ((uint2*)g_A_hi)[t] = hp;
}

// ============================================================
// Kernel: fused transpose+convert for ALL heads:
// W [D][N] -> Wt [NPTOT][D] bf16 (zero pad)
// ============================================================
__global__ void k_convW(const float* __restrict__ cw,
                        const float* __restrict__ mw,
                        const float* __restrict__ fw)
{
    __shared__ float t[32][33];
    int k0 = blockIdx.x * 32;
    int ng0 = blockIdx.y * 32;
    const float* W; int N, sec;
    if (ng0 < SEC_M)      { W = cw; N = NC; sec = SEC_C; }
    else if (ng0 < SEC_F) { W = mw; N = NM; sec = SEC_M; }
    else                  { W = fw; N = NF; sec = SEC_F; }
    int n0 = ng0 - sec;
#pragma unroll
    for (int j = 0; j < 32; j += 8) {
        int k = k0 + threadIdx.y + j;
        int n = n0 + threadIdx.x;
        t[threadIdx.y + j][threadIdx.x] = (n < N) ? W[(size_t)k * N + n] : 0.f;
    }
    __syncthreads();
#pragma unroll
    for (int j = 0; j < 32; j += 8) {
        int n = ng0 + threadIdx.y + j;
        int k = k0 + threadIdx.x;
        float v = t[threadIdx.x][threadIdx.y + j];
        g_Wt_hi[(size_t)n * D + k] = __float2bfloat16(v);
    }
}

// ============================================================
// Pure-bf16 GEMM: logits = A_bf16 * B_bf16 (1 product).
// 128x256 tile, warp tile 64x64, 256 threads, BK=64, 2-stage pipe,
// SW128 swizzle, R8-proven loop structure (2 barriers/chunk).
// In-epilogue per-sub-strip LSE partials.
// ============================================================
#define BM 128
#define BN 256
#define BK 64
#define ST_AH 0
#define ST_BH 16384
#define STAGE_BYTES 49152
#define GEMM_SMEM (2 * STAGE_BYTES)        // 96 KB
#define NKC (D / BK)              // 28
#define GRID_M (B / BM)           // 32
#define GRID_N NSTRIP             // 91 = 7 * 13
#define SUPER_N 13

__global__ __launch_bounds__(256, 1)
void k_mmagemm(const float* __restrict__ cb, const float* __restrict__ mb,
               const float* __restrict__ fb)
{
    extern __shared__ __align__(1024) char smem[];
    uint32_t sb = smem_to_u32(smem);
    const int tid  = threadIdx.x;
    const int wid  = tid >> 5;
    const int lane = tid & 31;
    const int wm   = wid >> 2;     // 0..1
    const int wn   = wid & 3;      // 0..3

    // supertile rasterization: 32 m x 13 n per supertile
    const int gid = blockIdx.x;
    const int sy  = gid / (GRID_M * SUPER_N);
    const int r   = gid % (GRID_M * SUPER_N);
    const int mx  = r / SUPER_N;
    const int ny  = sy * SUPER_N + (r % SUPER_N);
    const int m0  = mx * BM;
    const int n0  = ny * BN;

    int N, sec; size_t outOff; const float* bias;
    if (n0 < SEC_M)      { N = NC; sec = SEC_C; outOff = OFF_C; bias = cb; }
    else if (n0 < SEC_F) { N = NM; sec = SEC_M; outOff = OFF_M; bias = mb; }
    else                 { N = NF; sec = SEC_F; outOff = OFF_F; bias = fb; }
    const int nloc0 = n0 - sec;

    // ---- cp.async addressing (SW128, 128B rows) ----
    uint32_t aSw[4], aGo[4];
#pragma unroll
    for (int i = 0; i < 4; i++) {
        int idx = tid + i * 256;              // 0..1023 (A: 128 rows x 8 segs)
        int row = idx >> 3, seg = idx & 7;
        aSw[i] = (uint32_t)(row * 128 + ((seg * 16) ^ ((row & 7) << 4)));
        aGo[i] = (uint32_t)((row * D + seg * 8) * 2);     // byte offset
    }
    uint32_t bSw[8], bGo[8];
#pragma unroll
    for (int i = 0; i < 8; i++) {
        int idx = tid + i * 256;              // 0..2047 (B: 256 rows x 8 segs)
        int row = idx >> 3, seg = idx & 7;
        bSw[i] = (uint32_t)(row * 128 + ((seg * 16) ^ ((row & 7) << 4)));
        bGo[i] = (uint32_t)((row * D + seg * 8) * 2);
    }
    const char* Ahp = (const char*)(g_A_hi  + (size_t)m0 * D);
    const char* Bhp = (const char*)(g_Wt_hi + (size_t)n0 * D);

    // ---- ldsm per-lane addressing (SW128) ----
    uint32_t aTerm[4], aXor[4];
#pragma unroll
    for (int mt = 0; mt < 4; mt++) {
        int row = wm * 64 + mt * 16 + (lane & 7) + ((lane >> 3) & 1) * 8;
        aTerm[mt] = (uint32_t)(row * 128);
        aXor[mt]  = (uint32_t)((row & 7) << 4);
    }
    const uint32_t aCSel = ((lane >> 4) & 1) * 16;
    uint32_t bTerm[4], bXor[4];
#pragma unroll
    for (int np = 0; np < 4; np++) {
        int row = wn * 64 + np * 16 + (lane & 7) + ((lane >> 4) & 1) * 8;
        bTerm[np] = (uint32_t)(row * 128);
        bXor[np]  = (uint32_t)((row & 7) << 4);
    }
    const uint32_t bCSel = ((lane >> 3) & 1) * 16;

    float acc[4][8][4];
#pragma unroll
    for (int i = 0; i < 4; i++)
#pragma unroll
        for (int j = 0; j < 8; j++)
#pragma unroll
            for (int k = 0; k < 4; k++) acc[i][j][k] = 0.f;

#define ISSUE(c) do { \
        int _c = (c); \
        uint32_t kb2 = (uint32_t)(_c * BK * 2); \
        uint32_t st = sb + (uint32_t)(_c & 1) * STAGE_BYTES; \
        _Pragma("unroll") \
        for (int i = 0; i < 4; i++) { \
            CP_ASYNC16(st + ST_AH + aSw[i], Ahp + kb2 + aGo[i]); \
        } \
        _Pragma("unroll") \
        for (int i = 0; i < 8; i++) { \
            CP_ASYNC16(st + ST_BH + bSw[i], Bhp + kb2 + bGo[i]); \
        } \
        asm volatile("cp.async.commit_group;" ::: "memory"); \
    } while (0)

    ISSUE(0);
    ISSUE(1);

    for (int c = 0; c < NKC; c++) {
        if (c + 1 < NKC) asm volatile("cp.async.wait_group 1;" ::: "memory");
        else             asm volatile("cp.async.wait_group 0;" ::: "memory");
        __syncthreads();
        uint32_t st = sb + (uint32_t)(c & 1) * STAGE_BYTES;
#pragma unroll
        for (int ks = 0; ks < 4; ks++) {
            const uint32_t kb = (uint32_t)(ks * 32);
            uint32_t a[4][4], bh[4][4];
#pragma unroll
            for (int mt = 0; mt < 4; mt++)
                ldsm_x4(a[mt], st + ST_AH + aTerm[mt] + ((kb + aCSel) ^ aXor[mt]));
#pragma unroll
            for (int np = 0; np < 4; np++)
                ldsm_x4(bh[np], st + ST_BH + bTerm[np] + ((kb + bCSel) ^ bXor[np]));
#pragma unroll
            for (int mt = 0; mt < 4; mt++)
#pragma unroll
                for (int nt = 0; nt < 8; nt++)
                    mma_bf16(acc[mt][nt], a[mt], &bh[nt >> 1][(nt & 1) * 2]);
        }
        __syncthreads();
        if (c + 2 < NKC) ISSUE(c + 2);
    }
#undef ISSUE

    // ---- epilogue: bias + store logits + per-sub-strip LSE partials ----
    float* out = g_logits + outOff;
    const int sub = ny * 4 + wn;
    const int rbase = m0 + wm * 64 + (lane >> 2);
    const int cb0 = nloc0 + wn * 64 + (lane & 3) * 2;
#pragma unroll
    for (int mt = 0; mt < 4; mt++) {
        int r0 = rbase + mt * 16;
        float v0[16], v1[16];
#pragma unroll
        for (int nt = 0; nt < 8; nt++) {
            int col = cb0 + nt * 8;
            bool ok = (col < N);
            float bx = 0.f, by = 0.f;
            if (ok) { bx = bias[col]; by = bias[col + 1]; }
            float a0 = acc[mt][nt][0] + bx;
            float a1 = acc[mt][nt][1] + by;
            float a2 = acc[mt][nt][2] + bx;
            float a3 = acc[mt][nt][3] + by;
            if (ok) {
                float2 w0 = { a0, a1 }, w1 = { a2, a3 };
                *(float2*)&out[(size_t)r0 * N + col]       = w0;
                *(float2*)&out[(size_t)(r0 + 8) * N + col] = w1;
            }
            v0[nt * 2 + 0] = ok ? a0 : -1e30f;
            v0[nt * 2 + 1] = ok ? a1 : -1e30f;
            v1[nt * 2 + 0] = ok ? a2 : -1e30f;
            v1[nt * 2 + 1] = ok ? a3 : -1e30f;
        }
        float m0v = v0[0], m1v = v1[0];
#pragma unroll
        for (int j = 1; j < 16; j++) { m0v = fmaxf(m0v, v0[j]); m1v = fmaxf(m1v, v1[j]); }
#pragma unroll
        for (int o = 1; o <= 2; o <<= 1) {
            m0v = fmaxf(m0v, __shfl_xor_sync(0xffffffffu, m0v, o));
            m1v = fmaxf(m1v, __shfl_xor_sync(0xffffffffu, m1v, o));
        }
        float s0 = 0.f, s1 = 0.f;
#pragma unroll
        for (int j = 0; j < 16; j++) {
            s0 += __expf(v0[j] - m0v);
            s1 += __expf(v1[j] - m1v);
        }
#pragma unroll
        for (int o = 1; o <= 2; o <<= 1) {
            s0 += __shfl_xor_sync(0xffffffffu, s0, o);
            s1 += __shfl_xor_sync(0xffffffffu, s1, o);
        }
        if ((lane & 3) == 0) {
            g_pm[(size_t)sub * B + r0]     = m0v;
            g_ps[(size_t)sub * B + r0]     = s0;
            g_pm[(size_t)sub * B + r0 + 8] = m1v;
            g_ps[(size_t)sub * B + r0 + 8] = s1;
        }
    }
}

// ============================================================
// Tail (512 threads): per row b — combine LSE partials, NLL,
// hierarchical argmax via t[m]=Mv[m]+sC[mp[m]], acc bins.
// ============================================================
#define TAIL_SMEM ((NC + NM) * 4)
#define TAIL_T 512

__global__ __launch_bounds__(TAIL_T)
void k_tail(const float* __restrict__ labels,
            const float* __restrict__ fpart,
            const int*   __restrict__ fparents,
            const int*   __restrict__ mparents)
{
    extern __shared__ float sh[];
    float* sC = sh;          // NC
    float* tM = sh + NC;     // NM
    __shared__ float lseS[3];
    __shared__ float rf[16];
    __shared__ int   ri[16];

    int b = blockIdx.x, tid = threadIdx.x;
    int lane = tid & 31, wid = tid >> 5;
    const float* Cv = g_logits + OFF_C + (size_t)b * NC;
    const float* Mv = g_logits + OFF_M + (size_t)b * NM;
    const float* Fv = g_logits + OFF_F + (size_t)b * NF;

    for (int i = tid; i < NC; i += TAIL_T) sC[i] = Cv[i];

    // warps 0..2: combine per-sub-strip LSE partials for head wid (2-pass)
    if (wid < 3) {
        int base = (wid == 0) ? SUB_C0 : (wid == 1) ? SUB_M0 : SUB_F0;
        int cnt  = (wid == 0) ? SUB_CN : (wid == 1) ? SUB_MN : SUB_FN;
        float m = -3.402823466e38f;
        for (int i = lane; i < cnt; i += 32)
            m = fmaxf(m, g_pm[(size_t)(base + i) * B + b]);
#pragma unroll
        for (int o = 16; o > 0; o >>= 1)
            m = fmaxf(m, __shfl_xor_sync(0xffffffffu, m, o));
        float s = 0.f;
        for (int i = lane; i < cnt; i += 32)
            s += g_ps[(size_t)(base + i) * B + b] *
                 __expf(g_pm[(size_t)(base + i) * B + b] - m);
#pragma unroll
        for (int o = 16; o > 0; o >>= 1)
            s += __shfl_xor_sync(0xffffffffu, s, o);
        if (lane == 0) lseS[wid] = m + logf(s);
    }
    __syncthreads();

    // t[m] = Mv[m] + sC[mparents[m]]
    for (int i = tid; i < NM; i += TAIL_T) tM[i] = Mv[i] + sC[mparents[i]];
    __syncthreads();

    // hierarchical argmax over fine classes
    float best = -3.402823466e38f; int bi = 0x7fffffff;
    for (int f = tid; f < NF; f += TAIL_T) {
        float sc = Fv[f] + tM[fparents[f]];
        if (sc > best) { best = sc; bi = f; }
    }
#pragma unroll
    for (int o = 16; o > 0; o >>= 1) {
        float ob = __shfl_xor_sync(0xffffffffu, best, o);
        int   oi = __shfl_xor_sync(0xffffffffu, bi,   o);
        if (ob > best || (ob == best && oi < bi)) { best = ob; bi = oi; }
    }
    if (lane == 0) { rf[wid] = best; ri[wid] = bi; }
    __syncthreads();

    if (tid == 0) {
        float bb = rf[0]; int pp = ri[0];
#pragma unroll
        for (int j = 1; j < 16; j++) {
            if (rf[j] > bb || (rf[j] == bb && ri[j] < pp)) { bb = rf[j]; pp = ri[j]; }
        }
        int liC = g_label_idx[b];
        int liM = g_label_idx[B + b];
        int liF = g_label_idx[2 * B + b];
        g_nll[b] = (lseS[0] - sC[liC]) + (lseS[1] - Mv[liM]) + (lseS[2] - Fv[liF]);

        const float RADF = 0.017453292519943295f;
        float lat1 = labels[b * 2]      * RADF;
        float lon1 = labels[b * 2 + 1]  * RADF;
        float lat2 = fpart[pp * 2]      * RADF;
        float lon2 = fpart[pp * 2 + 1]  * RADF;
        float sdlat = sinf((lat2 - lat1) * 0.5f);
        float sdlon = sinf((lon2 - lon1) * 0.5f);
        float a = sdlat * sdlat + cosf(lat1) * cosf(lat2) * sdlon * sdlon;
        a = fminf(fmaxf(a, 0.f), 1.f);
        float d = 2.0f * 6371.0f * asinf(sqrtf(a));
        if (d <= 1.0f)    atomicAdd(&g_counts[0], 1);
        if (d <= 25.0f)   atomicAdd(&g_counts[1], 1);
        if (d <= 200.0f)  atomicAdd(&g_counts[2], 1);
        if (d <= 750.0f)  atomicAdd(&g_counts[3], 1);
        if (d <= 2500.0f) atomicAdd(&g_counts[4], 1);
    }
}

// ============================================================
// Final deterministic reduction -> out[0]=loss, out[1..5]=acc
// ============================================================
__global__ void k_finalize(float* __restrict__ out)
{
    __shared__ float red[256];
    int tid = threadIdx.x;
    float s = 0.f;
    for (int i = tid; i < B; i += 256) s += g_nll[i];
    red[tid] = s; __syncthreads();
    for (int st = 128; st > 0; st >>= 1) {
        if (tid < st) red[tid] += red[tid + st];
        __syncthreads();
    }
    if (tid == 0) out[0] = red[0] / (float)B;
    if (tid < 5)  out[1 + tid] = (float)g_counts[tid] / (float)B;
}

// ============================================================
extern "C" void kernel_launch(void* const* d_in, const int* in_sizes, int n_in,
                              void* d_out, int out_size)
{
    const float* features = (const float*)d_in[0];
    const float* labels   = (const float*)d_in[1];
    const float* cpart    = (const float*)d_in[2];
    const float* mpart    = (const float*)d_in[3];
    const float* fpart    = (const float*)d_in[4];
    const int*   mparents = (const int*)d_in[5];
    const int*   fparents = (const int*)d_in[6];
    const float* cw = (const float*)d_in[7];
    const float* cb = (const float*)d_in[8];
    const float* mw = (const float*)d_in[9];
    const float* mb = (const float*)d_in[10];
    const float* fw = (const float*)d_in[11];
    const float* fb = (const float*)d_in[12];
    float* out = (float*)d_out;

    static int s_attr_done = 0;
    if (!s_attr_done) {
        cudaFuncSetAttribute(k_mmagemm, cudaFuncAttributeMaxDynamicSharedMemorySize,
                             GEMM_SMEM);
        cudaFuncSetAttribute(k_tail, cudaFuncAttributeMaxDynamicSharedMemorySize,
                             TAIL_SMEM);
        s_attr_done = 1;
    }

    // order: GEMM is my 4th launch so ncu (-s 5 -c 1) profiles it
    k_convA<<<((B * D) / 4 + 255) / 256, 256>>>((const float4*)features);
    k_convW<<<dim3(D / 32, NPTOT / 32), dim3(32, 8)>>>(cw, mw, fw);
    k_init<<<(NTOT + 255) / 256, 256>>>(labels, cpart, mpart, fpart);

    k_mmagemm<<<GRID_M * GRID_N, 256, GEMM_SMEM>>>(cb, mb, fb);

    k_labelidx<<<(3 * B + 7) / 8, 256>>>();
    k_tail<<<B, TAIL_T, TAIL_SMEM>>>(labels, fpart, fparents, mparents);
    k_finalize<<<1, 256>>>(out);
}

// round 12
// speedup vs baseline: 2.4889x; 1.0976x over previous
#include <cuda_runtime.h>
#include <cuda_bf16.h>
#include <math.h>
#include <stdint.h>

#define B  4096
#define D  1792
#define NC 3000
#define NM 7000
#define NF 13000
#define NTOT (NC + NM + NF)

// padded (tile-128) class counts for the transposed weight buffers
#define NPC 3072
#define NPM 7168
#define NPF 13056
#define SEC_C 0
#define SEC_M 3072
#define SEC_F 10240
#define NPTOT 23296
#define NSTRIP (NPTOT / 128)      // 182 n-tiles
#define NSUB   (NSTRIP * 4)       // 728 sub-strips of 32 cols

// sub-strip ranges per head (4 per 128-col tile)
#define SUB_C0 0
#define SUB_CN 96                 // 24 tiles * 4
#define SUB_M0 96
#define SUB_MN 224                // 56 tiles * 4
#define SUB_F0 320
#define SUB_FN 408                // 102 tiles * 4

#define OFF_C ((size_t)0)
#define OFF_M ((size_t)B * NC)
#define OFF_F (OFF_M + (size_t)B * NM)

// ---- device scratch (no runtime allocation allowed) ----
__device__ float         g_logits[(size_t)B * NTOT];   // ~377 MB
__device__ __nv_bfloat16 g_A_hi[(size_t)B * D];
__device__ __nv_bfloat16 g_Wt_hi[(size_t)NPTOT * D];   // transposed [n][k]
__device__ float g_pm[(size_t)NSUB * B];               // per-sub-strip row max
__device__ float g_ps[(size_t)NSUB * B];               // per-sub-strip row sumexp
__device__ float g_label_xyz[B * 3];
__device__ float g_part_xyz[NTOT * 3];
__device__ int   g_label_idx[3 * B];
__device__ float g_nll[B];
__device__ int   g_counts[5];

// ============================================================
// helpers
// ============================================================
__device__ __forceinline__ uint32_t smem_to_u32(const void* p) {
    uint32_t a;
    asm("{ .reg .u64 t; cvta.to.shared.u64 t, %1; cvt.u32.u64 %0, t; }"
        : "=r"(a) : "l"(p));
    return a;
}
#define CP_ASYNC16(sm, gp) \
    asm volatile("cp.async.cg.shared.global [%0], [%1], 16;" :: "r"(sm), "l"(gp) : "memory")

__device__ __forceinline__ void ldsm_x4(uint32_t* r, uint32_t addr) {
    asm volatile("ldmatrix.sync.aligned.m8n8.x4.shared.b16 {%0,%1,%2,%3}, [%4];"
        : "=r"(r[0]), "=r"(r[1]), "=r"(r[2]), "=r"(r[3]) : "r"(addr));
}
__device__ __forceinline__ void mma_bf16(float* d, const uint32_t* a, const uint32_t* b) {
    asm volatile("mma.sync.aligned.m16n8k16.row.col.f32.bf16.bf16.f32 "
        "{%0,%1,%2,%3}, {%4,%5,%6,%7}, {%8,%9}, {%0,%1,%2,%3};"
        : "+f"(d[0]), "+f"(d[1]), "+f"(d[2]), "+f"(d[3])
        : "r"(a[0]), "r"(a[1]), "r"(a[2]), "r"(a[3]), "r"(b[0]), "r"(b[1]));
}

// ============================================================
// Kernel: precompute unit vectors, zero counters
// ============================================================
__global__ void k_init(const float* __restrict__ labels,
                       const float* __restrict__ cpart,
                       const float* __restrict__ mpart,
                       const float* __restrict__ fpart)
{
    int t = blockIdx.x * blockDim.x + threadIdx.x;
    const float RADF = 0.017453292519943295f;
    if (t < B) {
        float la = labels[t * 2] * RADF, lo = labels[t * 2 + 1] * RADF;
        float cl = cosf(la);
        g_label_xyz[t * 3 + 0] = cl * cosf(lo);
        g_label_xyz[t * 3 + 1] = cl * sinf(lo);
        g_label_xyz[t * 3 + 2] = sinf(la);
    }
    if (t < NTOT) {
        const float* src;
        if (t < NC)            src = cpart + (size_t)t * 2;
        else if (t < NC + NM)  src = mpart + (size_t)(t - NC) * 2;
        else                   src = fpart + (size_t)(t - NC - NM) * 2;
        float la = src[0] * RADF, lo = src[1] * RADF;
        float cl = cosf(la);
        g_part_xyz[t * 3 + 0] = cl * cosf(lo);
        g_part_xyz[t * 3 + 1] = cl * sinf(lo);
        g_part_xyz[t * 3 + 2] = sinf(la);
    }
    if (t < 5) g_counts[t] = 0;
}

// ============================================================
// Kernel: label index — one WARP per (head, b), shfl argmax reduce
// ============================================================
__global__ __launch_bounds__(256)
void k_labelidx()
{
    int gw = blockIdx.x * 8 + (threadIdx.x >> 5);
    if (gw >= 3 * B) return;
    int lane = threadIdx.x & 31;
    int head = gw >> 12;
    int b    = gw & (B - 1);
    int base, n;
    if (head == 0)      { base = 0;       n = NC; }
    else if (head == 1) { base = NC;      n = NM; }
    else                { base = NC + NM; n = NF; }
    float lx = g_label_xyz[b * 3 + 0];
    float ly = g_label_xyz[b * 3 + 1];
    float lz = g_label_xyz[b * 3 + 2];
    const float* P = g_part_xyz + (size_t)base * 3;
    float best = -2.0f; int bi = 0x7fffffff;
    for (int i = lane; i < n; i += 32) {
        float d = lx * P[i * 3] + ly * P[i * 3 + 1] + lz * P[i * 3 + 2];
        if (d > best || (d == best && i < bi)) { best = d; bi = i; }
    }
#pragma unroll
    for (int off = 16; off > 0; off >>= 1) {
        float ob = __shfl_down_sync(0xffffffffu, best, off);
        int   oi = __shfl_down_sync(0xffffffffu, bi,   off);
        if (ob > best || (ob == best && oi < bi)) { best = ob; bi = oi; }
    }
    if (lane == 0) g_label_idx[head * B + b] = bi;
}

// ============================================================
// Kernel: convert features -> bf16, float4 -> uint2
// ============================================================
__global__ void k_convA(const float4* __restrict__ A)
{
    int t = blockIdx.x * blockDim.x + threadIdx.x;
    if (t >= (B * D) / 4) return;
    float4 v = A[t];
    __nv_bfloat16 h0 = __float2bfloat16(v.x);
    __nv_bfloat16 h1 = __float2bfloat16(v.y);
    __nv_bfloat16 h2 = __float2bfloat16(v.z);
    __nv_bfloat16 h3 = __float2bfloat16(v.w);
    uint2 hp;
    hp.x = ((uint32_t)__bfloat16_as_ushort(h1) << 16) | __bfloat16_as_ushort(h0);
    hp.y = ((uint32_t)__bfloat16_as_ushort(h3) << 16) | __bfloat16_as_ushort(h2);
    ((uint2*)g_A_hi)[t] = hp;
}

// ============================================================
// Kernel: fused transpose+convert for ALL heads:
// W [D][N] -> Wt [NPTOT][D] bf16 (zero pad)
// ============================================================
__global__ void k_convW(const float* __restrict__ cw,
                        const float* __restrict__ mw,
                        const float* __restrict__ fw)
{
    __shared__ float t[32][33];
    int k0 = blockIdx.x * 32;
    int ng0 = blockIdx.y * 32;
    const float* W; int N, sec;
    if (ng0 < SEC_M)      { W = cw; N = NC; sec = SEC_C; }
    else if (ng0 < SEC_F) { W = mw; N = NM; sec = SEC_M; }
    else                  { W = fw; N = NF; sec = SEC_F; }
    int n0 = ng0 - sec;
#pragma unroll
    for (int j = 0; j < 32; j += 8) {
        int k = k0 + threadIdx.y + j;
        int n = n0 + threadIdx.x;
        t[threadIdx.y + j][threadIdx.x] = (n < N) ? W[(size_t)k * N + n] : 0.f;
    }
    __syncthreads();
#pragma unroll
    for (int j = 0; j < 32; j += 8) {
        int n = ng0 + threadIdx.y + j;
        int k = k0 + threadIdx.x;
        float v = t[threadIdx.x][threadIdx.y + j];
        g_Wt_hi[(size_t)n * D + k] = __float2bfloat16(v);
    }
}

// ============================================================
// Pure-bf16 GEMM, 2 CTAs/SM: 128x128 tile, warp tile 64x32,
// 256 threads, BK=64, 2-stage pipe, SW128 swizzle.
// In-epilogue per-sub-strip (32-col) LSE partials.
// ============================================================
#define BM 128
#define BN 128
#define BK 64
#define ST_A 0
#define ST_B 16384
#define STAGE_BYTES 32768
#define GEMM_SMEM (2 * STAGE_BYTES)        // 64 KB -> 2 CTAs/SM
#define NKC (D / BK)              // 28
#define GRID_M (B / BM)           // 32
#define GRID_N NSTRIP             // 182 = 14 * 13
#define SUPER_N 13
#define A_GSTRIDE (32 * D * 2)    // +32 rows, bytes
#define SW_STRIDE (32 * 128)      // +32 rows in smem (row&7 invariant)

__global__ __launch_bounds__(256, 2)
void k_mmagemm(const float* __restrict__ cb, const float* __restrict__ mb,
               const float* __restrict__ fb)
{
    extern __shared__ __align__(1024) char smem[];
    uint32_t sb = smem_to_u32(smem);
    const int tid  = threadIdx.x;
    const int wid  = tid >> 5;
    const int lane = tid & 31;
    const int wm   = wid >> 2;     // 0..1
    const int wn   = wid & 3;      // 0..3

    // supertile rasterization: 32 m x 13 n per supertile (182 = 14*13 exact)
    const int gid = blockIdx.x;
    const int sy  = gid / (GRID_M * SUPER_N);
    const int r   = gid % (GRID_M * SUPER_N);
    const int mx  = r / SUPER_N;
    const int ny  = sy * SUPER_N + (r % SUPER_N);
    const int m0  = mx * BM;
    const int n0  = ny * BN;

    int N, sec; size_t outOff; const float* bias;
    if (n0 < SEC_M)      { N = NC; sec = SEC_C; outOff = OFF_C; bias = cb; }
    else if (n0 < SEC_F) { N = NM; sec = SEC_M; outOff = OFF_M; bias = mb; }
    else                 { N = NF; sec = SEC_F; outOff = OFF_F; bias = fb; }
    const int nloc0 = n0 - sec;

    // ---- cp.async addressing (SW128; bases only, +32-row strides) ----
    const int crow = tid >> 3, cseg = tid & 7;
    const uint32_t cSw0 = (uint32_t)(crow * 128 + ((cseg * 16) ^ ((crow & 7) << 4)));
    const uint32_t cGo0 = (uint32_t)((crow * D + cseg * 8) * 2);
    const char* Ahp = (const char*)(g_A_hi  + (size_t)m0 * D);
    const char* Bhp = (const char*)(g_Wt_hi + (size_t)n0 * D);

    // ---- ldsm per-lane addressing (bases; +16-row stride = 2048B) ----
    const int arow = wm * 64 + (lane & 7) + ((lane >> 3) & 1) * 8;
    const uint32_t aTerm0 = (uint32_t)(arow * 128);
    const uint32_t aXor   = (uint32_t)((arow & 7) << 4);
    const uint32_t aCSel  = ((lane >> 4) & 1) * 16;
    const int brow = wn * 32 + (lane & 7) + ((lane >> 4) & 1) * 8;
    const uint32_t bTerm0 = (uint32_t)(brow * 128);
    const uint32_t bXor   = (uint32_t)((brow & 7) << 4);
    const uint32_t bCSel  = ((lane >> 3) & 1) * 16;

    float acc[4][4][4];
#pragma unroll
    for (int i = 0; i < 4; i++)
#pragma unroll
        for (int j = 0; j < 4; j++)
#pragma unroll
            for (int k = 0; k < 4; k++) acc[i][j][k] = 0.f;

#define ISSUE(c) do { \
        int _c = (c); \
        uint32_t kb2 = (uint32_t)(_c * BK * 2); \
        uint32_t st = sb + (uint32_t)(_c & 1) * STAGE_BYTES; \
        _Pragma("unroll") \
        for (int i = 0; i < 4; i++) { \
            CP_ASYNC16(st + ST_A + cSw0 + i * SW_STRIDE, Ahp + kb2 + cGo0 + i * A_GSTRIDE); \
            CP_ASYNC16(st + ST_B + cSw0 + i * SW_STRIDE, Bhp + kb2 + cGo0 + i * A_GSTRIDE); \
        } \
        asm volatile("cp.async.commit_group;" ::: "memory"); \
    } while (0)

    ISSUE(0);
    ISSUE(1);

    for (int c = 0; c < NKC; c++) {
        if (c + 1 < NKC) asm volatile("cp.async.wait_group 1;" ::: "memory");
        else             asm volatile("cp.async.wait_group 0;" ::: "memory");
        __syncthreads();
        uint32_t st = sb + (uint32_t)(c & 1) * STAGE_BYTES;
#pragma unroll
        for (int ks = 0; ks < 4; ks++) {
            const uint32_t kb = (uint32_t)(ks * 32);
            uint32_t a[4][4], bh[2][4];
            const uint32_t aOff = (kb + aCSel) ^ aXor;
            const uint32_t bOff = (kb + bCSel) ^ bXor;
#pragma unroll
            for (int mt = 0; mt < 4; mt++)
                ldsm_x4(a[mt], st + ST_A + aTerm0 + mt * 2048 + aOff);
#pragma unroll
            for (int np = 0; np < 2; np++)
                ldsm_x4(bh[np], st + ST_B + bTerm0 + np * 2048 + bOff);
#pragma unroll
            for (int mt = 0; mt < 4; mt++)
#pragma unroll
                for (int nt = 0; nt < 4; nt++)
                    mma_bf16(acc[mt][nt], a[mt], &bh[nt >> 1][(nt & 1) * 2]);
        }
        __syncthreads();
        if (c + 2 < NKC) ISSUE(c + 2);
    }
#undef ISSUE

    // ---- epilogue: bias + store logits + per-sub-strip LSE partials ----
    float* out = g_logits + outOff;
    const int sub = ny * 4 + wn;
    const int rbase = m0 + wm * 64 + (lane >> 2);
    const int cb0 = nloc0 + wn * 32 + (lane & 3) * 2;
#pragma unroll
    for (int mt = 0; mt < 4; mt++) {
        int r0 = rbase + mt * 16;
        float v0[8], v1[8];
#pragma unroll
        for (int nt = 0; nt < 4; nt++) {
            int col = cb0 + nt * 8;
            bool ok = (col < N);
            float bx = 0.f, by = 0.f;
            if (ok) { bx = bias[col]; by = bias[col + 1]; }
            float a0 = acc[mt][nt][0] + bx;
            float a1 = acc[mt][nt][1] + by;
            float a2 = acc[mt][nt][2] + bx;
            float a3 = acc[mt][nt][3] + by;
            if (ok) {
                float2 w0 = { a0, a1 }, w1 = { a2, a3 };
                *(float2*)&out[(size_t)r0 * N + col]       = w0;
                *(float2*)&out[(size_t)(r0 + 8) * N + col] = w1;
            }
            v0[nt * 2 + 0] = ok ? a0 : -1e30f;
            v0[nt * 2 + 1] = ok ? a1 : -1e30f;
            v1[nt * 2 + 0] = ok ? a2 : -1e30f;
            v1[nt * 2 + 1] = ok ? a3 : -1e30f;
        }
        float m0v = v0[0], m1v = v1[0];
#pragma unroll
        for (int j = 1; j < 8; j++) { m0v = fmaxf(m0v, v0[j]); m1v = fmaxf(m1v, v1[j]); }
#pragma unroll
        for (int o = 1; o <= 2; o <<= 1) {
            m0v = fmaxf(m0v, __shfl_xor_sync(0xffffffffu, m0v, o));
            m1v = fmaxf(m1v, __shfl_xor_sync(0xffffffffu, m1v, o));
        }
        float s0 = 0.f, s1 = 0.f;
#pragma unroll
        for (int j = 0; j < 8; j++) {
            s0 += __expf(v0[j] - m0v);
            s1 += __expf(v1[j] - m1v);
        }
#pragma unroll
        for (int o = 1; o <= 2; o <<= 1) {
            s0 += __shfl_xor_sync(0xffffffffu, s0, o);
            s1 += __shfl_xor_sync(0xffffffffu, s1, o);
        }
        if ((lane & 3) == 0) {
            g_pm[(size_t)sub * B + r0]     = m0v;
            g_ps[(size_t)sub * B + r0]     = s0;
            g_pm[(size_t)sub * B + r0 + 8] = m1v;
            g_ps[(size_t)sub * B + r0 + 8] = s1;
        }
    }
}

// ============================================================
// Tail (512 threads): per row b — combine LSE partials, NLL,
// hierarchical argmax via t[m]=Mv[m]+sC[mp[m]], acc bins.
// ============================================================
#define TAIL_SMEM ((NC + NM) * 4)
#define TAIL_T 512

__global__ __launch_bounds__(TAIL_T)
void k_tail(const float* __restrict__ labels,
            const float* __restrict__ fpart,
            const int*   __restrict__ fparents,
            const int*   __restrict__ mparents)
{
    extern __shared__ float sh[];
    float* sC = sh;          // NC
    float* tM = sh + NC;     // NM
    __shared__ float lseS[3];
    __shared__ float rf[16];
    __shared__ int   ri[16];

    int b = blockIdx.x, tid = threadIdx.x;
    int lane = tid & 31, wid = tid >> 5;
    const float* Cv = g_logits + OFF_C + (size_t)b * NC;
    const float* Mv = g_logits + OFF_M + (size_t)b * NM;
    const float* Fv = g_logits + OFF_F + (size_t)b * NF;

    for (int i = tid; i < NC; i += TAIL_T) sC[i] = Cv[i];

    // warps 0..2: combine per-sub-strip LSE partials for head wid (2-pass)
    if (wid < 3) {
        int base = (wid == 0) ? SUB_C0 : (wid == 1) ? SUB_M0 : SUB_F0;
        int cnt  = (wid == 0) ? SUB_CN : (wid == 1) ? SUB_MN : SUB_FN;
        float m = -3.402823466e38f;
        for (int i = lane; i < cnt; i += 32)
            m = fmaxf(m, g_pm[(size_t)(base + i) * B + b]);
#pragma unroll
        for (int o = 16; o > 0; o >>= 1)
            m = fmaxf(m, __shfl_xor_sync(0xffffffffu, m, o));
        float s = 0.f;
        for (int i = lane; i < cnt; i += 32)
            s += g_ps[(size_t)(base + i) * B + b] *
                 __expf(g_pm[(size_t)(base + i) * B + b] - m);
#pragma unroll
        for (int o = 16; o > 0; o >>= 1)
            s += __shfl_xor_sync(0xffffffffu, s, o);
        if (lane == 0) lseS[wid] = m + logf(s);
    }
    __syncthreads();

    // t[m] = Mv[m] + sC[mparents[m]]
    for (int i = tid; i < NM; i += TAIL_T) tM[i] = Mv[i] + sC[mparents[i]];
    __syncthreads();

    // hierarchical argmax over fine classes
    float best = -3.402823466e38f; int bi = 0x7fffffff;
    for (int f = tid; f < NF; f += TAIL_T) {
        float sc = Fv[f] + tM[fparents[f]];
        if (sc > best) { best = sc; bi = f; }
    }
#pragma unroll
    for (int o = 16; o > 0; o >>= 1) {
        float ob = __shfl_xor_sync(0xffffffffu, best, o);
        int   oi = __shfl_xor_sync(0xffffffffu, bi,   o);
        if (ob > best || (ob == best && oi < bi)) { best = ob; bi = oi; }
    }
    if (lane == 0) { rf[wid] = best; ri[wid] = bi; }
    __syncthreads();

    if (tid == 0) {
        float bb = rf[0]; int pp = ri[0];
#pragma unroll
        for (int j = 1; j < 16; j++) {
            if (rf[j] > bb || (rf[j] == bb && ri[j] < pp)) { bb = rf[j]; pp = ri[j]; }
        }
        int liC = g_label_idx[b];
        int liM = g_label_idx[B + b];
        int liF = g_label_idx[2 * B + b];
        g_nll[b] = (lseS[0] - sC[liC]) + (lseS[1] - Mv[liM]) + (lseS[2] - Fv[liF]);

        const float RADF = 0.017453292519943295f;
        float lat1 = labels[b * 2]      * RADF;
        float lon1 = labels[b * 2 + 1]  * RADF;
        float lat2 = fpart[pp * 2]      * RADF;
        float lon2 = fpart[pp * 2 + 1]  * RADF;
        float sdlat = sinf((lat2 - lat1) * 0.5f);
        float sdlon = sinf((lon2 - lon1) * 0.5f);
        float a = sdlat * sdlat + cosf(lat1) * cosf(lat2) * sdlon * sdlon;
        a = fminf(fmaxf(a, 0.f), 1.f);
        float d = 2.0f * 6371.0f * asinf(sqrtf(a));
        if (d <= 1.0f)    atomicAdd(&g_counts[0], 1);
        if (d <= 25.0f)   atomicAdd(&g_counts[1], 1);
        if (d <= 200.0f)  atomicAdd(&g_counts[2], 1);
        if (d <= 750.0f)  atomicAdd(&g_counts[3], 1);
        if (d <= 2500.0f) atomicAdd(&g_counts[4], 1);
    }
}

// ============================================================
// Final deterministic reduction -> out[0]=loss, out[1..5]=acc
// ============================================================
__global__ void k_finalize(float* __restrict__ out)
{
    __shared__ float red[256];
    int tid = threadIdx.x;
    float s = 0.f;
    for (int i = tid; i < B; i += 256) s += g_nll[i];
    red[tid] = s; __syncthreads();
    for (int st = 128; st > 0; st >>= 1) {
        if (tid < st) red[tid] += red[tid + st];
        __syncthreads();
    }
    if (tid == 0) out[0] = red[0] / (float)B;
    if (tid < 5)  out[1 + tid] = (float)g_counts[tid] / (float)B;
}

// ============================================================
extern "C" void kernel_launch(void* const* d_in, const int* in_sizes, int n_in,
                              void* d_out, int out_size)
{
    const float* features = (const float*)d_in[0];
    const float* labels   = (const float*)d_in[1];
    const float* cpart    = (const float*)d_in[2];
    const float* mpart    = (const float*)d_in[3];
    const float* fpart    = (const float*)d_in[4];
    const int*   mparents = (const int*)d_in[5];
    const int*   fparents = (const int*)d_in[6];
    const float* cw = (const float*)d_in[7];
    const float* cb = (const float*)d_in[8];
    const float* mw = (const float*)d_in[9];
    const float* mb = (const float*)d_in[10];
    const float* fw = (const float*)d_in[11];
    const float* fb = (const float*)d_in[12];
    float* out = (float*)d_out;

    static int s_attr_done = 0;
    if (!s_attr_done) {
        cudaFuncSetAttribute(k_mmagemm, cudaFuncAttributeMaxDynamicSharedMemorySize,
                             GEMM_SMEM);
        cudaFuncSetAttribute(k_tail, cudaFuncAttributeMaxDynamicSharedMemorySize,
                             TAIL_SMEM);
        s_attr_done = 1;
    }

    // order: GEMM is my 4th launch so ncu (-s 5 -c 1) profiles it
    k_convA<<<((B * D) / 4 + 255) / 256, 256>>>((const float4*)features);
    k_convW<<<dim3(D / 32, NPTOT / 32), dim3(32, 8)>>>(cw, mw, fw);
    k_init<<<(NTOT + 255) / 256, 256>>>(labels, cpart, mpart, fpart);

    k_mmagemm<<<GRID_M * GRID_N, 256, GEMM_SMEM>>>(cb, mb, fb);

    k_labelidx<<<(3 * B + 7) / 8, 256>>>();
    k_tail<<<B, TAIL_T, TAIL_SMEM>>>(labels, fpart, fparents, mparents);
    k_finalize<<<1, 256>>>(out);
}

// round 13
// speedup vs baseline: 2.5138x; 1.0100x over previous
#include <cuda_runtime.h>
#include <cuda_bf16.h>
#include <math.h>
#include <stdint.h>

#define B  4096
#define D  1792
#define NC 3000
#define NM 7000
#define NF 13000
#define NTOT (NC + NM + NF)

// padded (tile-128) class counts for the transposed weight buffers
#define NPC 3072
#define NPM 7168
#define NPF 13056
#define SEC_C 0
#define SEC_M 3072
#define SEC_F 10240
#define NPTOT 23296
#define NSTRIP (NPTOT / 128)      // 182 n-tiles
#define NSUB   (NSTRIP * 4)       // 728 sub-strips of 32 cols

// sub-strip ranges per head (4 per 128-col tile)
#define SUB_C0 0
#define SUB_CN 96                 // 24 tiles * 4
#define SUB_M0 96
#define SUB_MN 224                // 56 tiles * 4
#define SUB_F0 320
#define SUB_FN 408                // 102 tiles * 4

#define OFF_C ((size_t)0)
#define OFF_M ((size_t)B * NC)
#define OFF_F (OFF_M + (size_t)B * NM)

// ---- device scratch (no runtime allocation allowed) ----
__device__ __nv_bfloat16 g_logits[(size_t)B * NTOT];   // ~188 MB (bf16)
__device__ __nv_bfloat16 g_A_hi[(size_t)B * D];
__device__ __nv_bfloat16 g_Wt_hi[(size_t)NPTOT * D];   // transposed [n][k]
__device__ float g_pm[(size_t)NSUB * B];               // per-sub-strip row max
__device__ float g_ps[(size_t)NSUB * B];               // per-sub-strip row sumexp
__device__ float g_label_xyz[B * 3];
__device__ float g_part_xyz[NTOT * 3];
__device__ int   g_label_idx[3 * B];
__device__ float g_nll[B];
__device__ int   g_counts[5];

// ============================================================
// helpers
// ============================================================
__device__ __forceinline__ uint32_t smem_to_u32(const void* p) {
    uint32_t a;
    asm("{ .reg .u64 t; cvta.to.shared.u64 t, %1; cvt.u32.u64 %0, t; }"
        : "=r"(a) : "l"(p));
    return a;
}
#define CP_ASYNC16(sm, gp) \
    asm volatile("cp.async.cg.shared.global [%0], [%1], 16;" :: "r"(sm), "l"(gp) : "memory")

__device__ __forceinline__ void ldsm_x4(uint32_t* r, uint32_t addr) {
    asm volatile("ldmatrix.sync.aligned.m8n8.x4.shared.b16 {%0,%1,%2,%3}, [%4];"
        : "=r"(r[0]), "=r"(r[1]), "=r"(r[2]), "=r"(r[3]) : "r"(addr));
}
__device__ __forceinline__ void mma_bf16(float* d, const uint32_t* a, const uint32_t* b) {
    asm volatile("mma.sync.aligned.m16n8k16.row.col.f32.bf16.bf16.f32 "
        "{%0,%1,%2,%3}, {%4,%5,%6,%7}, {%8,%9}, {%0,%1,%2,%3};"
        : "+f"(d[0]), "+f"(d[1]), "+f"(d[2]), "+f"(d[3])
        : "r"(a[0]), "r"(a[1]), "r"(a[2]), "r"(a[3]), "r"(b[0]), "r"(b[1]));
}
__device__ __forceinline__ uint32_t pack_bf16x2(float x, float y) {
    __nv_bfloat16 bx = __float2bfloat16(x), by = __float2bfloat16(y);
    return ((uint32_t)__bfloat16_as_ushort(by) << 16) | __bfloat16_as_ushort(bx);
}

// ============================================================
// Kernel: precompute unit vectors, zero counters
// ============================================================
__global__ void k_init(const float* __restrict__ labels,
                       const float* __restrict__ cpart,
                       const float* __restrict__ mpart,
                       const float* __restrict__ fpart)
{
    int t = blockIdx.x * blockDim.x + threadIdx.x;
    const float RADF = 0.017453292519943295f;
    if (t < B) {
        float la = labels[t * 2] * RADF, lo = labels[t * 2 + 1] * RADF;
        float cl = cosf(la);
        g_label_xyz[t * 3 + 0] = cl * cosf(lo);
        g_label_xyz[t * 3 + 1] = cl * sinf(lo);
        g_label_xyz[t * 3 + 2] = sinf(la);
    }
    if (t < NTOT) {
        const float* src;
        if (t < NC)            src = cpart + (size_t)t * 2;
        else if (t < NC + NM)  src = mpart + (size_t)(t - NC) * 2;
        else                   src = fpart + (size_t)(t - NC - NM) * 2;
        float la = src[0] * RADF, lo = src[1] * RADF;
        float cl = cosf(la);
        g_part_xyz[t * 3 + 0] = cl * cosf(lo);
        g_part_xyz[t * 3 + 1] = cl * sinf(lo);
        g_part_xyz[t * 3 + 2] = sinf(la);
    }
    if (t < 5) g_counts[t] = 0;
}

// ============================================================
// Kernel: label index — one WARP per (head, b), shfl argmax reduce
// ============================================================
__global__ __launch_bounds__(256)
void k_labelidx()
{
    int gw = blockIdx.x * 8 + (threadIdx.x >> 5);
    if (gw >= 3 * B) return;
    int lane = threadIdx.x & 31;
    int head = gw >> 12;
    int b    = gw & (B - 1);
    int base, n;
    if (head == 0)      { base = 0;       n = NC; }
    else if (head == 1) { base = NC;      n = NM; }
    else                { base = NC + NM; n = NF; }
    float lx = g_label_xyz[b * 3 + 0];
    float ly = g_label_xyz[b * 3 + 1];
    float lz = g_label_xyz[b * 3 + 2];
    const float* P = g_part_xyz + (size_t)base * 3;
    float best = -2.0f; int bi = 0x7fffffff;
    for (int i = lane; i < n; i += 32) {
        float d = lx * P[i * 3] + ly * P[i * 3 + 1] + lz * P[i * 3 + 2];
        if (d > best || (d == best && i < bi)) { best = d; bi = i; }
    }
#pragma unroll
    for (int off = 16; off > 0; off >>= 1) {
        float ob = __shfl_down_sync(0xffffffffu, best, off);
        int   oi = __shfl_down_sync(0xffffffffu, bi,   off);
        if (ob > best || (ob == best && oi < bi)) { best = ob; bi = oi; }
    }
    if (lane == 0) g_label_idx[head * B + b] = bi;
}

// ============================================================
// Kernel: convert features -> bf16, float4 -> uint2
// ============================================================
__global__ void k_convA(const float4* __restrict__ A)
{
    int t = blockIdx.x * blockDim.x + threadIdx.x;
    if (t >= (B * D) / 4) return;
    float4 v = A[t];
    uint2 hp;
    hp.x = pack_bf16x2(v.x, v.y);
    hp.y = pack_bf16x2(v.z, v.w);
    ((uint2*)g_A_hi)[t] = hp;
}

// ============================================================
// Kernel: fused transpose+convert for ALL heads:
// W [D][N] -> Wt [NPTOT][D] bf16 (zero pad)
// ============================================================
__global__ void k_convW(const float* __restrict__ cw,
                        const float* __restrict__ mw,
                        const float* __restrict__ fw)
{
    __shared__ float t[32][33];
    int k0 = blockIdx.x * 32;
    int ng0 = blockIdx.y * 32;
    const float* W; int N, sec;
    if (ng0 < SEC_M)      { W = cw; N = NC; sec = SEC_C; }
    else if (ng0 < SEC_F) { W = mw; N = NM; sec = SEC_M; }
    else                  { W = fw; N = NF; sec = SEC_F; }
    int n0 = ng0 - sec;
#pragma unroll
    for (int j = 0; j < 32; j += 8) {
        int k = k0 + threadIdx.y + j;
        int n = n0 + threadIdx.x;
        t[threadIdx.y + j][threadIdx.x] = (n < N) ? W[(size_t)k * N + n] : 0.f;
    }
    __syncthreads();
#pragma unroll
    for (int j = 0; j < 32; j += 8) {
        int n = ng0 + threadIdx.y + j;
        int k = k0 + threadIdx.x;
        float v = t[threadIdx.x][threadIdx.y + j];
        g_Wt_hi[(size_t)n * D + k] = __float2bfloat16(v);
    }
}

// ============================================================
// Pure-bf16 GEMM, 2 CTAs/SM: 128x128 tile, warp tile 64x32,
// 256 threads, BK=64, 3-stage pipe, ONE barrier/chunk, SW128.
// Epilogue: bf16 logits store + per-sub-strip (32-col) LSE partials.
// ============================================================
#define BM 128
#define BN 128
#define BK 64
#define ST_A 0
#define ST_B 16384
#define STAGE_BYTES 32768
#define NSTG 3
#define GEMM_SMEM (NSTG * STAGE_BYTES)     // 96 KB -> 2 CTAs/SM (192 KB)
#define NKC (D / BK)              // 28
#define GRID_M (B / BM)           // 32
#define GRID_N NSTRIP             // 182 = 14 * 13
#define SUPER_N 13
#define A_GSTRIDE (32 * D * 2)    // +32 rows, bytes
#define SW_STRIDE (32 * 128)      // +32 rows in smem (row&7 invariant)

__global__ __launch_bounds__(256, 2)
void k_mmagemm(const float* __restrict__ cb, const float* __restrict__ mb,
               const float* __restrict__ fb)
{
    extern __shared__ __align__(1024) char smem[];
    uint32_t sb = smem_to_u32(smem);
    const int tid  = threadIdx.x;
    const int wid  = tid >> 5;
    const int lane = tid & 31;
    const int wm   = wid >> 2;     // 0..1
    const int wn   = wid & 3;      // 0..3

    // supertile rasterization: 32 m x 13 n per supertile (182 = 14*13 exact)
    const int gid = blockIdx.x;
    const int sy  = gid / (GRID_M * SUPER_N);
    const int r   = gid % (GRID_M * SUPER_N);
    const int mx  = r / SUPER_N;
    const int ny  = sy * SUPER_N + (r % SUPER_N);
    const int m0  = mx * BM;
    const int n0  = ny * BN;

    int N, sec; size_t outOff; const float* bias;
    if (n0 < SEC_M)      { N = NC; sec = SEC_C; outOff = OFF_C; bias = cb; }
    else if (n0 < SEC_F) { N = NM; sec = SEC_M; outOff = OFF_M; bias = mb; }
    else                 { N = NF; sec = SEC_F; outOff = OFF_F; bias = fb; }
    const int nloc0 = n0 - sec;

    // ---- cp.async addressing (SW128; bases only, +32-row strides) ----
    const int crow = tid >> 3, cseg = tid & 7;
    const uint32_t cSw0 = (uint32_t)(crow * 128 + ((cseg * 16) ^ ((crow & 7) << 4)));
    const uint32_t cGo0 = (uint32_t)((crow * D + cseg * 8) * 2);
    const char* Ahp = (const char*)(g_A_hi  + (size_t)m0 * D);
    const char* Bhp = (const char*)(g_Wt_hi + (size_t)n0 * D);

    // ---- ldsm per-lane addressing (bases; +16-row stride = 2048B) ----
    const int arow = wm * 64 + (lane & 7) + ((lane >> 3) & 1) * 8;
    const uint32_t aTerm0 = (uint32_t)(arow * 128);
    const uint32_t aXor   = (uint32_t)((arow & 7) << 4);
    const uint32_t aCSel  = ((lane >> 4) & 1) * 16;
    const int brow = wn * 32 + (lane & 7) + ((lane >> 4) & 1) * 8;
    const uint32_t bTerm0 = (uint32_t)(brow * 128);
    const uint32_t bXor   = (uint32_t)((brow & 7) << 4);
    const uint32_t bCSel  = ((lane >> 3) & 1) * 16;

    float acc[4][4][4];
#pragma unroll
    for (int i = 0; i < 4; i++)
#pragma unroll
        for (int j = 0; j < 4; j++)
#pragma unroll
            for (int k = 0; k < 4; k++) acc[i][j][k] = 0.f;

#define ISSUE(c) do { \
        int _c = (c); \
        uint32_t kb2 = (uint32_t)(_c * BK * 2); \
        uint32_t st = sb + (uint32_t)(_c % NSTG) * STAGE_BYTES; \
        _Pragma("unroll") \
        for (int i = 0; i < 4; i++) { \
            CP_ASYNC16(st + ST_A + cSw0 + i * SW_STRIDE, Ahp + kb2 + cGo0 + i * A_GSTRIDE); \
            CP_ASYNC16(st + ST_B + cSw0 + i * SW_STRIDE, Bhp + kb2 + cGo0 + i * A_GSTRIDE); \
        } \
        asm volatile("cp.async.commit_group;" ::: "memory"); \
    } while (0)

    ISSUE(0);
    ISSUE(1);

    for (int c = 0; c < NKC; c++) {
        if (c + 1 < NKC) asm volatile("cp.async.wait_group 1;" ::: "memory");
        else             asm volatile("cp.async.wait_group 0;" ::: "memory");
        __syncthreads();   // chunk c visible; all warps done with stage (c-1)%3
        if (c + 2 < NKC) ISSUE(c + 2);   // stage (c+2)%3 == (c-1)%3: safe

        uint32_t st = sb + (uint32_t)(c % NSTG) * STAGE_BYTES;
#pragma unroll
        for (int ks = 0; ks < 4; ks++) {
            const uint32_t kb = (uint32_t)(ks * 32);
            uint32_t a[4][4], bh[2][4];
            const uint32_t aOff = (kb + aCSel) ^ aXor;
            const uint32_t bOff = (kb + bCSel) ^ bXor;
#pragma unroll
            for (int mt = 0; mt < 4; mt++)
                ldsm_x4(a[mt], st + ST_A + aTerm0 + mt * 2048 + aOff);
#pragma unroll
            for (int np = 0; np < 2; np++)
                ldsm_x4(bh[np], st + ST_B + bTerm0 + np * 2048 + bOff);
#pragma unroll
            for (int mt = 0; mt < 4; mt++)
#pragma unroll
                for (int nt = 0; nt < 4; nt++)
                    mma_bf16(acc[mt][nt], a[mt], &bh[nt >> 1][(nt & 1) * 2]);
        }
    }
#undef ISSUE

    // ---- epilogue: bias + store bf16 logits + per-sub-strip LSE partials ----
    __nv_bfloat16* out = g_logits + outOff;
    const int sub = ny * 4 + wn;
    const int rbase = m0 + wm * 64 + (lane >> 2);
    const int cb0 = nloc0 + wn * 32 + (lane & 3) * 2;
#pragma unroll
    for (int mt = 0; mt < 4; mt++) {
        int r0 = rbase + mt * 16;
        float v0[8], v1[8];
#pragma unroll
        for (int nt = 0; nt < 4; nt++) {
            int col = cb0 + nt * 8;
            bool ok = (col < N);
            float bx = 0.f, by = 0.f;
            if (ok) { bx = bias[col]; by = bias[col + 1]; }
            float a0 = acc[mt][nt][0] + bx;
            float a1 = acc[mt][nt][1] + by;
            float a2 = acc[mt][nt][2] + bx;
            float a3 = acc[mt][nt][3] + by;
            if (ok) {
                *(uint32_t*)&out[(size_t)r0 * N + col]       = pack_bf16x2(a0, a1);
                *(uint32_t*)&out[(size_t)(r0 + 8) * N + col] = pack_bf16x2(a2, a3);
            }
            v0[nt * 2 + 0] = ok ? a0 : -1e30f;
            v0[nt * 2 + 1] = ok ? a1 : -1e30f;
            v1[nt * 2 + 0] = ok ? a2 : -1e30f;
            v1[nt * 2 + 1] = ok ? a3 : -1e30f;
        }
        float m0v = v0[0], m1v = v1[0];
#pragma unroll
        for (int j = 1; j < 8; j++) { m0v = fmaxf(m0v, v0[j]); m1v = fmaxf(m1v, v1[j]); }
#pragma unroll
        for (int o = 1; o <= 2; o <<= 1) {
            m0v = fmaxf(m0v, __shfl_xor_sync(0xffffffffu, m0v, o));
            m1v = fmaxf(m1v, __shfl_xor_sync(0xffffffffu, m1v, o));
        }
        float s0 = 0.f, s1 = 0.f;
#pragma unroll
        for (int j = 0; j < 8; j++) {
            s0 += __expf(v0[j] - m0v);
            s1 += __expf(v1[j] - m1v);
        }
#pragma unroll
        for (int o = 1; o <= 2; o <<= 1) {
            s0 += __shfl_xor_sync(0xffffffffu, s0, o);
            s1 += __shfl_xor_sync(0xffffffffu, s1, o);
        }
        if ((lane & 3) == 0) {
            g_pm[(size_t)sub * B + r0]     = m0v;
            g_ps[(size_t)sub * B + r0]     = s0;
            g_pm[(size_t)sub * B + r0 + 8] = m1v;
            g_ps[(size_t)sub * B + r0 + 8] = s1;
        }
    }
}

// ============================================================
// Tail (512 threads): per row b — combine LSE partials, NLL,
// hierarchical argmax via t[m]=Mv[m]+sC[mp[m]], acc bins.
// Logits read as bf16.
// ============================================================
#define TAIL_SMEM ((NC + NM) * 4)
#define TAIL_T 512

__global__ __launch_bounds__(TAIL_T)
void k_tail(const float* __restrict__ labels,
            const float* __restrict__ fpart,
            const int*   __restrict__ fparents,
            const int*   __restrict__ mparents)
{
    extern __shared__ float sh[];
    float* sC = sh;          // NC
    float* tM = sh + NC;     // NM
    __shared__ float lseS[3];
    __shared__ float rf[16];
    __shared__ int   ri[16];

    int b = blockIdx.x, tid = threadIdx.x;
    int lane = tid & 31, wid = tid >> 5;
    const __nv_bfloat16* Cv = g_logits + OFF_C + (size_t)b * NC;
    const __nv_bfloat16* Mv = g_logits + OFF_M + (size_t)b * NM;
    const __nv_bfloat16* Fv = g_logits + OFF_F + (size_t)b * NF;

    for (int i = tid; i < NC; i += TAIL_T) sC[i] = __bfloat162float(Cv[i]);

    // warps 0..2: combine per-sub-strip LSE partials for head wid (2-pass)
    if (wid < 3) {
        int base = (wid == 0) ? SUB_C0 : (wid == 1) ? SUB_M0 : SUB_F0;
        int cnt  = (wid == 0) ? SUB_CN : (wid == 1) ? SUB_MN : SUB_FN;
        float m = -3.402823466e38f;
        for (int i = lane; i < cnt; i += 32)
            m = fmaxf(m, g_pm[(size_t)(base + i) * B + b]);
#pragma unroll
        for (int o = 16; o > 0; o >>= 1)
            m = fmaxf(m, __shfl_xor_sync(0xffffffffu, m, o));
        float s = 0.f;
        for (int i = lane; i < cnt; i += 32)
            s += g_ps[(size_t)(base + i) * B + b] *
                 __expf(g_pm[(size_t)(base + i) * B + b] - m);
#pragma unroll
        for (int o = 16; o > 0; o >>= 1)
            s += __shfl_xor_sync(0xffffffffu, s, o);
        if (lane == 0) lseS[wid] = m + logf(s);
    }
    __syncthreads();

    // t[m] = Mv[m] + sC[mparents[m]]
    for (int i = tid; i < NM; i += TAIL_T)
        tM[i] = __bfloat162float(Mv[i]) + sC[mparents[i]];
    __syncthreads();

    // hierarchical argmax over fine classes
    float best = -3.402823466e38f; int bi = 0x7fffffff;
    for (int f = tid; f < NF; f += TAIL_T) {
        float sc = __bfloat162float(Fv[f]) + tM[fparents[f]];
        if (sc > best) { best = sc; bi = f; }
    }
#pragma unroll
    for (int o = 16; o > 0; o >>= 1) {
        float ob = __shfl_xor_sync(0xffffffffu, best, o);
        int   oi = __shfl_xor_sync(0xffffffffu, bi,   o);
        if (ob > best || (ob == best && oi < bi)) { best = ob; bi = oi; }
    }
    if (lane == 0) { rf[wid] = best; ri[wid] = bi; }
    __syncthreads();

    if (tid == 0) {
        float bb = rf[0]; int pp = ri[0];
#pragma unroll
        for (int j = 1; j < 16; j++) {
            if (rf[j] > bb || (rf[j] == bb && ri[j] < pp)) { bb = rf[j]; pp = ri[j]; }
        }
        int liC = g_label_idx[b];
        int liM = g_label_idx[B + b];
        int liF = g_label_idx[2 * B + b];
        g_nll[b] = (lseS[0] - sC[liC]) + (lseS[1] - __bfloat162float(Mv[liM]))
                 + (lseS[2] - __bfloat162float(Fv[liF]));

        const float RADF = 0.017453292519943295f;
        float lat1 = labels[b * 2]      * RADF;
        float lon1 = labels[b * 2 + 1]  * RADF;
        float lat2 = fpart[pp * 2]      * RADF;
        float lon2 = fpart[pp * 2 + 1]  * RADF;
        float sdlat = sinf((lat2 - lat1) * 0.5f);
        float sdlon = sinf((lon2 - lon1) * 0.5f);
        float a = sdlat * sdlat + cosf(lat1) * cosf(lat2) * sdlon * sdlon;
        a = fminf(fmaxf(a, 0.f), 1.f);
        float d = 2.0f * 6371.0f * asinf(sqrtf(a));
        if (d <= 1.0f)    atomicAdd(&g_counts[0], 1);
        if (d <= 25.0f)   atomicAdd(&g_counts[1], 1);
        if (d <= 200.0f)  atomicAdd(&g_counts[2], 1);
        if (d <= 750.0f)  atomicAdd(&g_counts[3], 1);
        if (d <= 2500.0f) atomicAdd(&g_counts[4], 1);
    }
}

// ============================================================
// Final deterministic reduction -> out[0]=loss, out[1..5]=acc
// ============================================================
__global__ void k_finalize(float* __restrict__ out)
{
    __shared__ float red[256];
    int tid = threadIdx.x;
    float s = 0.f;
    for (int i = tid; i < B; i += 256) s += g_nll[i];
    red[tid] = s; __syncthreads();
    for (int st = 128; st > 0; st >>= 1) {
        if (tid < st) red[tid] += red[tid + st];
        __syncthreads();
    }
    if (tid == 0) out[0] = red[0] / (float)B;
    if (tid < 5)  out[1 + tid] = (float)g_counts[tid] / (float)B;
}

// ============================================================
extern "C" void kernel_launch(void* const* d_in, const int* in_sizes, int n_in,
                              void* d_out, int out_size)
{
    const float* features = (const float*)d_in[0];
    const float* labels   = (const float*)d_in[1];
    const float* cpart    = (const float*)d_in[2];
    const float* mpart    = (const float*)d_in[3];
    const float* fpart    = (const float*)d_in[4];
    const int*   mparents = (const int*)d_in[5];
    const int*   fparents = (const int*)d_in[6];
    const float* cw = (const float*)d_in[7];
    const float* cb = (const float*)d_in[8];
    const float* mw = (const float*)d_in[9];
    const float* mb = (const float*)d_in[10];
    const float* fw = (const float*)d_in[11];
    const float* fb = (const float*)d_in[12];
    float* out = (float*)d_out;

    static int s_attr_done = 0;
    if (!s_attr_done) {
        cudaFuncSetAttribute(k_mmagemm, cudaFuncAttributeMaxDynamicSharedMemorySize,
                             GEMM_SMEM);
        cudaFuncSetAttribute(k_tail, cudaFuncAttributeMaxDynamicSharedMemorySize,
                             TAIL_SMEM);
        s_attr_done = 1;
    }

    // order: GEMM is my 4th launch so ncu (-s 5 -c 1) profiles it
    k_convA<<<((B * D) / 4 + 255) / 256, 256>>>((const float4*)features);
    k_convW<<<dim3(D / 32, NPTOT / 32), dim3(32, 8)>>>(cw, mw, fw);
    k_init<<<(NTOT + 255) / 256, 256>>>(labels, cpart, mpart, fpart);

    k_mmagemm<<<GRID_M * GRID_N, 256, GEMM_SMEM>>>(cb, mb, fb);

    k_labelidx<<<(3 * B + 7) / 8, 256>>>();
    k_tail<<<B, TAIL_T, TAIL_SMEM>>>(labels, fpart, fparents, mparents);
    k_finalize<<<1, 256>>>(out);
}

// round 14
// speedup vs baseline: 2.6018x; 1.0350x over previous
#include <cuda_runtime.h>
#include <cuda_bf16.h>
#include <math.h>
#include <stdint.h>

#define B  4096
#define D  1792
#define NC 3000
#define NM 7000
#define NF 13000
#define NTOT (NC + NM + NF)

// padded (tile-128) class counts for the transposed weight buffers
#define NPC 3072
#define NPM 7168
#define NPF 13056
#define SEC_C 0
#define SEC_M 3072
#define SEC_F 10240
#define NPTOT 23296
#define NSTRIP (NPTOT / 128)      // 182 n-tiles
#define NSUB   (NSTRIP * 4)       // 728 sub-strips of 32 cols

// sub-strip ranges per head (4 per 128-col tile)
#define SUB_C0 0
#define SUB_CN 96                 // 24 tiles * 4
#define SUB_M0 96
#define SUB_MN 224                // 56 tiles * 4
#define SUB_F0 320
#define SUB_FN 408                // 102 tiles * 4

#define OFF_C ((size_t)0)
#define OFF_M ((size_t)B * NC)
#define OFF_F (OFF_M + (size_t)B * NM)

// ---- device scratch (no runtime allocation allowed) ----
__device__ __nv_bfloat16 g_logits[(size_t)B * NTOT];   // ~188 MB (bf16)
__device__ __nv_bfloat16 g_A_hi[(size_t)B * D];
__device__ __nv_bfloat16 g_Wt_hi[(size_t)NPTOT * D];   // transposed [n][k]
__device__ float g_pm[(size_t)B * NSUB];               // [b][sub] row max
__device__ float g_ps[(size_t)B * NSUB];               // [b][sub] row sumexp
__device__ float g_label_xyz[B * 3];
__device__ float g_part_xyz[NTOT * 3];
__device__ int   g_label_idx[3 * B];
__device__ float g_nll[B];
__device__ int   g_counts[5];

// ============================================================
// helpers
// ============================================================
__device__ __forceinline__ uint32_t smem_to_u32(const void* p) {
    uint32_t a;
    asm("{ .reg .u64 t; cvta.to.shared.u64 t, %1; cvt.u32.u64 %0, t; }"
        : "=r"(a) : "l"(p));
    return a;
}
#define CP_ASYNC16(sm, gp) \
    asm volatile("cp.async.cg.shared.global [%0], [%1], 16;" :: "r"(sm), "l"(gp) : "memory")

__device__ __forceinline__ void ldsm_x4(uint32_t* r, uint32_t addr) {
    asm volatile("ldmatrix.sync.aligned.m8n8.x4.shared.b16 {%0,%1,%2,%3}, [%4];"
        : "=r"(r[0]), "=r"(r[1]), "=r"(r[2]), "=r"(r[3]) : "r"(addr));
}
__device__ __forceinline__ void mma_bf16(float* d, const uint32_t* a, const uint32_t* b) {
    asm volatile("mma.sync.aligned.m16n8k16.row.col.f32.bf16.bf16.f32 "
        "{%0,%1,%2,%3}, {%4,%5,%6,%7}, {%8,%9}, {%0,%1,%2,%3};"
        : "+f"(d[0]), "+f"(d[1]), "+f"(d[2]), "+f"(d[3])
        : "r"(a[0]), "r"(a[1]), "r"(a[2]), "r"(a[3]), "r"(b[0]), "r"(b[1]));
}
__device__ __forceinline__ uint32_t pack_bf16x2(float x, float y) {
    __nv_bfloat16 bx = __float2bfloat16(x), by = __float2bfloat16(y);
    return ((uint32_t)__bfloat16_as_ushort(by) << 16) | __bfloat16_as_ushort(bx);
}

// ============================================================
// Kernel: precompute unit vectors, zero counters
// ============================================================
__global__ void k_init(const float* __restrict__ labels,
                       const float* __restrict__ cpart,
                       const float* __restrict__ mpart,
                       const float* __restrict__ fpart)
{
    int t = blockIdx.x * blockDim.x + threadIdx.x;
    const float RADF = 0.017453292519943295f;
    if (t < B) {
        float la = labels[t * 2] * RADF, lo = labels[t * 2 + 1] * RADF;
        float cl = cosf(la);
        g_label_xyz[t * 3 + 0] = cl * cosf(lo);
        g_label_xyz[t * 3 + 1] = cl * sinf(lo);
        g_label_xyz[t * 3 + 2] = sinf(la);
    }
    if (t < NTOT) {
        const float* src;
        if (t < NC)            src = cpart + (size_t)t * 2;
        else if (t < NC + NM)  src = mpart + (size_t)(t - NC) * 2;
        else                   src = fpart + (size_t)(t - NC - NM) * 2;
        float la = src[0] * RADF, lo = src[1] * RADF;
        float cl = cosf(la);
        g_part_xyz[t * 3 + 0] = cl * cosf(lo);
        g_part_xyz[t * 3 + 1] = cl * sinf(lo);
        g_part_xyz[t * 3 + 2] = sinf(la);
    }
    if (t < 5) g_counts[t] = 0;
}

// ============================================================
// Kernel: label index — one WARP per (head, b), shfl argmax reduce
// ============================================================
__global__ __launch_bounds__(256)
void k_labelidx()
{
    int gw = blockIdx.x * 8 + (threadIdx.x >> 5);
    if (gw >= 3 * B) return;
    int lane = threadIdx.x & 31;
    int head = gw >> 12;
    int b    = gw & (B - 1);
    int base, n;
    if (head == 0)      { base = 0;       n = NC; }
    else if (head == 1) { base = NC;      n = NM; }
    else                { base = NC + NM; n = NF; }
    float lx = g_label_xyz[b * 3 + 0];
    float ly = g_label_xyz[b * 3 + 1];
    float lz = g_label_xyz[b * 3 + 2];
    const float* P = g_part_xyz + (size_t)base * 3;
    float best = -2.0f; int bi = 0x7fffffff;
    for (int i = lane; i < n; i += 32) {
        float d = lx * P[i * 3] + ly * P[i * 3 + 1] + lz * P[i * 3 + 2];
        if (d > best || (d == best && i < bi)) { best = d; bi = i; }
    }
#pragma unroll
    for (int off = 16; off > 0; off >>= 1) {
        float ob = __shfl_down_sync(0xffffffffu, best, off);
        int   oi = __shfl_down_sync(0xffffffffu, bi,   off);
        if (ob > best || (ob == best && oi < bi)) { best = ob; bi = oi; }
    }
    if (lane == 0) g_label_idx[head * B + b] = bi;
}

// ============================================================
// Kernel: convert features -> bf16, float4 -> uint2
// ============================================================
__global__ void k_convA(const float4* __restrict__ A)
{
    int t = blockIdx.x * blockDim.x + threadIdx.x;
    if (t >= (B * D) / 4) return;
    float4 v = A[t];
    uint2 hp;
    hp.x = pack_bf16x2(v.x, v.y);
    hp.y = pack_bf16x2(v.z, v.w);
    ((uint2*)g_A_hi)[t] = hp;
}

// ============================================================
// Kernel: fused transpose+convert for ALL heads:
// W [D][N] -> Wt [NPTOT][D] bf16 (zero pad)
// ============================================================
__global__ void k_convW(const float* __restrict__ cw,
                        const float* __restrict__ mw,
                        const float* __restrict__ fw)
{
    __shared__ float t[32][33];
    int k0 = blockIdx.x * 32;
    int ng0 = blockIdx.y * 32;
    const float* W; int N, sec;
    if (ng0 < SEC_M)      { W = cw; N = NC; sec = SEC_C; }
    else if (ng0 < SEC_F) { W = mw; N = NM; sec = SEC_M; }
    else                  { W = fw; N = NF; sec = SEC_F; }
    int n0 = ng0 - sec;
#pragma unroll
    for (int j = 0; j < 32; j += 8) {
        int k = k0 + threadIdx.y + j;
        int n = n0 + threadIdx.x;
        t[threadIdx.y + j][threadIdx.x] = (n < N) ? W[(size_t)k * N + n] : 0.f;
    }
    __syncthreads();
#pragma unroll
    for (int j = 0; j < 32; j += 8) {
        int n = ng0 + threadIdx.y + j;
        int k = k0 + threadIdx.x;
        float v = t[threadIdx.x][threadIdx.y + j];
        g_Wt_hi[(size_t)n * D + k] = __float2bfloat16(v);
    }
}

// ============================================================
// Pure-bf16 GEMM, 2 CTAs/SM: 128x128 tile, warp tile 64x32,
// 256 threads, BK=64, 3-stage pipe, ONE barrier/chunk, SW128.
// Epilogue: bf16 logits store + per-sub-strip (32-col) LSE partials.
// ============================================================
#define BM 128
#define BN 128
#define BK 64
#define ST_A 0
#define ST_B 16384
#define STAGE_BYTES 32768
#define NSTG 3
#define GEMM_SMEM (NSTG * STAGE_BYTES)     // 96 KB -> 2 CTAs/SM (192 KB)
#define NKC (D / BK)              // 28
#define GRID_M (B / BM)           // 32
#define GRID_N NSTRIP             // 182 = 14 * 13
#define SUPER_N 13
#define A_GSTRIDE (32 * D * 2)    // +32 rows, bytes
#define SW_STRIDE (32 * 128)      // +32 rows in smem (row&7 invariant)

__global__ __launch_bounds__(256, 2)
void k_mmagemm(const float* __restrict__ cb, const float* __restrict__ mb,
               const float* __restrict__ fb)
{
    extern __shared__ __align__(1024) char smem[];
    uint32_t sb = smem_to_u32(smem);
    const int tid  = threadIdx.x;
    const int wid  = tid >> 5;
    const int lane = tid & 31;
    const int wm   = wid >> 2;     // 0..1
    const int wn   = wid & 3;      // 0..3

    // supertile rasterization: 32 m x 13 n per supertile (182 = 14*13 exact)
    const int gid = blockIdx.x;
    const int sy  = gid / (GRID_M * SUPER_N);
    const int r   = gid % (GRID_M * SUPER_N);
    const int mx  = r / SUPER_N;
    const int ny  = sy * SUPER_N + (r % SUPER_N);
    const int m0  = mx * BM;
    const int n0  = ny * BN;

    int N, sec; size_t outOff; const float* bias;
    if (n0 < SEC_M)      { N = NC; sec = SEC_C; outOff = OFF_C; bias = cb; }
    else if (n0 < SEC_F) { N = NM; sec = SEC_M; outOff = OFF_M; bias = mb; }
    else                 { N = NF; sec = SEC_F; outOff = OFF_F; bias = fb; }
    const int nloc0 = n0 - sec;

    // ---- cp.async addressing (SW128; bases only, +32-row strides) ----
    const int crow = tid >> 3, cseg = tid & 7;
    const uint32_t cSw0 = (uint32_t)(crow * 128 + ((cseg * 16) ^ ((crow & 7) << 4)));
    const uint32_t cGo0 = (uint32_t)((crow * D + cseg * 8) * 2);
    const char* Ahp = (const char*)(g_A_hi  + (size_t)m0 * D);
    const char* Bhp = (const char*)(g_Wt_hi + (size_t)n0 * D);

    // ---- ldsm per-lane addressing (bases; +16-row stride = 2048B) ----
    const int arow = wm * 64 + (lane & 7) + ((lane >> 3) & 1) * 8;
    const uint32_t aTerm0 = (uint32_t)(arow * 128);
    const uint32_t aXor   = (uint32_t)((arow & 7) << 4);
    const uint32_t aCSel  = ((lane >> 4) & 1) * 16;
    const int brow = wn * 32 + (lane & 7) + ((lane >> 4) & 1) * 8;
    const uint32_t bTerm0 = (uint32_t)(brow * 128);
    const uint32_t bXor   = (uint32_t)((brow & 7) << 4);
    const uint32_t bCSel  = ((lane >> 3) & 1) * 16;

    float acc[4][4][4];
#pragma unroll
    for (int i = 0; i < 4; i++)
#pragma unroll
        for (int j = 0; j < 4; j++)
#pragma unroll
            for (int k = 0; k < 4; k++) acc[i][j][k] = 0.f;

#define ISSUE(c) do { \
        int _c = (c); \
        uint32_t kb2 = (uint32_t)(_c * BK * 2); \
        uint32_t st = sb + (uint32_t)(_c % NSTG) * STAGE_BYTES; \
        _Pragma("unroll") \
        for (int i = 0; i < 4; i++) { \
            CP_ASYNC16(st + ST_A + cSw0 + i * SW_STRIDE, Ahp + kb2 + cGo0 + i * A_GSTRIDE); \
            CP_ASYNC16(st + ST_B + cSw0 + i * SW_STRIDE, Bhp + kb2 + cGo0 + i * A_GSTRIDE); \
        } \
        asm volatile("cp.async.commit_group;" ::: "memory"); \
    } while (0)

    ISSUE(0);
    ISSUE(1);

    for (int c = 0; c < NKC; c++) {
        if (c + 1 < NKC) asm volatile("cp.async.wait_group 1;" ::: "memory");
        else             asm volatile("cp.async.wait_group 0;" ::: "memory");
        __syncthreads();   // chunk c visible; all warps done with stage (c-1)%3
        if (c + 2 < NKC) ISSUE(c + 2);   // stage (c+2)%3 == (c-1)%3: safe

        uint32_t st = sb + (uint32_t)(c % NSTG) * STAGE_BYTES;
#pragma unroll
        for (int ks = 0; ks < 4; ks++) {
            const uint32_t kb = (uint32_t)(ks * 32);
            uint32_t a[4][4], bh[2][4];
            const uint32_t aOff = (kb + aCSel) ^ aXor;
            const uint32_t bOff = (kb + bCSel) ^ bXor;
#pragma unroll
            for (int mt = 0; mt < 4; mt++)
                ldsm_x4(a[mt], st + ST_A + aTerm0 + mt * 2048 + aOff);
#pragma unroll
            for (int np = 0; np < 2; np++)
                ldsm_x4(bh[np], st + ST_B + bTerm0 + np * 2048 + bOff);
#pragma unroll
            for (int mt = 0; mt < 4; mt++)
#pragma unroll
                for (int nt = 0; nt < 4; nt++)
                    mma_bf16(acc[mt][nt], a[mt], &bh[nt >> 1][(nt & 1) * 2]);
        }
    }
#undef ISSUE

    // ---- epilogue: bias + store bf16 logits + per-sub-strip LSE partials ----
    __nv_bfloat16* out = g_logits + outOff;
    const int sub = ny * 4 + wn;
    const int rbase = m0 + wm * 64 + (lane >> 2);
    const int cb0 = nloc0 + wn * 32 + (lane & 3) * 2;
#pragma unroll
    for (int mt = 0; mt < 4; mt++) {
        int r0 = rbase + mt * 16;
        float v0[8], v1[8];
#pragma unroll
        for (int nt = 0; nt < 4; nt++) {
            int col = cb0 + nt * 8;
            bool ok = (col < N);
            float bx = 0.f, by = 0.f;
            if (ok) { bx = bias[col]; by = bias[col + 1]; }
            float a0 = acc[mt][nt][0] + bx;
            float a1 = acc[mt][nt][1] + by;
            float a2 = acc[mt][nt][2] + bx;
            float a3 = acc[mt][nt][3] + by;
            if (ok) {
                *(uint32_t*)&out[(size_t)r0 * N + col]       = pack_bf16x2(a0, a1);
                *(uint32_t*)&out[(size_t)(r0 + 8) * N + col] = pack_bf16x2(a2, a3);
            }
            v0[nt * 2 + 0] = ok ? a0 : -1e30f;
            v0[nt * 2 + 1] = ok ? a1 : -1e30f;
            v1[nt * 2 + 0] = ok ? a2 : -1e30f;
            v1[nt * 2 + 1] = ok ? a3 : -1e30f;
        }
        float m0v = v0[0], m1v = v1[0];
#pragma unroll
        for (int j = 1; j < 8; j++) { m0v = fmaxf(m0v, v0[j]); m1v = fmaxf(m1v, v1[j]); }
#pragma unroll
        for (int o = 1; o <= 2; o <<= 1) {
            m0v = fmaxf(m0v, __shfl_xor_sync(0xffffffffu, m0v, o));
            m1v = fmaxf(m1v, __shfl_xor_sync(0xffffffffu, m1v, o));
        }
        float s0 = 0.f, s1 = 0.f;
#pragma unroll
        for (int j = 0; j < 8; j++) {
            s0 += __expf(v0[j] - m0v);
            s1 += __expf(v1[j] - m1v);
        }
#pragma unroll
        for (int o = 1; o <= 2; o <<= 1) {
            s0 += __shfl_xor_sync(0xffffffffu, s0, o);
            s1 += __shfl_xor_sync(0xffffffffu, s1, o);
        }
        if ((lane & 3) == 0) {
            g_pm[(size_t)r0 * NSUB + sub]       = m0v;
            g_ps[(size_t)r0 * NSUB + sub]       = s0;
            g_pm[(size_t)(r0 + 8) * NSUB + sub] = m1v;
            g_ps[(size_t)(r0 + 8) * NSUB + sub] = s1;
        }
    }
}

// ============================================================
// Tail (512 threads): per row b — combine LSE partials, NLL,
// hierarchical argmax via t[m]=Mv[m]+sC[mp[m]], acc bins.
// Logits read as bf16; partials read coalesced from [b][sub].
// ============================================================
#define TAIL_SMEM ((NC + NM) * 4)
#define TAIL_T 512

__global__ __launch_bounds__(TAIL_T)
void k_tail(const float* __restrict__ labels,
            const float* __restrict__ fpart,
            const int*   __restrict__ fparents,
            const int*   __restrict__ mparents)
{
    extern __shared__ float sh[];
    float* sC = sh;          // NC
    float* tM = sh + NC;     // NM
    __shared__ float lseS[3];
    __shared__ float rf[16];
    __shared__ int   ri[16];

    int b = blockIdx.x, tid = threadIdx.x;
    int lane = tid & 31, wid = tid >> 5;
    const __nv_bfloat16* Cv = g_logits + OFF_C + (size_t)b * NC;
    const __nv_bfloat16* Mv = g_logits + OFF_M + (size_t)b * NM;
    const __nv_bfloat16* Fv = g_logits + OFF_F + (size_t)b * NF;
    const float* pmRow = g_pm + (size_t)b * NSUB;
    const float* psRow = g_ps + (size_t)b * NSUB;

    for (int i = tid; i < NC; i += TAIL_T) sC[i] = __bfloat162float(Cv[i]);

    // warps 0..2: combine per-sub-strip LSE partials for head wid (2-pass)
    if (wid < 3) {
        int base = (wid == 0) ? SUB_C0 : (wid == 1) ? SUB_M0 : SUB_F0;
        int cnt  = (wid == 0) ? SUB_CN : (wid == 1) ? SUB_MN : SUB_FN;
        float m = -3.402823466e38f;
        for (int i = lane; i < cnt; i += 32)
            m = fmaxf(m, pmRow[base + i]);
#pragma unroll
        for (int o = 16; o > 0; o >>= 1)
            m = fmaxf(m, __shfl_xor_sync(0xffffffffu, m, o));
        float s = 0.f;
        for (int i = lane; i < cnt; i += 32)
            s += psRow[base + i] * __expf(pmRow[base + i] - m);
#pragma unroll
        for (int o = 16; o > 0; o >>= 1)
            s += __shfl_xor_sync(0xffffffffu, s, o);
        if (lane == 0) lseS[wid] = m + logf(s);
    }
    __syncthreads();

    // t[m] = Mv[m] + sC[mparents[m]]
    for (int i = tid; i < NM; i += TAIL_T)
        tM[i] = __bfloat162float(Mv[i]) + sC[mparents[i]];
    __syncthreads();

    // hierarchical argmax over fine classes
    float best = -3.402823466e38f; int bi = 0x7fffffff;
    for (int f = tid; f < NF; f += TAIL_T) {
        float sc = __bfloat162float(Fv[f]) + tM[fparents[f]];
        if (sc > best) { best = sc; bi = f; }
    }
#pragma unroll
    for (int o = 16; o > 0; o >>= 1) {
        float ob = __shfl_xor_sync(0xffffffffu, best, o);
        int   oi = __shfl_xor_sync(0xffffffffu, bi,   o);
        if (ob > best || (ob == best && oi < bi)) { best = ob; bi = oi; }
    }
    if (lane == 0) { rf[wid] = best; ri[wid] = bi; }
    __syncthreads();

    if (tid == 0) {
        float bb = rf[0]; int pp = ri[0];
#pragma unroll
        for (int j = 1; j < 16; j++) {
            if (rf[j] > bb || (rf[j] == bb && ri[j] < pp)) { bb = rf[j]; pp = ri[j]; }
        }
        int liC = g_label_idx[b];
        int liM = g_label_idx[B + b];
        int liF = g_label_idx[2 * B + b];
        g_nll[b] = (lseS[0] - sC[liC]) + (lseS[1] - __bfloat162float(Mv[liM]))
                 + (lseS[2] - __bfloat162float(Fv[liF]));

        const float RADF = 0.017453292519943295f;
        float lat1 = labels[b * 2]      * RADF;
        float lon1 = labels[b * 2 + 1]  * RADF;
        float lat2 = fpart[pp * 2]      * RADF;
        float lon2 = fpart[pp * 2 + 1]  * RADF;
        float sdlat = sinf((lat2 - lat1) * 0.5f);
        float sdlon = sinf((lon2 - lon1) * 0.5f);
        float a = sdlat * sdlat + cosf(lat1) * cosf(lat2) * sdlon * sdlon;
        a = fminf(fmaxf(a, 0.f), 1.f);
        float d = 2.0f * 6371.0f * asinf(sqrtf(a));
        if (d <= 1.0f)    atomicAdd(&g_counts[0], 1);
        if (d <= 25.0f)   atomicAdd(&g_counts[1], 1);
        if (d <= 200.0f)  atomicAdd(&g_counts[2], 1);
        if (d <= 750.0f)  atomicAdd(&g_counts[3], 1);
        if (d <= 2500.0f) atomicAdd(&g_counts[4], 1);
    }
}

// ============================================================
// Final deterministic reduction -> out[0]=loss, out[1..5]=acc
// ============================================================
__global__ void k_finalize(float* __restrict__ out)
{
    __shared__ float red[256];
    int tid = threadIdx.x;
    float s = 0.f;
    for (int i = tid; i < B; i += 256) s += g_nll[i];
    red[tid] = s; __syncthreads();
    for (int st = 128; st > 0; st >>= 1) {
        if (tid < st) red[tid] += red[tid + st];
        __syncthreads();
    }
    if (tid == 0) out[0] = red[0] / (float)B;
    if (tid < 5)  out[1 + tid] = (float)g_counts[tid] / (float)B;
}

// ============================================================
extern "C" void kernel_launch(void* const* d_in, const int* in_sizes, int n_in,
                              void* d_out, int out_size)
{
    const float* features = (const float*)d_in[0];
    const float* labels   = (const float*)d_in[1];
    const float* cpart    = (const float*)d_in[2];
    const float* mpart    = (const float*)d_in[3];
    const float* fpart    = (const float*)d_in[4];
    const int*   mparents = (const int*)d_in[5];
    const int*   fparents = (const int*)d_in[6];
    const float* cw = (const float*)d_in[7];
    const float* cb = (const float*)d_in[8];
    const float* mw = (const float*)d_in[9];
    const float* mb = (const float*)d_in[10];
    const float* fw = (const float*)d_in[11];
    const float* fb = (const float*)d_in[12];
    float* out = (float*)d_out;

    static cudaStream_t s2 = nullptr;
    static cudaEvent_t evFork = nullptr, evJoin = nullptr;
    static int s_init_done = 0;
    if (!s_init_done) {
        cudaFuncSetAttribute(k_mmagemm, cudaFuncAttributeMaxDynamicSharedMemorySize,
                             GEMM_SMEM);
        cudaFuncSetAttribute(k_tail, cudaFuncAttributeMaxDynamicSharedMemorySize,
                             TAIL_SMEM);
        cudaStreamCreateWithFlags(&s2, cudaStreamNonBlocking);
        cudaEventCreateWithFlags(&evFork, cudaEventDisableTiming);
        cudaEventCreateWithFlags(&evJoin, cudaEventDisableTiming);
        s_init_done = 1;
    }

    // fork: init+labelidx chain on s2, overlapping convA/convW/GEMM on default
    cudaEventRecord(evFork, 0);
    cudaStreamWaitEvent(s2, evFork, 0);
    k_init<<<(NTOT + 255) / 256, 256, 0, s2>>>(labels, cpart, mpart, fpart);
    k_labelidx<<<(3 * B + 7) / 8, 256, 0, s2>>>();
    cudaEventRecord(evJoin, s2);

    k_convA<<<((B * D) / 4 + 255) / 256, 256>>>((const float4*)features);
    k_convW<<<dim3(D / 32, NPTOT / 32), dim3(32, 8)>>>(cw, mw, fw);
    k_mmagemm<<<GRID_M * GRID_N, 256, GEMM_SMEM>>>(cb, mb, fb);

    // join before tail (needs g_label_idx, g_counts)
    cudaStreamWaitEvent(0, evJoin, 0);
    k_tail<<<B, TAIL_T, TAIL_SMEM>>>(labels, fpart, fparents, mparents);
    k_finalize<<<1, 256>>>(out);
}

// round 15
// speedup vs baseline: 2.6454x; 1.0168x over previous
#include <cuda_runtime.h>
#include <cuda_bf16.h>
#include <math.h>
#include <stdint.h>

#define B  4096
#define D  1792
#define NC 3000
#define NM 7000
#define NF 13000
#define NTOT (NC + NM + NF)

// padded (tile-128) class counts for the transposed weight buffers
#define NPC 3072
#define NPM 7168
#define NPF 13056
#define SEC_C 0
#define SEC_M 3072
#define SEC_F 10240
#define NPTOT 23296
#define NSTRIP (NPTOT / 128)      // 182 n-tiles
#define NSUB   (NSTRIP * 4)       // 728 sub-strips of 32 cols

// sub-strip ranges per head (4 per 128-col tile)
#define SUB_C0 0
#define SUB_CN 96                 // 24 tiles * 4
#define SUB_M0 96
#define SUB_MN 224                // 56 tiles * 4
#define SUB_F0 320
#define SUB_FN 408                // 102 tiles * 4

#define OFF_C ((size_t)0)
#define OFF_M ((size_t)B * NC)
#define OFF_F (OFF_M + (size_t)B * NM)

// ---- device scratch (no runtime allocation allowed) ----
__device__ __nv_bfloat16 g_logits[(size_t)B * NTOT];   // ~188 MB (bf16)
__device__ __nv_bfloat16 g_A_hi[(size_t)B * D];
__device__ __nv_bfloat16 g_Wt_hi[(size_t)NPTOT * D];   // transposed [n][k]
__device__ float g_pm[(size_t)B * NSUB];               // [b][sub] row max
__device__ float g_ps[(size_t)B * NSUB];               // [b][sub] row sumexp
__device__ float g_label_xyz[B * 3];
__device__ float g_part_xyz[NTOT * 3];
__device__ int   g_label_idx[3 * B];
__device__ float g_nll[B];
__device__ int   g_counts[5];

// ============================================================
// helpers
// ============================================================
__device__ __forceinline__ uint32_t smem_to_u32(const void* p) {
    uint32_t a;
    asm("{ .reg .u64 t; cvta.to.shared.u64 t, %1; cvt.u32.u64 %0, t; }"
        : "=r"(a) : "l"(p));
    return a;
}
#define CP_ASYNC16(sm, gp) \
    asm volatile("cp.async.cg.shared.global [%0], [%1], 16;" :: "r"(sm), "l"(gp) : "memory")

__device__ __forceinline__ void ldsm_x4(uint32_t* r, uint32_t addr) {
    asm volatile("ldmatrix.sync.aligned.m8n8.x4.shared.b16 {%0,%1,%2,%3}, [%4];"
        : "=r"(r[0]), "=r"(r[1]), "=r"(r[2]), "=r"(r[3]) : "r"(addr));
}
__device__ __forceinline__ void mma_bf16(float* d, const uint32_t* a, const uint32_t* b) {
    asm volatile("mma.sync.aligned.m16n8k16.row.col.f32.bf16.bf16.f32 "
        "{%0,%1,%2,%3}, {%4,%5,%6,%7}, {%8,%9}, {%0,%1,%2,%3};"
        : "+f"(d[0]), "+f"(d[1]), "+f"(d[2]), "+f"(d[3])
        : "r"(a[0]), "r"(a[1]), "r"(a[2]), "r"(a[3]), "r"(b[0]), "r"(b[1]));
}
__device__ __forceinline__ uint32_t pack_bf16x2(float x, float y) {
    __nv_bfloat16 bx = __float2bfloat16(x), by = __float2bfloat16(y);
    return ((uint32_t)__bfloat16_as_ushort(by) << 16) | __bfloat16_as_ushort(bx);
}
// exact bf16x2 -> float unpack (bit ops only)
__device__ __forceinline__ float bf_lo(uint32_t p) { return __uint_as_float(p << 16); }
__device__ __forceinline__ float bf_hi(uint32_t p) { return __uint_as_float(p & 0xffff0000u); }

// ============================================================
// Kernel: precompute unit vectors, zero counters
// ============================================================
__global__ void k_init(const float* __restrict__ labels,
                       const float* __restrict__ cpart,
                       const float* __restrict__ mpart,
                       const float* __restrict__ fpart)
{
    int t = blockIdx.x * blockDim.x + threadIdx.x;
    const float RADF = 0.017453292519943295f;
    if (t < B) {
        float la = labels[t * 2] * RADF, lo = labels[t * 2 + 1] * RADF;
        float cl = cosf(la);
        g_label_xyz[t * 3 + 0] = cl * cosf(lo);
        g_label_xyz[t * 3 + 1] = cl * sinf(lo);
        g_label_xyz[t * 3 + 2] = sinf(la);
    }
    if (t < NTOT) {
        const float* src;
        if (t < NC)            src = cpart + (size_t)t * 2;
        else if (t < NC + NM)  src = mpart + (size_t)(t - NC) * 2;
        else                   src = fpart + (size_t)(t - NC - NM) * 2;
        float la = src[0] * RADF, lo = src[1] * RADF;
        float cl = cosf(la);
        g_part_xyz[t * 3 + 0] = cl * cosf(lo);
        g_part_xyz[t * 3 + 1] = cl * sinf(lo);
        g_part_xyz[t * 3 + 2] = sinf(la);
    }
    if (t < 5) g_counts[t] = 0;
}

// ============================================================
// Kernel: label index — one WARP per (head, b), shfl argmax reduce
// ============================================================
__global__ __launch_bounds__(256)
void k_labelidx()
{
    int gw = blockIdx.x * 8 + (threadIdx.x >> 5);
    if (gw >= 3 * B) return;
    int lane = threadIdx.x & 31;
    int head = gw >> 12;
    int b    = gw & (B - 1);
    int base, n;
    if (head == 0)      { base = 0;       n = NC; }
    else if (head == 1) { base = NC;      n = NM; }
    else                { base = NC + NM; n = NF; }
    float lx = g_label_xyz[b * 3 + 0];
    float ly = g_label_xyz[b * 3 + 1];
    float lz = g_label_xyz[b * 3 + 2];
    const float* P = g_part_xyz + (size_t)base * 3;
    float best = -2.0f; int bi = 0x7fffffff;
    for (int i = lane; i < n; i += 32) {
        float d = lx * P[i * 3] + ly * P[i * 3 + 1] + lz * P[i * 3 + 2];
        if (d > best || (d == best && i < bi)) { best = d; bi = i; }
    }
#pragma unroll
    for (int off = 16; off > 0; off >>= 1) {
        float ob = __shfl_down_sync(0xffffffffu, best, off);
        int   oi = __shfl_down_sync(0xffffffffu, bi,   off);
        if (ob > best || (ob == best && oi < bi)) { best = ob; bi = oi; }
    }
    if (lane == 0) g_label_idx[head * B + b] = bi;
}

// ============================================================
// Kernel: convert features -> bf16, float4 -> uint2
// ============================================================
__global__ void k_convA(const float4* __restrict__ A)
{
    int t = blockIdx.x * blockDim.x + threadIdx.x;
    if (t >= (B * D) / 4) return;
    float4 v = A[t];
    uint2 hp;
    hp.x = pack_bf16x2(v.x, v.y);
    hp.y = pack_bf16x2(v.z, v.w);
    ((uint2*)g_A_hi)[t] = hp;
}

// ============================================================
// Kernel: fused transpose+convert for ALL heads:
// W [D][N] -> Wt [NPTOT][D] bf16 (zero pad)
// ============================================================
__global__ void k_convW(const float* __restrict__ cw,
                        const float* __restrict__ mw,
                        const float* __restrict__ fw)
{
    __shared__ float t[32][33];
    int k0 = blockIdx.x * 32;
    int ng0 = blockIdx.y * 32;
    const float* W; int N, sec;
    if (ng0 < SEC_M)      { W = cw; N = NC; sec = SEC_C; }
    else if (ng0 < SEC_F) { W = mw; N = NM; sec = SEC_M; }
    else                  { W = fw; N = NF; sec = SEC_F; }
    int n0 = ng0 - sec;
#pragma unroll
    for (int j = 0; j < 32; j += 8) {
        int k = k0 + threadIdx.y + j;
        int n = n0 + threadIdx.x;
        t[threadIdx.y + j][threadIdx.x] = (n < N) ? W[(size_t)k * N + n] : 0.f;
    }
    __syncthreads();
#pragma unroll
    for (int j = 0; j < 32; j += 8) {
        int n = ng0 + threadIdx.y + j;
        int k = k0 + threadIdx.x;
        float v = t[threadIdx.x][threadIdx.y + j];
        g_Wt_hi[(size_t)n * D + k] = __float2bfloat16(v);
    }
}

// ============================================================
// Pure-bf16 GEMM, 2 CTAs/SM: 128x128 tile, warp tile 64x32,
// 256 threads, BK=64, 3-stage pipe, ONE barrier/chunk, SW128.
// Epilogue: bf16 logits store + per-sub-strip (32-col) LSE partials.
// ============================================================
#define BM 128
#define BN 128
#define BK 64
#define ST_A 0
#define ST_B 16384
#define STAGE_BYTES 32768
#define NSTG 3
#define GEMM_SMEM (NSTG * STAGE_BYTES)     // 96 KB -> 2 CTAs/SM (192 KB)
#define NKC (D / BK)              // 28
#define GRID_M (B / BM)           // 32
#define GRID_N NSTRIP             // 182 = 14 * 13
#define SUPER_N 13
#define A_GSTRIDE (32 * D * 2)    // +32 rows, bytes
#define SW_STRIDE (32 * 128)      // +32 rows in smem (row&7 invariant)

__global__ __launch_bounds__(256, 2)
void k_mmagemm(const float* __restrict__ cb, const float* __restrict__ mb,
               const float* __restrict__ fb)
{
    extern __shared__ __align__(1024) char smem[];
    uint32_t sb = smem_to_u32(smem);
    const int tid  = threadIdx.x;
    const int wid  = tid >> 5;
    const int lane = tid & 31;
    const int wm   = wid >> 2;     // 0..1
    const int wn   = wid & 3;      // 0..3

    // supertile rasterization: 32 m x 13 n per supertile (182 = 14*13 exact)
    const int gid = blockIdx.x;
    const int sy  = gid / (GRID_M * SUPER_N);
    const int r   = gid % (GRID_M * SUPER_N);
    const int mx  = r / SUPER_N;
    const int ny  = sy * SUPER_N + (r % SUPER_N);
    const int m0  = mx * BM;
    const int n0  = ny * BN;

    int N, sec; size_t outOff; const float* bias;
    if (n0 < SEC_M)      { N = NC; sec = SEC_C; outOff = OFF_C; bias = cb; }
    else if (n0 < SEC_F) { N = NM; sec = SEC_M; outOff = OFF_M; bias = mb; }
    else                 { N = NF; sec = SEC_F; outOff = OFF_F; bias = fb; }
    const int nloc0 = n0 - sec;

    // ---- cp.async addressing (SW128; bases only, +32-row strides) ----
    const int crow = tid >> 3, cseg = tid & 7;
    const uint32_t cSw0 = (uint32_t)(crow * 128 + ((cseg * 16) ^ ((crow & 7) << 4)));
    const uint32_t cGo0 = (uint32_t)((crow * D + cseg * 8) * 2);
    const char* Ahp = (const char*)(g_A_hi  + (size_t)m0 * D);
    const char* Bhp = (const char*)(g_Wt_hi + (size_t)n0 * D);

    // ---- ldsm per-lane addressing (bases; +16-row stride = 2048B) ----
    const int arow = wm * 64 + (lane & 7) + ((lane >> 3) & 1) * 8;
    const uint32_t aTerm0 = (uint32_t)(arow * 128);
    const uint32_t aXor   = (uint32_t)((arow & 7) << 4);
    const uint32_t aCSel  = ((lane >> 4) & 1) * 16;
    const int brow = wn * 32 + (lane & 7) + ((lane >> 4) & 1) * 8;
    const uint32_t bTerm0 = (uint32_t)(brow * 128);
    const uint32_t bXor   = (uint32_t)((brow & 7) << 4);
    const uint32_t bCSel  = ((lane >> 3) & 1) * 16;

    float acc[4][4][4];
#pragma unroll
    for (int i = 0; i < 4; i++)
#pragma unroll
        for (int j = 0; j < 4; j++)
#pragma unroll
            for (int k = 0; k < 4; k++) acc[i][j][k] = 0.f;

#define ISSUE(c) do { \
        int _c = (c); \
        uint32_t kb2 = (uint32_t)(_c * BK * 2); \
        uint32_t st = sb + (uint32_t)(_c % NSTG) * STAGE_BYTES; \
        _Pragma("unroll") \
        for (int i = 0; i < 4; i++) { \
            CP_ASYNC16(st + ST_A + cSw0 + i * SW_STRIDE, Ahp + kb2 + cGo0 + i * A_GSTRIDE); \
            CP_ASYNC16(st + ST_B + cSw0 + i * SW_STRIDE, Bhp + kb2 + cGo0 + i * A_GSTRIDE); \
        } \
        asm volatile("cp.async.commit_group;" ::: "memory"); \
    } while (0)

    ISSUE(0);
    ISSUE(1);

    for (int c = 0; c < NKC; c++) {
        if (c + 1 < NKC) asm volatile("cp.async.wait_group 1;" ::: "memory");
        else             asm volatile("cp.async.wait_group 0;" ::: "memory");
        __syncthreads();   // chunk c visible; all warps done with stage (c-1)%3
        if (c + 2 < NKC) ISSUE(c + 2);   // stage (c+2)%3 == (c-1)%3: safe

        uint32_t st = sb + (uint32_t)(c % NSTG) * STAGE_BYTES;
#pragma unroll
        for (int ks = 0; ks < 4; ks++) {
            const uint32_t kb = (uint32_t)(ks * 32);
            uint32_t a[4][4], bh[2][4];
            const uint32_t aOff = (kb + aCSel) ^ aXor;
            const uint32_t bOff = (kb + bCSel) ^ bXor;
#pragma unroll
            for (int mt = 0; mt < 4; mt++)
                ldsm_x4(a[mt], st + ST_A + aTerm0 + mt * 2048 + aOff);
#pragma unroll
            for (int np = 0; np < 2; np++)
                ldsm_x4(bh[np], st + ST_B + bTerm0 + np * 2048 + bOff);
#pragma unroll
            for (int mt = 0; mt < 4; mt++)
#pragma unroll
                for (int nt = 0; nt < 4; nt++)
                    mma_bf16(acc[mt][nt], a[mt], &bh[nt >> 1][(nt & 1) * 2]);
        }
    }
#undef ISSUE

    // ---- epilogue: bias + store bf16 logits + per-sub-strip LSE partials ----
    __nv_bfloat16* out = g_logits + outOff;
    const int sub = ny * 4 + wn;
    const int rbase = m0 + wm * 64 + (lane >> 2);
    const int cb0 = nloc0 + wn * 32 + (lane & 3) * 2;
#pragma unroll
    for (int mt = 0; mt < 4; mt++) {
        int r0 = rbase + mt * 16;
        float v0[8], v1[8];
#pragma unroll
        for (int nt = 0; nt < 4; nt++) {
            int col = cb0 + nt * 8;
            bool ok = (col < N);
            float bx = 0.f, by = 0.f;
            if (ok) { bx = bias[col]; by = bias[col + 1]; }
            float a0 = acc[mt][nt][0] + bx;
            float a1 = acc[mt][nt][1] + by;
            float a2 = acc[mt][nt][2] + bx;
            float a3 = acc[mt][nt][3] + by;
            if (ok) {
                *(uint32_t*)&out[(size_t)r0 * N + col]       = pack_bf16x2(a0, a1);
                *(uint32_t*)&out[(size_t)(r0 + 8) * N + col] = pack_bf16x2(a2, a3);
            }
            v0[nt * 2 + 0] = ok ? a0 : -1e30f;
            v0[nt * 2 + 1] = ok ? a1 : -1e30f;
            v1[nt * 2 + 0] = ok ? a2 : -1e30f;
            v1[nt * 2 + 1] = ok ? a3 : -1e30f;
        }
        float m0v = v0[0], m1v = v1[0];
#pragma unroll
        for (int j = 1; j < 8; j++) { m0v = fmaxf(m0v, v0[j]); m1v = fmaxf(m1v, v1[j]); }
#pragma unroll
        for (int o = 1; o <= 2; o <<= 1) {
            m0v = fmaxf(m0v, __shfl_xor_sync(0xffffffffu, m0v, o));
            m1v = fmaxf(m1v, __shfl_xor_sync(0xffffffffu, m1v, o));
        }
        float s0 = 0.f, s1 = 0.f;
#pragma unroll
        for (int j = 0; j < 8; j++) {
            s0 += __expf(v0[j] - m0v);
            s1 += __expf(v1[j] - m1v);
        }
#pragma unroll
        for (int o = 1; o <= 2; o <<= 1) {
            s0 += __shfl_xor_sync(0xffffffffu, s0, o);
            s1 += __shfl_xor_sync(0xffffffffu, s1, o);
        }
        if ((lane & 3) == 0) {
            g_pm[(size_t)r0 * NSUB + sub]       = m0v;
            g_ps[(size_t)r0 * NSUB + sub]       = s0;
            g_pm[(size_t)(r0 + 8) * NSUB + sub] = m1v;
            g_ps[(size_t)(r0 + 8) * NSUB + sub] = s1;
        }
    }
}

// ============================================================
// Tail (512 threads): per row b — combine LSE partials, NLL,
// hierarchical argmax. Vectorized bf16x2 logit loads + int2 gathers.
// ============================================================
#define TAIL_SMEM ((NC + NM) * 4)
#define TAIL_T 512

__global__ __launch_bounds__(TAIL_T)
void k_tail(const float* __restrict__ labels,
            const float* __restrict__ fpart,
            const int*   __restrict__ fparents,
            const int*   __restrict__ mparents)
{
    extern __shared__ float sh[];
    float* sC = sh;          // NC
    float* tM = sh + NC;     // NM
    __shared__ float lseS[3];
    __shared__ float rf[16];
    __shared__ int   ri[16];

    int b = blockIdx.x, tid = threadIdx.x;
    int lane = tid & 31, wid = tid >> 5;
    const __nv_bfloat16* Cv = g_logits + OFF_C + (size_t)b * NC;
    const __nv_bfloat16* Mv = g_logits + OFF_M + (size_t)b * NM;
    const __nv_bfloat16* Fv = g_logits + OFF_F + (size_t)b * NF;
    const uint32_t* Cv2 = (const uint32_t*)Cv;   // rows are 4B-aligned (NC,NM,NF even)
    const uint32_t* Mv2 = (const uint32_t*)Mv;
    const uint32_t* Fv2 = (const uint32_t*)Fv;
    const float* pmRow = g_pm + (size_t)b * NSUB;
    const float* psRow = g_ps + (size_t)b * NSUB;

    for (int i = tid; i < NC / 2; i += TAIL_T) {
        uint32_t p = Cv2[i];
        sC[2 * i]     = bf_lo(p);
        sC[2 * i + 1] = bf_hi(p);
    }

    // warps 0..2: combine per-sub-strip LSE partials for head wid (2-pass)
    if (wid < 3) {
        int base = (wid == 0) ? SUB_C0 : (wid == 1) ? SUB_M0 : SUB_F0;
        int cnt  = (wid == 0) ? SUB_CN : (wid == 1) ? SUB_MN : SUB_FN;
        float m = -3.402823466e38f;
        for (int i = lane; i < cnt; i += 32)
            m = fmaxf(m, pmRow[base + i]);
#pragma unroll
        for (int o = 16; o > 0; o >>= 1)
            m = fmaxf(m, __shfl_xor_sync(0xffffffffu, m, o));
        float s = 0.f;
        for (int i = lane; i < cnt; i += 32)
            s += psRow[base + i] * __expf(pmRow[base + i] - m);
#pragma unroll
        for (int o = 16; o > 0; o >>= 1)
            s += __shfl_xor_sync(0xffffffffu, s, o);
        if (lane == 0) lseS[wid] = m + logf(s);
    }
    __syncthreads();

    // t[m] = Mv[m] + sC[mparents[m]]  (vectorized: 2 per iter)
    const int2* mp2 = (const int2*)mparents;
    for (int i = tid; i < NM / 2; i += TAIL_T) {
        uint32_t p = Mv2[i];
        int2 mp = mp2[i];
        tM[2 * i]     = bf_lo(p) + sC[mp.x];
        tM[2 * i + 1] = bf_hi(p) + sC[mp.y];
    }
    __syncthreads();

    // hierarchical argmax over fine classes (vectorized: 2 per iter)
    const int2* fp2 = (const int2*)fparents;
    float best = -3.402823466e38f; int bi = 0x7fffffff;
    for (int i = tid; i < NF / 2; i += TAIL_T) {
        uint32_t p = Fv2[i];
        int2 fp = fp2[i];
        float s0 = bf_lo(p) + tM[fp.x];
        float s1 = bf_hi(p) + tM[fp.y];
        if (s0 > best) { best = s0; bi = 2 * i; }
        if (s1 > best) { best = s1; bi = 2 * i + 1; }
    }
#pragma unroll
    for (int o = 16; o > 0; o >>= 1) {
        float ob = __shfl_xor_sync(0xffffffffu, best, o);
        int   oi = __shfl_xor_sync(0xffffffffu, bi,   o);
        if (ob > best || (ob == best && oi < bi)) { best = ob; bi = oi; }
    }
    if (lane == 0) { rf[wid] = best; ri[wid] = bi; }
    __syncthreads();

    if (tid == 0) {
        float bb = rf[0]; int pp = ri[0];
#pragma unroll
        for (int j = 1; j < 16; j++) {
            if (rf[j] > bb || (rf[j] == bb && ri[j] < pp)) { bb = rf[j]; pp = ri[j]; }
        }
        int liC = g_label_idx[b];
        int liM = g_label_idx[B + b];
        int liF = g_label_idx[2 * B + b];
        g_nll[b] = (lseS[0] - sC[liC]) + (lseS[1] - __bfloat162float(Mv[liM]))
                 + (lseS[2] - __bfloat162float(Fv[liF]));

        const float RADF = 0.017453292519943295f;
        float lat1 = labels[b * 2]      * RADF;
        float lon1 = labels[b * 2 + 1]  * RADF;
        float lat2 = fpart[pp * 2]      * RADF;
        float lon2 = fpart[pp * 2 + 1]  * RADF;
        float sdlat = sinf((lat2 - lat1) * 0.5f);
        float sdlon = sinf((lon2 - lon1) * 0.5f);
        float a = sdlat * sdlat + cosf(lat1) * cosf(lat2) * sdlon * sdlon;
        a = fminf(fmaxf(a, 0.f), 1.f);
        float d = 2.0f * 6371.0f * asinf(sqrtf(a));
        if (d <= 1.0f)    atomicAdd(&g_counts[0], 1);
        if (d <= 25.0f)   atomicAdd(&g_counts[1], 1);
        if (d <= 200.0f)  atomicAdd(&g_counts[2], 1);
        if (d <= 750.0f)  atomicAdd(&g_counts[3], 1);
        if (d <= 2500.0f) atomicAdd(&g_counts[4], 1);
    }
}

// ============================================================
// Final deterministic reduction -> out[0]=loss, out[1..5]=acc
// ============================================================
__global__ void k_finalize(float* __restrict__ out)
{
    __shared__ float red[256];
    int tid = threadIdx.x;
    float s = 0.f;
    for (int i = tid; i < B; i += 256) s += g_nll[i];
    red[tid] = s; __syncthreads();
    for (int st = 128; st > 0; st >>= 1) {
        if (tid < st) red[tid] += red[tid + st];
        __syncthreads();
    }
    if (tid == 0) out[0] = red[0] / (float)B;
    if (tid < 5)  out[1 + tid] = (float)g_counts[tid] / (float)B;
}

// ============================================================
extern "C" void kernel_launch(void* const* d_in, const int* in_sizes, int n_in,
                              void* d_out, int out_size)
{
    const float* features = (const float*)d_in[0];
    const float* labels   = (const float*)d_in[1];
    const float* cpart    = (const float*)d_in[2];
    const float* mpart    = (const float*)d_in[3];
    const float* fpart    = (const float*)d_in[4];
    const int*   mparents = (const int*)d_in[5];
    const int*   fparents = (const int*)d_in[6];
    const float* cw = (const float*)d_in[7];
    const float* cb = (const float*)d_in[8];
    const float* mw = (const float*)d_in[9];
    const float* mb = (const float*)d_in[10];
    const float* fw = (const float*)d_in[11];
    const float* fb = (const float*)d_in[12];
    float* out = (float*)d_out;

    static cudaStream_t s2 = nullptr;
    static cudaEvent_t evFork = nullptr, evA = nullptr, evJoin = nullptr;
    static int s_init_done = 0;
    if (!s_init_done) {
        cudaFuncSetAttribute(k_mmagemm, cudaFuncAttributeMaxDynamicSharedMemorySize,
                             GEMM_SMEM);
        cudaFuncSetAttribute(k_tail, cudaFuncAttributeMaxDynamicSharedMemorySize,
                             TAIL_SMEM);
        cudaStreamCreateWithFlags(&s2, cudaStreamNonBlocking);
        cudaEventCreateWithFlags(&evFork, cudaEventDisableTiming);
        cudaEventCreateWithFlags(&evA, cudaEventDisableTiming);
        cudaEventCreateWithFlags(&evJoin, cudaEventDisableTiming);
        s_init_done = 1;
    }

    // fork: convA + init + labelidx on s2, overlapping convW on default
    cudaEventRecord(evFork, 0);
    cudaStreamWaitEvent(s2, evFork, 0);
    k_convA<<<((B * D) / 4 + 255) / 256, 256, 0, s2>>>((const float4*)features);
    cudaEventRecord(evA, s2);
    k_init<<<(NTOT + 255) / 256, 256, 0, s2>>>(labels, cpart, mpart, fpart);
    k_labelidx<<<(3 * B + 7) / 8, 256, 0, s2>>>();
    cudaEventRecord(evJoin, s2);

    k_convW<<<dim3(D / 32, NPTOT / 32), dim3(32, 8)>>>(cw, mw, fw);
    cudaStreamWaitEvent(0, evA, 0);      // GEMM needs g_A_hi
    k_mmagemm<<<GRID_M * GRID_N, 256, GEMM_SMEM>>>(cb, mb, fb);

    // join before tail (needs g_label_idx, g_counts)
    cudaStreamWaitEvent(0, evJoin, 0);
    k_tail<<<B, TAIL_T, TAIL_SMEM>>>(labels, fpart, fparents, mparents);
    k_finalize<<<1, 256>>>(out);
}

// round 16
// speedup vs baseline: 2.7249x; 1.0300x over previous
#include <cuda_runtime.h>
#include <cuda_bf16.h>
#include <math.h>
#include <stdint.h>

#define B  4096
#define D  1792
#define NC 3000
#define NM 7000
#define NF 13000
#define NTOT (NC + NM + NF)

// padded (tile-128) class counts for the transposed weight buffers
#define NPC 3072
#define NPM 7168
#define NPF 13056
#define SEC_C 0
#define SEC_M 3072
#define SEC_F 10240
#define NPTOT 23296
#define NSTRIP (NPTOT / 128)      // 182 n-tiles
#define NSUB   (NSTRIP * 4)       // 728 sub-strips of 32 cols

// sub-strip ranges per head (4 per 128-col tile)
#define SUB_C0 0
#define SUB_CN 96                 // 24 tiles * 4
#define SUB_M0 96
#define SUB_MN 224                // 56 tiles * 4
#define SUB_F0 320
#define SUB_FN 408                // 102 tiles * 4

#define OFF_C ((size_t)0)
#define OFF_M ((size_t)B * NC)
#define OFF_F (OFF_M + (size_t)B * NM)

// ---- device scratch (no runtime allocation allowed) ----
__device__ __nv_bfloat16 g_logits[(size_t)B * NTOT];   // ~188 MB (bf16)
__device__ __nv_bfloat16 g_A_hi[(size_t)B * D];
__device__ __nv_bfloat16 g_Wt_hi[(size_t)NPTOT * D];   // transposed [n][k]
__device__ float g_pm[(size_t)B * NSUB];               // [b][sub] row max
__device__ float g_ps[(size_t)B * NSUB];               // [b][sub] row sumexp
__device__ float g_label_xyz[B * 3];
__device__ float g_part_xyz[NTOT * 3];
__device__ int   g_label_idx[3 * B];
__device__ float g_nll[B];
__device__ int   g_counts[5];

// ============================================================
// helpers
// ============================================================
__device__ __forceinline__ uint32_t smem_to_u32(const void* p) {
    uint32_t a;
    asm("{ .reg .u64 t; cvta.to.shared.u64 t, %1; cvt.u32.u64 %0, t; }"
        : "=r"(a) : "l"(p));
    return a;
}
#define CP_ASYNC16(sm, gp) \
    asm volatile("cp.async.cg.shared.global [%0], [%1], 16;" :: "r"(sm), "l"(gp) : "memory")

__device__ __forceinline__ void ldsm_x4(uint32_t* r, uint32_t addr) {
    asm volatile("ldmatrix.sync.aligned.m8n8.x4.shared.b16 {%0,%1,%2,%3}, [%4];"
        : "=r"(r[0]), "=r"(r[1]), "=r"(r[2]), "=r"(r[3]) : "r"(addr));
}
__device__ __forceinline__ void mma_bf16(float* d, const uint32_t* a, const uint32_t* b) {
    asm volatile("mma.sync.aligned.m16n8k16.row.col.f32.bf16.bf16.f32 "
        "{%0,%1,%2,%3}, {%4,%5,%6,%7}, {%8,%9}, {%0,%1,%2,%3};"
        : "+f"(d[0]), "+f"(d[1]), "+f"(d[2]), "+f"(d[3])
        : "r"(a[0]), "r"(a[1]), "r"(a[2]), "r"(a[3]), "r"(b[0]), "r"(b[1]));
}
__device__ __forceinline__ uint32_t pack_bf16x2(float x, float y) {
    __nv_bfloat16 bx = __float2bfloat16(x), by = __float2bfloat16(y);
    return ((uint32_t)__bfloat16_as_ushort(by) << 16) | __bfloat16_as_ushort(bx);
}
// exact bf16x2 -> float unpack (bit ops only)
__device__ __forceinline__ float bf_lo(uint32_t p) { return __uint_as_float(p << 16); }
__device__ __forceinline__ float bf_hi(uint32_t p) { return __uint_as_float(p & 0xffff0000u); }

// ============================================================
// Kernel: precompute unit vectors, zero counters
// ============================================================
__global__ void k_init(const float* __restrict__ labels,
                       const float* __restrict__ cpart,
                       const float* __restrict__ mpart,
                       const float* __restrict__ fpart)
{
    int t = blockIdx.x * blockDim.x + threadIdx.x;
    const float RADF = 0.017453292519943295f;
    if (t < B) {
        float la = labels[t * 2] * RADF, lo = labels[t * 2 + 1] * RADF;
        float cl = cosf(la);
        g_label_xyz[t * 3 + 0] = cl * cosf(lo);
        g_label_xyz[t * 3 + 1] = cl * sinf(lo);
        g_label_xyz[t * 3 + 2] = sinf(la);
    }
    if (t < NTOT) {
        const float* src;
        if (t < NC)            src = cpart + (size_t)t * 2;
        else if (t < NC + NM)  src = mpart + (size_t)(t - NC) * 2;
        else                   src = fpart + (size_t)(t - NC - NM) * 2;
        float la = src[0] * RADF, lo = src[1] * RADF;
        float cl = cosf(la);
        g_part_xyz[t * 3 + 0] = cl * cosf(lo);
        g_part_xyz[t * 3 + 1] = cl * sinf(lo);
        g_part_xyz[t * 3 + 2] = sinf(la);
    }
    if (t < 5) g_counts[t] = 0;
}

// ============================================================
// Kernel: label index — one WARP per (head, b), shfl argmax reduce
// ============================================================
__global__ __launch_bounds__(256)
void k_labelidx()
{
    int gw = blockIdx.x * 8 + (threadIdx.x >> 5);
    if (gw >= 3 * B) return;
    int lane = threadIdx.x & 31;
    int head = gw >> 12;
    int b    = gw & (B - 1);
    int base, n;
    if (head == 0)      { base = 0;       n = NC; }
    else if (head == 1) { base = NC;      n = NM; }
    else                { base = NC + NM; n = NF; }
    float lx = g_label_xyz[b * 3 + 0];
    float ly = g_label_xyz[b * 3 + 1];
    float lz = g_label_xyz[b * 3 + 2];
    const float* P = g_part_xyz + (size_t)base * 3;
    float best = -2.0f; int bi = 0x7fffffff;
    for (int i = lane; i < n; i += 32) {
        float d = lx * P[i * 3] + ly * P[i * 3 + 1] + lz * P[i * 3 + 2];
        if (d > best || (d == best && i < bi)) { best = d; bi = i; }
    }
#pragma unroll
    for (int off = 16; off > 0; off >>= 1) {
        float ob = __shfl_down_sync(0xffffffffu, best, off);
        int   oi = __shfl_down_sync(0xffffffffu, bi,   off);
        if (ob > best || (ob == best && oi < bi)) { best = ob; bi = oi; }
    }
    if (lane == 0) g_label_idx[head * B + b] = bi;
}

// ============================================================
// Kernel: convert features -> bf16, float4 -> uint2
// ============================================================
__global__ void k_convA(const float4* __restrict__ A)
{
    int t = blockIdx.x * blockDim.x + threadIdx.x;
    if (t >= (B * D) / 4) return;
    float4 v = A[t];
    uint2 hp;
    hp.x = pack_bf16x2(v.x, v.y);
    hp.y = pack_bf16x2(v.z, v.w);
    ((uint2*)g_A_hi)[t] = hp;
}

// ============================================================
// Kernel: fused transpose+convert for ALL heads, vectorized:
// W [D][N] -> Wt [NPTOT][D] bf16 (zero pad). 64x64 tiles,
// float4 loads, uint2 (4xbf16) stores. Section offsets are
// multiples of 64; N is a multiple of 4 for every head.
// ============================================================
__global__ __launch_bounds__(256)
void k_convW(const float* __restrict__ cw,
             const float* __restrict__ mw,
             const float* __restrict__ fw)
{
    __shared__ float t[64][65];
    int k0  = blockIdx.x * 64;
    int ng0 = blockIdx.y * 64;
    const float* W; int N, sec;
    if (ng0 < SEC_M)      { W = cw; N = NC; sec = SEC_C; }
    else if (ng0 < SEC_F) { W = mw; N = NM; sec = SEC_M; }
    else                  { W = fw; N = NF; sec = SEC_F; }
    int n0 = ng0 - sec;
    const int tx = threadIdx.x & 15;   // 4-col group
    const int ty = threadIdx.x >> 4;   // 0..15
#pragma unroll
    for (int j = 0; j < 4; j++) {
        int k = k0 + ty + j * 16;
        int n = n0 + tx * 4;
        float4 v = make_float4(0.f, 0.f, 0.f, 0.f);
        if (n < N) v = *(const float4*)&W[(size_t)k * N + n];
        t[ty + j * 16][tx * 4 + 0] = v.x;
        t[ty + j * 16][tx * 4 + 1] = v.y;
        t[ty + j * 16][tx * 4 + 2] = v.z;
        t[ty + j * 16][tx * 4 + 3] = v.w;
    }
    __syncthreads();
#pragma unroll
    for (int j = 0; j < 4; j++) {
        int nl = ty + j * 16;
        int n  = ng0 + nl;
        uint2 o;
        o.x = pack_bf16x2(t[tx * 4 + 0][nl], t[tx * 4 + 1][nl]);
        o.y = pack_bf16x2(t[tx * 4 + 2][nl], t[tx * 4 + 3][nl]);
        *(uint2*)&g_Wt_hi[(size_t)n * D + k0 + tx * 4] = o;
    }
}

// ============================================================
// Pure-bf16 GEMM, 2 CTAs/SM: 128x128 tile, warp tile 64x32,
// 256 threads, BK=64, 3-stage pipe, ONE barrier/chunk, SW128.
// Epilogue: bf16 logits store + per-sub-strip (32-col) LSE partials.
// ============================================================
#define BM 128
#define BN 128
#define BK 64
#define ST_A 0
#define ST_B 16384
#define STAGE_BYTES 32768
#define NSTG 3
#define GEMM_SMEM (NSTG * STAGE_BYTES)     // 96 KB -> 2 CTAs/SM (192 KB)
#define NKC (D / BK)              // 28
#define GRID_M (B / BM)           // 32
#define GRID_N NSTRIP             // 182 = 14 * 13
#define SUPER_N 13
#define A_GSTRIDE (32 * D * 2)    // +32 rows, bytes
#define SW_STRIDE (32 * 128)      // +32 rows in smem (row&7 invariant)

__global__ __launch_bounds__(256, 2)
void k_mmagemm(const float* __restrict__ cb, const float* __restrict__ mb,
               const float* __restrict__ fb)
{
    extern __shared__ __align__(1024) char smem[];
    uint32_t sb = smem_to_u32(smem);
    const int tid  = threadIdx.x;
    const int wid  = tid >> 5;
    const int lane = tid & 31;
    const int wm   = wid >> 2;     // 0..1
    const int wn   = wid & 3;      // 0..3

    // supertile rasterization: 32 m x 13 n per supertile (182 = 14*13 exact)
    const int gid = blockIdx.x;
    const int sy  = gid / (GRID_M * SUPER_N);
    const int r   = gid % (GRID_M * SUPER_N);
    const int mx  = r / SUPER_N;
    const int ny  = sy * SUPER_N + (r % SUPER_N);
    const int m0  = mx * BM;
    const int n0  = ny * BN;

    int N, sec; size_t outOff; const float* bias;
    if (n0 < SEC_M)      { N = NC; sec = SEC_C; outOff = OFF_C; bias = cb; }
    else if (n0 < SEC_F) { N = NM; sec = SEC_M; outOff = OFF_M; bias = mb; }
    else                 { N = NF; sec = SEC_F; outOff = OFF_F; bias = fb; }
    const int nloc0 = n0 - sec;

    // ---- cp.async addressing (SW128; bases only, +32-row strides) ----
    const int crow = tid >> 3, cseg = tid & 7;
    const uint32_t cSw0 = (uint32_t)(crow * 128 + ((cseg * 16) ^ ((crow & 7) << 4)));
    const uint32_t cGo0 = (uint32_t)((crow * D + cseg * 8) * 2);
    const char* Ahp = (const char*)(g_A_hi  + (size_t)m0 * D);
    const char* Bhp = (const char*)(g_Wt_hi + (size_t)n0 * D);

    // ---- ldsm per-lane addressing (bases; +16-row stride = 2048B) ----
    const int arow = wm * 64 + (lane & 7) + ((lane >> 3) & 1) * 8;
    const uint32_t aTerm0 = (uint32_t)(arow * 128);
    const uint32_t aXor   = (uint32_t)((arow & 7) << 4);
    const uint32_t aCSel  = ((lane >> 4) & 1) * 16;
    const int brow = wn * 32 + (lane & 7) + ((lane >> 4) & 1) * 8;
    const uint32_t bTerm0 = (uint32_t)(brow * 128);
    const uint32_t bXor   = (uint32_t)((brow & 7) << 4);
    const uint32_t bCSel  = ((lane >> 3) & 1) * 16;

    float acc[4][4][4];
#pragma unroll
    for (int i = 0; i < 4; i++)
#pragma unroll
        for (int j = 0; j < 4; j++)
#pragma unroll
            for (int k = 0; k < 4; k++) acc[i][j][k] = 0.f;

#define ISSUE(c) do { \
        int _c = (c); \
        uint32_t kb2 = (uint32_t)(_c * BK * 2); \
        uint32_t st = sb + (uint32_t)(_c % NSTG) * STAGE_BYTES; \
        _Pragma("unroll") \
        for (int i = 0; i < 4; i++) { \
            CP_ASYNC16(st + ST_A + cSw0 + i * SW_STRIDE, Ahp + kb2 + cGo0 + i * A_GSTRIDE); \
            CP_ASYNC16(st + ST_B + cSw0 + i * SW_STRIDE, Bhp + kb2 + cGo0 + i * A_GSTRIDE); \
        } \
        asm volatile("cp.async.commit_group;" ::: "memory"); \
    } while (0)

    ISSUE(0);
    ISSUE(1);

    for (int c = 0; c < NKC; c++) {
        if (c + 1 < NKC) asm volatile("cp.async.wait_group 1;" ::: "memory");
        else             asm volatile("cp.async.wait_group 0;" ::: "memory");
        __syncthreads();   // chunk c visible; all warps done with stage (c-1)%3
        if (c + 2 < NKC) ISSUE(c + 2);   // stage (c+2)%3 == (c-1)%3: safe

        uint32_t st = sb + (uint32_t)(c % NSTG) * STAGE_BYTES;
#pragma unroll
        for (int ks = 0; ks < 4; ks++) {
            const uint32_t kb = (uint32_t)(ks * 32);
            uint32_t a[4][4], bh[2][4];
            const uint32_t aOff = (kb + aCSel) ^ aXor;
            const uint32_t bOff = (kb + bCSel) ^ bXor;
#pragma unroll
            for (int mt = 0; mt < 4; mt++)
                ldsm_x4(a[mt], st + ST_A + aTerm0 + mt * 2048 + aOff);
#pragma unroll
            for (int np = 0; np < 2; np++)
                ldsm_x4(bh[np], st + ST_B + bTerm0 + np * 2048 + bOff);
#pragma unroll
            for (int mt = 0; mt < 4; mt++)
#pragma unroll
                for (int nt = 0; nt < 4; nt++)
                    mma_bf16(acc[mt][nt], a[mt], &bh[nt >> 1][(nt & 1) * 2]);
        }
    }
#undef ISSUE

    // ---- epilogue: bias + store bf16 logits + per-sub-strip LSE partials ----
    __nv_bfloat16* out = g_logits + outOff;
    const int sub = ny * 4 + wn;
    const int rbase = m0 + wm * 64 + (lane >> 2);
    const int cb0 = nloc0 + wn * 32 + (lane & 3) * 2;
#pragma unroll
    for (int mt = 0; mt < 4; mt++) {
        int r0 = rbase + mt * 16;
        float v0[8], v1[8];
#pragma unroll
        for (int nt = 0; nt < 4; nt++) {
            int col = cb0 + nt * 8;
            bool ok = (col < N);
            float bx = 0.f, by = 0.f;
            if (ok) { bx = bias[col]; by = bias[col + 1]; }
            float a0 = acc[mt][nt][0] + bx;
            float a1 = acc[mt][nt][1] + by;
            float a2 = acc[mt][nt][2] + bx;
            float a3 = acc[mt][nt][3] + by;
            if (ok) {
                *(uint32_t*)&out[(size_t)r0 * N + col]       = pack_bf16x2(a0, a1);
                *(uint32_t*)&out[(size_t)(r0 + 8) * N + col] = pack_bf16x2(a2, a3);
            }
            v0[nt * 2 + 0] = ok ? a0 : -1e30f;
            v0[nt * 2 + 1] = ok ? a1 : -1e30f;
            v1[nt * 2 + 0] = ok ? a2 : -1e30f;
            v1[nt * 2 + 1] = ok ? a3 : -1e30f;
        }
        float m0v = v0[0], m1v = v1[0];
#pragma unroll
        for (int j = 1; j < 8; j++) { m0v = fmaxf(m0v, v0[j]); m1v = fmaxf(m1v, v1[j]); }
#pragma unroll
        for (int o = 1; o <= 2; o <<= 1) {
            m0v = fmaxf(m0v, __shfl_xor_sync(0xffffffffu, m0v, o));
            m1v = fmaxf(m1v, __shfl_xor_sync(0xffffffffu, m1v, o));
        }
        float s0 = 0.f, s1 = 0.f;
#pragma unroll
        for (int j = 0; j < 8; j++) {
            s0 += __expf(v0[j] - m0v);
            s1 += __expf(v1[j] - m1v);
        }
#pragma unroll
        for (int o = 1; o <= 2; o <<= 1) {
            s0 += __shfl_xor_sync(0xffffffffu, s0, o);
            s1 += __shfl_xor_sync(0xffffffffu, s1, o);
        }
        if ((lane & 3) == 0) {
            g_pm[(size_t)r0 * NSUB + sub]       = m0v;
            g_ps[(size_t)r0 * NSUB + sub]       = s0;
            g_pm[(size_t)(r0 + 8) * NSUB + sub] = m1v;
            g_ps[(size_t)(r0 + 8) * NSUB + sub] = s1;
        }
    }
}

// ============================================================
// Tail (512 threads): per row b — combine LSE partials, NLL,
// hierarchical argmax. 4-wide bf16 logit loads + int4 gathers.
// ============================================================
#define TAIL_SMEM ((NC + NM) * 4)
#define TAIL_T 512

__global__ __launch_bounds__(TAIL_T)
void k_tail(const float* __restrict__ labels,
            const float* __restrict__ fpart,
            const int*   __restrict__ fparents,
            const int*   __restrict__ mparents)
{
    extern __shared__ float sh[];
    float* sC = sh;          // NC
    float* tM = sh + NC;     // NM
    __shared__ float lseS[3];
    __shared__ float rf[16];
    __shared__ int   ri[16];

    int b = blockIdx.x, tid = threadIdx.x;
    int lane = tid & 31, wid = tid >> 5;
    const __nv_bfloat16* Cv = g_logits + OFF_C + (size_t)b * NC;
    const __nv_bfloat16* Mv = g_logits + OFF_M + (size_t)b * NM;
    const __nv_bfloat16* Fv = g_logits + OFF_F + (size_t)b * NF;
    // all row bases 4-element (8B) aligned: NC,NM,NF ≡ 0 mod 4
    const uint2* Cv4 = (const uint2*)Cv;
    const uint2* Mv4 = (const uint2*)Mv;
    const uint2* Fv4 = (const uint2*)Fv;
    const float* pmRow = g_pm + (size_t)b * NSUB;
    const float* psRow = g_ps + (size_t)b * NSUB;

    for (int i = tid; i < NC / 4; i += TAIL_T) {
        uint2 p = Cv4[i];
        sC[4 * i + 0] = bf_lo(p.x);
        sC[4 * i + 1] = bf_hi(p.x);
        sC[4 * i + 2] = bf_lo(p.y);
        sC[4 * i + 3] = bf_hi(p.y);
    }

    // warps 0..2: combine per-sub-strip LSE partials for head wid (2-pass)
    if (wid < 3) {
        int base = (wid == 0) ? SUB_C0 : (wid == 1) ? SUB_M0 : SUB_F0;
        int cnt  = (wid == 0) ? SUB_CN : (wid == 1) ? SUB_MN : SUB_FN;
        float m = -3.402823466e38f;
        for (int i = lane; i < cnt; i += 32)
            m = fmaxf(m, pmRow[base + i]);
#pragma unroll
        for (int o = 16; o > 0; o >>= 1)
            m = fmaxf(m, __shfl_xor_sync(0xffffffffu, m, o));
        float s = 0.f;
        for (int i = lane; i < cnt; i += 32)
            s += psRow[base + i] * __expf(pmRow[base + i] - m);
#pragma unroll
        for (int o = 16; o > 0; o >>= 1)
            s += __shfl_xor_sync(0xffffffffu, s, o);
        if (lane == 0) lseS[wid] = m + logf(s);
    }
    __syncthreads();

    // t[m] = Mv[m] + sC[mparents[m]]  (4 per iter)
    const int4* mp4 = (const int4*)mparents;
    for (int i = tid; i < NM / 4; i += TAIL_T) {
        uint2 p = Mv4[i];
        int4 mp = mp4[i];
        tM[4 * i + 0] = bf_lo(p.x) + sC[mp.x];
        tM[4 * i + 1] = bf_hi(p.x) + sC[mp.y];
        tM[4 * i + 2] = bf_lo(p.y) + sC[mp.z];
        tM[4 * i + 3] = bf_hi(p.y) + sC[mp.w];
    }
    __syncthreads();

    // hierarchical argmax over fine classes (4 per iter)
    const int4* fp4 = (const int4*)fparents;
    float best = -3.402823466e38f; int bi = 0x7fffffff;
    for (int i = tid; i < NF / 4; i += TAIL_T) {
        uint2 p = Fv4[i];
        int4 fp = fp4[i];
        float s0 = bf_lo(p.x) + tM[fp.x];
        float s1 = bf_hi(p.x) + tM[fp.y];
        float s2 = bf_lo(p.y) + tM[fp.z];
        float s3 = bf_hi(p.y) + tM[fp.w];
        if (s0 > best) { best = s0; bi = 4 * i; }
        if (s1 > best) { best = s1; bi = 4 * i + 1; }
        if (s2 > best) { best = s2; bi = 4 * i + 2; }
        if (s3 > best) { best = s3; bi = 4 * i + 3; }
    }
#pragma unroll
    for (int o = 16; o > 0; o >>= 1) {
        float ob = __shfl_xor_sync(0xffffffffu, best, o);
        int   oi = __shfl_xor_sync(0xffffffffu, bi,   o);
        if (ob > best || (ob == best && oi < bi)) { best = ob; bi = oi; }
    }
    if (lane == 0) { rf[wid] = best; ri[wid] = bi; }
    __syncthreads();

    if (tid == 0) {
        float bb = rf[0]; int pp = ri[0];
#pragma unroll
        for (int j = 1; j < 16; j++) {
            if (rf[j] > bb || (rf[j] == bb && ri[j] < pp)) { bb = rf[j]; pp = ri[j]; }
        }
        int liC = g_label_idx[b];
        int liM = g_label_idx[B + b];
        int liF = g_label_idx[2 * B + b];
        g_nll[b] = (lseS[0] - sC[liC]) + (lseS[1] - __bfloat162float(Mv[liM]))
                 + (lseS[2] - __bfloat162float(Fv[liF]));

        const float RADF = 0.017453292519943295f;
        float lat1 = labels[b * 2]      * RADF;
        float lon1 = labels[b * 2 + 1]  * RADF;
        float lat2 = fpart[pp * 2]      * RADF;
        float lon2 = fpart[pp * 2 + 1]  * RADF;
        float sdlat = sinf((lat2 - lat1) * 0.5f);
        float sdlon = sinf((lon2 - lon1) * 0.5f);
        float a = sdlat * sdlat + cosf(lat1) * cosf(lat2) * sdlon * sdlon;
        a = fminf(fmaxf(a, 0.f), 1.f);
        float d = 2.0f * 6371.0f * asinf(sqrtf(a));
        if (d <= 1.0f)    atomicAdd(&g_counts[0], 1);
        if (d <= 25.0f)   atomicAdd(&g_counts[1], 1);
        if (d <= 200.0f)  atomicAdd(&g_counts[2], 1);
        if (d <= 750.0f)  atomicAdd(&g_counts[3], 1);
        if (d <= 2500.0f) atomicAdd(&g_counts[4], 1);
    }
}

// ============================================================
// Final deterministic reduction -> out[0]=loss, out[1..5]=acc
// ============================================================
__global__ void k_finalize(float* __restrict__ out)
{
    __shared__ float red[256];
    int tid = threadIdx.x;
    float s = 0.f;
    for (int i = tid; i < B; i += 256) s += g_nll[i];
    red[tid] = s; __syncthreads();
    for (int st = 128; st > 0; st >>= 1) {
        if (tid < st) red[tid] += red[tid + st];
        __syncthreads();
    }
    if (tid == 0) out[0] = red[0] / (float)B;
    if (tid < 5)  out[1 + tid] = (float)g_counts[tid] / (float)B;
}

// ============================================================
extern "C" void kernel_launch(void* const* d_in, const int* in_sizes, int n_in,
                              void* d_out, int out_size)
{
    const float* features = (const float*)d_in[0];
    const float* labels   = (const float*)d_in[1];
    const float* cpart    = (const float*)d_in[2];
    const float* mpart    = (const float*)d_in[3];
    const float* fpart    = (const float*)d_in[4];
    const int*   mparents = (const int*)d_in[5];
    const int*   fparents = (const int*)d_in[6];
    const float* cw = (const float*)d_in[7];
    const float* cb = (const float*)d_in[8];
    const float* mw = (const float*)d_in[9];
    const float* mb = (const float*)d_in[10];
    const float* fw = (const float*)d_in[11];
    const float* fb = (const float*)d_in[12];
    float* out = (float*)d_out;

    static cudaStream_t s2 = nullptr;
    static cudaEvent_t evFork = nullptr, evA = nullptr, evJoin = nullptr;
    static int s_init_done = 0;
    if (!s_init_done) {
        cudaFuncSetAttribute(k_mmagemm, cudaFuncAttributeMaxDynamicSharedMemorySize,
                             GEMM_SMEM);
        cudaFuncSetAttribute(k_tail, cudaFuncAttributeMaxDynamicSharedMemorySize,
                             TAIL_SMEM);
        cudaStreamCreateWithFlags(&s2, cudaStreamNonBlocking);
        cudaEventCreateWithFlags(&evFork, cudaEventDisableTiming);
        cudaEventCreateWithFlags(&evA, cudaEventDisableTiming);
        cudaEventCreateWithFlags(&evJoin, cudaEventDisableTiming);
        s_init_done = 1;
    }

    // fork: convA + init + labelidx on s2, overlapping convW on default
    cudaEventRecord(evFork, 0);
    cudaStreamWaitEvent(s2, evFork, 0);
    k_convA<<<((B * D) / 4 + 255) / 256, 256, 0, s2>>>((const float4*)features);
    cudaEventRecord(evA, s2);
    k_init<<<(NTOT + 255) / 256, 256, 0, s2>>>(labels, cpart, mpart, fpart);
    k_labelidx<<<(3 * B + 7) / 8, 256, 0, s2>>>();
    cudaEventRecord(evJoin, s2);

    k_convW<<<dim3(D / 64, NPTOT / 64), 256>>>(cw, mw, fw);
    cudaStreamWaitEvent(0, evA, 0);      // GEMM needs g_A_hi
    k_mmagemm<<<GRID_M * GRID_N, 256, GEMM_SMEM>>>(cb, mb, fb);

    // join before tail (needs g_label_idx, g_counts)
    cudaStreamWaitEvent(0, evJoin, 0);
    k_tail<<<B, TAIL_T, TAIL_SMEM>>>(labels, fpart, fparents, mparents);
    k_finalize<<<1, 256>>>(out);
}